// round 2
// baseline (speedup 1.0000x reference)
#include <cuda_runtime.h>
#include <math.h>

#define B    256
#define CTXD 512
#define DOF  6
#define WSZ  300
#define CATD 306
#define PG   256
#define PW   512
#define HG   256
#define HW   512
#define MS   20
#define NSTEPS 19

// ---------------- device scratch (no allocations allowed) ----------------
__device__ float g_Wt[(size_t)CATD * CTXD * PW];   // [j][i][o]
__device__ float g_Gt[(size_t)DOF  * CTXD * PG];   // [j][i][o]
__device__ float g_Aw[(size_t)B * CATD * PW];      // [b][j][o]
__device__ float g_Ag[(size_t)B * DOF  * PG];      // [b][j][o]
__device__ float g_xg[B * PG];
__device__ float g_x2[B * PG];
__device__ float g_yw[B * PW];
__device__ float g_y2[B * PW];
__device__ float g_cat[B * CATD];
__device__ float g_gh[2 * B * HG];
__device__ float g_gc[2 * B * HG];
__device__ float g_wh[2 * B * HW];
__device__ float g_wc[2 * B * HW];
__device__ float g_gatesG[B * 4 * HG];
__device__ float g_gatesW[B * 4 * HW];

__device__ __forceinline__ float sigf(float x) { return 1.f / (1.f + expf(-x)); }

// ---------------- transpose (o,i,j) -> (j,i,o) ----------------
__global__ void transpose_oij_jio(const float* __restrict__ in, float* __restrict__ out,
                                  int O, int I, int J) {
    __shared__ float tile[32][33];
    int i  = blockIdx.x;
    int o0 = blockIdx.y * 32;
    int j0 = blockIdx.z * 32;
    int tx = threadIdx.x, ty = threadIdx.y;
    int o = o0 + ty, j = j0 + tx;
    if (o < O && j < J)
        tile[ty][tx] = in[(size_t)o * I * J + (size_t)i * J + j];
    __syncthreads();
    int jo = j0 + ty, oo = o0 + tx;
    if (jo < J && oo < O)
        out[(size_t)jo * I * O + (size_t)i * O + oo] = tile[tx][ty];
}

// ---------------- precompute GEMM: C_z[m,n] = sum_k A[m,k] * B_z[k,n] ----------------
// BM=128, BN=64, BK=16, 256 threads, per-thread 8x4.
__global__ __launch_bounds__(256) void gemm_nn_batched(
        const float* __restrict__ A, int lda,
        const float* __restrict__ Bm, size_t bStrideZ,
        float* __restrict__ C, int ldc, int cStrideZ,
        int N, int K) {
    __shared__ float As[16][132];   // row stride 132*4=528B, 16B aligned
    __shared__ float Bs[16][68];    // 68*4=272B, 16B aligned
    int z = blockIdx.z;
    const float* Bz = Bm + (size_t)z * bStrideZ;
    float* Cz = C + (size_t)z * cStrideZ;
    int m0 = blockIdx.y * 128, n0 = blockIdx.x * 64;
    int t = threadIdx.x;
    int tx = t & 15, ty = t >> 4;
    float acc[8][4];
#pragma unroll
    for (int i = 0; i < 8; i++)
#pragma unroll
        for (int j = 0; j < 4; j++) acc[i][j] = 0.f;

    for (int k0 = 0; k0 < K; k0 += 16) {
#pragma unroll
        for (int i = 0; i < 8; i++) {
            int idx = t + i * 256;
            int r = idx >> 4, c = idx & 15;
            As[c][r] = A[(size_t)(m0 + r) * lda + k0 + c];
        }
#pragma unroll
        for (int i = 0; i < 4; i++) {
            int idx = t + i * 256;
            int r = idx >> 6, c = idx & 63;
            Bs[r][c] = Bz[(size_t)(k0 + r) * N + n0 + c];
        }
        __syncthreads();
#pragma unroll
        for (int kk = 0; kk < 16; kk++) {
            float a[8], bb[4];
            *(float4*)&a[0] = *(const float4*)&As[kk][ty * 8];
            *(float4*)&a[4] = *(const float4*)&As[kk][ty * 8 + 4];
            *(float4*)&bb[0] = *(const float4*)&Bs[kk][tx * 4];
#pragma unroll
            for (int i = 0; i < 8; i++)
#pragma unroll
                for (int j = 0; j < 4; j++) acc[i][j] += a[i] * bb[j];
        }
        __syncthreads();
    }
#pragma unroll
    for (int i = 0; i < 8; i++)
#pragma unroll
        for (int j = 0; j < 4; j++)
            Cz[(size_t)(m0 + ty * 8 + i) * ldc + n0 + tx * 4 + j] = acc[i][j];
}

// ---------------- dual-job step GEMM (TN): C = act(A@W^T (+A2@W2^T) + b1 (+b2)) ------
// BM=BN=64, BK=16, 256 threads, 4x4 per thread. M==256 fixed; N guarded; K%16==0.
struct Job {
    const float* A;  int lda;  int K;
    const float* W;
    const float* A2; int lda2; int K2;
    const float* W2;
    const float* b1; const float* b2;
    float* C;  int ldc;
    float* C2; int ldc2;
    int N; int act;
    int tilesX;    // N tiles of 64
    int nblocks;   // tilesX * (B/64)
};

__global__ __launch_bounds__(256) void gemm_dual(Job j0, Job j1) {
    __shared__ float As[16][68];
    __shared__ float Ws[16][68];
    int bid = blockIdx.x;
    Job jb = (bid < j0.nblocks) ? j0 : j1;
    int lb = (bid < j0.nblocks) ? bid : bid - j0.nblocks;
    int n0 = (lb % jb.tilesX) * 64;
    int m0 = (lb / jb.tilesX) * 64;
    int N = jb.N;
    int t = threadIdx.x;
    int tx = t & 15, ty = t >> 4;
    float acc[4][4];
#pragma unroll
    for (int i = 0; i < 4; i++)
#pragma unroll
        for (int j = 0; j < 4; j++) acc[i][j] = 0.f;

    for (int pass = 0; pass < 2; pass++) {
        const float* Ac = pass ? jb.A2 : jb.A;
        const float* Wc = pass ? jb.W2 : jb.W;
        const int Kc   = pass ? jb.K2 : jb.K;
        const int ldac = pass ? jb.lda2 : jb.lda;
        if (Kc <= 0) break;
        for (int k0 = 0; k0 < Kc; k0 += 16) {
#pragma unroll
            for (int i = 0; i < 4; i++) {
                int idx = t + i * 256;
                int r = idx >> 4, c = idx & 15;
                As[c][r] = Ac[(size_t)(m0 + r) * ldac + k0 + c];
                int nr = n0 + r;
                Ws[c][r] = (nr < N) ? Wc[(size_t)nr * Kc + k0 + c] : 0.f;
            }
            __syncthreads();
#pragma unroll
            for (int kk = 0; kk < 16; kk++) {
                float a[4], w[4];
                *(float4*)&a[0] = *(const float4*)&As[kk][ty * 4];
                *(float4*)&w[0] = *(const float4*)&Ws[kk][tx * 4];
#pragma unroll
                for (int i = 0; i < 4; i++)
#pragma unroll
                    for (int j = 0; j < 4; j++) acc[i][j] += a[i] * w[j];
            }
            __syncthreads();
        }
    }
#pragma unroll
    for (int i = 0; i < 4; i++) {
        int m = m0 + ty * 4 + i;
#pragma unroll
        for (int j = 0; j < 4; j++) {
            int n = n0 + tx * 4 + j;
            if (n < N) {
                float v = acc[i][j] + jb.b1[n];
                if (jb.b2) v += jb.b2[n];
                if (jb.act == 1) v = tanhf(v);
                jb.C[(size_t)m * jb.ldc + n] = v;
                if (jb.C2) jb.C2[(size_t)m * jb.ldc2 + n] = v;
            }
        }
    }
}

// ---------------- bilinear apply: y = Aw . cat + bw_b ; x = Ag . pg + bg_b ----------------
__global__ void bilinear_apply(const float* __restrict__ bw_b, const float* __restrict__ bg_b) {
    int b = blockIdx.x;
    int part = blockIdx.y;
    int t = threadIdx.x;  // 256
    __shared__ float sc[CATD];
    for (int k = t; k < CATD; k += 256) sc[k] = g_cat[b * CATD + k];
    __syncthreads();
    if (part < 2) {
        int o = part * 256 + t;
        const float* a = g_Aw + (size_t)b * CATD * PW + o;
        float acc0 = bw_b[o];
        float acc1 = 0.f;
#pragma unroll 6
        for (int j = 0; j < CATD; j += 2) {
            acc0 += a[(size_t)j * PW] * sc[j];
            acc1 += a[(size_t)(j + 1) * PW] * sc[j + 1];
        }
        g_yw[b * PW + o] = acc0 + acc1;
    } else {
        int o = t;
        const float* a = g_Ag + (size_t)b * DOF * PG + o;
        float acc = bg_b[o];
#pragma unroll
        for (int j = 0; j < DOF; j++) acc += a[j * PG] * sc[j];
        g_xg[b * PG + o] = acc;
    }
}

// ---------------- LSTM pointwise, fused over both LSTMs for one layer ----------------
__global__ void point_fused(const float* __restrict__ gatesG, float* __restrict__ hG,
                            float* __restrict__ cG,
                            const float* __restrict__ gatesW, float* __restrict__ hW,
                            float* __restrict__ cW) {
    int idx = blockIdx.x * blockDim.x + threadIdx.x;
    const float* gates; float* h; float* c; int H; int li;
    if (idx < B * HG) { gates = gatesG; h = hG; c = cG; H = HG; li = idx; }
    else              { gates = gatesW; h = hW; c = cW; H = HW; li = idx - B * HG; }
    int b = li / H, u = li - b * H;
    const float* g = gates + (size_t)b * 4 * H;
    float ig = sigf(g[u]);
    float fg = sigf(g[H + u]);
    float gg = tanhf(g[2 * H + u]);
    float og = sigf(g[3 * H + u]);
    float cn = fg * c[li] + ig * gg;
    c[li] = cn;
    h[li] = og * tanhf(cn);
}

// ---------------- init ----------------
__global__ void init_k(const float* __restrict__ goal0, const float* __restrict__ w0,
                       float* __restrict__ outGoals, float* __restrict__ outWs) {
    int idx = blockIdx.x * blockDim.x + threadIdx.x;
    if (idx < 2 * B * HG) { g_gh[idx] = 0.f; g_gc[idx] = 0.f; }
    if (idx < 2 * B * HW) { g_wh[idx] = 0.f; g_wc[idx] = 0.f; }
    if (idx < B * DOF) {
        int b = idx / DOF, d = idx - b * DOF;
        float v = goal0[idx];
        g_cat[b * CATD + d] = v;
        outGoals[(size_t)b * MS * DOF + d] = v;
    }
    if (idx < B * WSZ) {
        int b = idx / WSZ, d = idx - b * WSZ;
        float v = w0[idx];
        g_cat[b * CATD + DOF + d] = v;
        outWs[(size_t)b * MS * WSZ + d] = v;
    }
}

// ---------------- host ----------------
static inline Job mkjob(const float* A, int lda, int K, const float* W,
                        const float* A2, int lda2, int K2, const float* W2,
                        const float* b1, const float* b2,
                        float* C, int ldc, float* C2, int ldc2,
                        int N, int act) {
    Job j;
    j.A = A; j.lda = lda; j.K = K; j.W = W;
    j.A2 = A2; j.lda2 = lda2; j.K2 = K2; j.W2 = W2;
    j.b1 = b1; j.b2 = b2;
    j.C = C; j.ldc = ldc; j.C2 = C2; j.ldc2 = ldc2;
    j.N = N; j.act = act;
    j.tilesX = (N + 63) / 64;
    j.nblocks = j.tilesX * (B / 64);
    return j;
}

extern "C" void kernel_launch(void* const* d_in, const int* in_sizes, int n_in,
                              void* d_out, int out_size) {
    const float* ctx    = (const float*)d_in[0];
    const float* goal0  = (const float*)d_in[1];
    const float* w0     = (const float*)d_in[2];
    const float* bg_W   = (const float*)d_in[3];
    const float* bg_b   = (const float*)d_in[4];
    const float* bw_W   = (const float*)d_in[5];
    const float* bw_b   = (const float*)d_in[6];
    const float* fcg_W  = (const float*)d_in[7];
    const float* fcg_b  = (const float*)d_in[8];
    const float* fcw_W  = (const float*)d_in[9];
    const float* fcw_b  = (const float*)d_in[10];
    const float* lg_Wih = (const float*)d_in[11];
    const float* lg_Whh = (const float*)d_in[12];
    const float* lg_bih = (const float*)d_in[13];
    const float* lg_bhh = (const float*)d_in[14];
    const float* lw_Wih = (const float*)d_in[15];
    const float* lw_Whh = (const float*)d_in[16];
    const float* lw_bih = (const float*)d_in[17];
    const float* lw_bhh = (const float*)d_in[18];
    const float* og_W   = (const float*)d_in[19];
    const float* og_b   = (const float*)d_in[20];
    const float* ow_W   = (const float*)d_in[21];
    const float* ow_b   = (const float*)d_in[22];

    float* out   = (float*)d_out;
    float* goals = out;                        // [B][MS][DOF]
    float* ws    = out + (size_t)B * MS * DOF; // [B][MS][WSZ]

    float *Wt, *Gt, *Aw, *Ag, *xg, *x2, *yw, *y2, *cat, *gh, *gc, *wh, *wc, *gatesG, *gatesW;
    cudaGetSymbolAddress((void**)&Wt, g_Wt);
    cudaGetSymbolAddress((void**)&Gt, g_Gt);
    cudaGetSymbolAddress((void**)&Aw, g_Aw);
    cudaGetSymbolAddress((void**)&Ag, g_Ag);
    cudaGetSymbolAddress((void**)&xg, g_xg);
    cudaGetSymbolAddress((void**)&x2, g_x2);
    cudaGetSymbolAddress((void**)&yw, g_yw);
    cudaGetSymbolAddress((void**)&y2, g_y2);
    cudaGetSymbolAddress((void**)&cat, g_cat);
    cudaGetSymbolAddress((void**)&gh, g_gh);
    cudaGetSymbolAddress((void**)&gc, g_gc);
    cudaGetSymbolAddress((void**)&wh, g_wh);
    cudaGetSymbolAddress((void**)&wc, g_wc);
    cudaGetSymbolAddress((void**)&gatesG, g_gatesG);
    cudaGetSymbolAddress((void**)&gatesW, g_gatesW);

    dim3 tblk(32, 32);
    transpose_oij_jio<<<dim3(CTXD, PW / 32, (CATD + 31) / 32), tblk>>>(bw_W, Wt, PW, CTXD, CATD);
    transpose_oij_jio<<<dim3(CTXD, PG / 32, 1), tblk>>>(bg_W, Gt, PG, CTXD, DOF);

    gemm_nn_batched<<<dim3(PW / 64, B / 128, CATD), 256>>>(
        ctx, CTXD, Wt, (size_t)CTXD * PW, Aw, CATD * PW, PW, PW, CTXD);
    gemm_nn_batched<<<dim3(PG / 64, B / 128, DOF), 256>>>(
        ctx, CTXD, Gt, (size_t)CTXD * PG, Ag, DOF * PG, PG, PG, CTXD);

    init_k<<<(2 * B * HW) / 256, 256>>>(goal0, w0, goals, ws);

    const int pointBlocks = (B * (HG + HW)) / 256;

    for (int s = 0; s < NSTEPS; s++) {
        // bilinear: y = Aw.cat + bw_b ; x = Ag.pg + bg_b
        bilinear_apply<<<dim3(B, 3), 256>>>(bw_b, bg_b);

        // fc + tanh (both chains fused)
        {
            Job jw = mkjob(yw, PW, PW, fcw_W, nullptr, 0, 0, nullptr,
                           fcw_b, nullptr, y2, PW, nullptr, 0, PW, 1);
            Job jg = mkjob(xg, PG, PG, fcg_W, nullptr, 0, 0, nullptr,
                           fcg_b, nullptr, x2, PG, nullptr, 0, PG, 1);
            gemm_dual<<<jw.nblocks + jg.nblocks, 256>>>(jw, jg);
        }
        // LSTM layer 0 gates (both chains fused)
        {
            Job jw = mkjob(y2, PW, PW, lw_Wih, wh, HW, HW, lw_Whh,
                           lw_bih, lw_bhh, gatesW, 4 * HW, nullptr, 0, 4 * HW, 0);
            Job jg = mkjob(x2, PG, PG, lg_Wih, gh, HG, HG, lg_Whh,
                           lg_bih, lg_bhh, gatesG, 4 * HG, nullptr, 0, 4 * HG, 0);
            gemm_dual<<<jw.nblocks + jg.nblocks, 256>>>(jw, jg);
        }
        point_fused<<<pointBlocks, 256>>>(gatesG, gh, gc, gatesW, wh, wc);

        // LSTM layer 1 gates
        {
            Job jw = mkjob(wh, HW, HW, lw_Wih + (size_t)4 * HW * PW,
                           wh + B * HW, HW, HW, lw_Whh + (size_t)4 * HW * HW,
                           lw_bih + 4 * HW, lw_bhh + 4 * HW, gatesW, 4 * HW,
                           nullptr, 0, 4 * HW, 0);
            Job jg = mkjob(gh, HG, HG, lg_Wih + (size_t)4 * HG * PG,
                           gh + B * HG, HG, HG, lg_Whh + (size_t)4 * HG * HG,
                           lg_bih + 4 * HG, lg_bhh + 4 * HG, gatesG, 4 * HG,
                           nullptr, 0, 4 * HG, 0);
            gemm_dual<<<jw.nblocks + jg.nblocks, 256>>>(jw, jg);
        }
        point_fused<<<pointBlocks, 256>>>(gatesG, gh + B * HG, gc + B * HG,
                                          gatesW, wh + B * HW, wc + B * HW);

        // outputs (both chains fused): ng -> goals & cat[:,0:6]; nw -> ws & cat[:,6:306]
        {
            Job jw = mkjob(wh + B * HW, HW, HW, ow_W, nullptr, 0, 0, nullptr,
                           ow_b, nullptr, ws + (size_t)(s + 1) * WSZ, MS * WSZ,
                           cat + DOF, CATD, WSZ, 0);
            Job jg = mkjob(gh + B * HG, HG, HG, og_W, nullptr, 0, 0, nullptr,
                           og_b, nullptr, goals + (size_t)(s + 1) * DOF, MS * DOF,
                           cat, CATD, DOF, 0);
            gemm_dual<<<jw.nblocks + jg.nblocks, 256>>>(jw, jg);
        }
    }
    (void)in_sizes; (void)n_in; (void)out_size;
}

// round 3
// speedup vs baseline: 1.0129x; 1.0129x over previous
#include <cuda_runtime.h>
#include <math.h>

#define B    256
#define CTXD 512
#define DOF  6
#define WSZ  300
#define CATD 306
#define PG   256
#define PW   512
#define HG   256
#define HW   512
#define MS   20
#define NSTEPS 19
#define NBLK 296

// ---------------- device scratch ----------------
__device__ float g_Wt[(size_t)CATD * CTXD * PW];   // [j][i][o]
__device__ float g_Gt[(size_t)DOF  * CTXD * PG];   // [j][i][o]
__device__ float g_Aw[(size_t)B * CATD * PW];      // [b][j][o]
__device__ float g_Ag[(size_t)B * DOF  * PG];      // [b][j][o]
__device__ float g_xg[B * PG];
__device__ float g_x2[B * PG];
__device__ float g_yw[B * PW];
__device__ float g_y2[B * PW];
__device__ float g_cat[B * CATD];
__device__ float g_gh[2 * B * HG];
__device__ float g_gc[2 * B * HG];
__device__ float g_wh[2 * B * HW];
__device__ float g_wc[2 * B * HW];
__device__ float g_gatesG[B * 4 * HG];
__device__ float g_gatesW[B * 4 * HW];

__device__ unsigned g_bar_count = 0;
__device__ unsigned g_bar_gen   = 0;

__device__ __forceinline__ float sigf(float x) { return 1.f / (1.f + expf(-x)); }

__device__ __forceinline__ void gridbar() {
    __syncthreads();
    if (threadIdx.x == 0) {
        __threadfence();                       // release: my stores visible
        unsigned gen = *(volatile unsigned*)&g_bar_gen;
        if (atomicAdd(&g_bar_count, 1u) == NBLK - 1) {
            g_bar_count = 0;
            __threadfence();
            *(volatile unsigned*)&g_bar_gen = gen + 1;
        } else {
            while (*(volatile unsigned*)&g_bar_gen == gen) __nanosleep(64);
        }
        __threadfence();                       // acquire: invalidate L1
    }
    __syncthreads();
}

// ---------------- transpose (o,i,j) -> (j,i,o) ----------------
__global__ void transpose_oij_jio(const float* __restrict__ in, float* __restrict__ out,
                                  int O, int I, int J) {
    __shared__ float tile[32][33];
    int i  = blockIdx.x;
    int o0 = blockIdx.y * 32;
    int j0 = blockIdx.z * 32;
    int tx = threadIdx.x, ty = threadIdx.y;
    int o = o0 + ty, j = j0 + tx;
    if (o < O && j < J)
        tile[ty][tx] = in[(size_t)o * I * J + (size_t)i * J + j];
    __syncthreads();
    int jo = j0 + ty, oo = o0 + tx;
    if (jo < J && oo < O)
        out[(size_t)jo * I * O + (size_t)i * O + oo] = tile[tx][ty];
}

// ---------------- precompute GEMM: C_z[m,n] = sum_k A[m,k] * B_z[k,n] ----------------
__global__ __launch_bounds__(256) void gemm_nn_batched(
        const float* __restrict__ A, int lda,
        const float* __restrict__ Bm, size_t bStrideZ,
        float* __restrict__ C, int ldc, int cStrideZ,
        int N, int K) {
    __shared__ float As[16][132];
    __shared__ float Bs[16][68];
    int z = blockIdx.z;
    const float* Bz = Bm + (size_t)z * bStrideZ;
    float* Cz = C + (size_t)z * cStrideZ;
    int m0 = blockIdx.y * 128, n0 = blockIdx.x * 64;
    int t = threadIdx.x;
    int tx = t & 15, ty = t >> 4;
    float acc[8][4];
#pragma unroll
    for (int i = 0; i < 8; i++)
#pragma unroll
        for (int j = 0; j < 4; j++) acc[i][j] = 0.f;

    for (int k0 = 0; k0 < K; k0 += 16) {
#pragma unroll
        for (int i = 0; i < 8; i++) {
            int idx = t + i * 256;
            int r = idx >> 4, c = idx & 15;
            As[c][r] = A[(size_t)(m0 + r) * lda + k0 + c];
        }
#pragma unroll
        for (int i = 0; i < 4; i++) {
            int idx = t + i * 256;
            int r = idx >> 6, c = idx & 63;
            Bs[r][c] = Bz[(size_t)(k0 + r) * N + n0 + c];
        }
        __syncthreads();
#pragma unroll
        for (int kk = 0; kk < 16; kk++) {
            float a[8], bb[4];
            *(float4*)&a[0] = *(const float4*)&As[kk][ty * 8];
            *(float4*)&a[4] = *(const float4*)&As[kk][ty * 8 + 4];
            *(float4*)&bb[0] = *(const float4*)&Bs[kk][tx * 4];
#pragma unroll
            for (int i = 0; i < 8; i++)
#pragma unroll
                for (int j = 0; j < 4; j++) acc[i][j] += a[i] * bb[j];
        }
        __syncthreads();
    }
#pragma unroll
    for (int i = 0; i < 8; i++)
#pragma unroll
        for (int j = 0; j < 4; j++)
            Cz[(size_t)(m0 + ty * 8 + i) * ldc + n0 + tx * 4 + j] = acc[i][j];
}

// ---------------- init ----------------
__global__ void init_k(const float* __restrict__ goal0, const float* __restrict__ w0,
                       float* __restrict__ outGoals, float* __restrict__ outWs) {
    int idx = blockIdx.x * blockDim.x + threadIdx.x;
    if (idx < 2 * B * HG) { g_gh[idx] = 0.f; g_gc[idx] = 0.f; }
    if (idx < 2 * B * HW) { g_wh[idx] = 0.f; g_wc[idx] = 0.f; }
    if (idx < B * DOF) {
        int b = idx / DOF, d = idx - b * DOF;
        float v = goal0[idx];
        g_cat[b * CATD + d] = v;
        outGoals[(size_t)b * MS * DOF + d] = v;
    }
    if (idx < B * WSZ) {
        int b = idx / WSZ, d = idx - b * WSZ;
        float v = w0[idx];
        g_cat[b * CATD + DOF + d] = v;
        outWs[(size_t)b * MS * WSZ + d] = v;
    }
}

// ---------------- one 64x64 TN GEMM tile (dual-K) ----------------
// sm: 2*16*68 floats.  C = act(A@W^T (+ A2@W2^T) + b1 (+b2)); optional copy to C2.
__device__ __noinline__ void gemm_tile(
        const float* A, int lda, int K, const float* W,
        const float* A2, int lda2, int K2, const float* W2,
        const float* b1, const float* b2,
        float* C, int ldc, float* C2, int ldc2,
        int N, int act, int m0, int n0, float* sm) {
    float (*As)[68] = (float(*)[68])sm;
    float (*Ws)[68] = (float(*)[68])(sm + 16 * 68);
    int t = threadIdx.x;
    int tx = t & 15, ty = t >> 4;
    float acc[4][4];
#pragma unroll
    for (int i = 0; i < 4; i++)
#pragma unroll
        for (int j = 0; j < 4; j++) acc[i][j] = 0.f;

    for (int pass = 0; pass < 2; pass++) {
        const float* Ac = pass ? A2 : A;
        const float* Wc = pass ? W2 : W;
        const int Kc   = pass ? K2 : K;
        const int ldac = pass ? lda2 : lda;
        if (Kc <= 0) break;
        for (int k0 = 0; k0 < Kc; k0 += 16) {
#pragma unroll
            for (int i = 0; i < 4; i++) {
                int idx = t + i * 256;
                int r = idx >> 4, c = idx & 15;
                As[c][r] = Ac[(size_t)(m0 + r) * ldac + k0 + c];
                int nr = n0 + r;
                Ws[c][r] = (nr < N) ? Wc[(size_t)nr * Kc + k0 + c] : 0.f;
            }
            __syncthreads();
#pragma unroll
            for (int kk = 0; kk < 16; kk++) {
                float a[4], w[4];
                *(float4*)&a[0] = *(const float4*)&As[kk][ty * 4];
                *(float4*)&w[0] = *(const float4*)&Ws[kk][tx * 4];
#pragma unroll
                for (int i = 0; i < 4; i++)
#pragma unroll
                    for (int j = 0; j < 4; j++) acc[i][j] += a[i] * w[j];
            }
            __syncthreads();
        }
    }
#pragma unroll
    for (int i = 0; i < 4; i++) {
        int m = m0 + ty * 4 + i;
#pragma unroll
        for (int j = 0; j < 4; j++) {
            int n = n0 + tx * 4 + j;
            if (n < N) {
                float v = acc[i][j] + b1[n];
                if (b2) v += b2[n];
                if (act) v = tanhf(v);
                C[(size_t)m * ldc + n] = v;
                if (C2) C2[(size_t)m * ldc2 + n] = v;
            }
        }
    }
}

// ---------------- persistent megakernel: all 19 steps ----------------
__global__ __launch_bounds__(256, 2) void step_megakernel(
        const float* __restrict__ bg_b, const float* __restrict__ bw_b,
        const float* __restrict__ fcg_W, const float* __restrict__ fcg_b,
        const float* __restrict__ fcw_W, const float* __restrict__ fcw_b,
        const float* __restrict__ lg_Wih, const float* __restrict__ lg_Whh,
        const float* __restrict__ lg_bih, const float* __restrict__ lg_bhh,
        const float* __restrict__ lw_Wih, const float* __restrict__ lw_Whh,
        const float* __restrict__ lw_bih, const float* __restrict__ lw_bhh,
        const float* __restrict__ og_W, const float* __restrict__ og_b,
        const float* __restrict__ ow_W, const float* __restrict__ ow_b,
        float* goals, float* ws) {
    __shared__ float sm[2 * 16 * 68];
    const int t = threadIdx.x;
    const int gb = NBLK;

    for (int s = 0; s < NSTEPS; s++) {
        // -------- Phase A: bilinear  y=Aw.cat+bw_b (512 units), x=Ag.pg+bg_b (256) ----
        for (int u = blockIdx.x; u < 768; u += gb) {
            if (u < 512) {
                int b = u >> 1, part = u & 1;
                for (int k = t; k < CATD; k += 256) sm[k] = g_cat[b * CATD + k];
                __syncthreads();
                int o = part * 256 + t;
                const float* a = g_Aw + (size_t)b * CATD * PW + o;
                float acc0 = bw_b[o], acc1 = 0.f;
#pragma unroll 6
                for (int j = 0; j < CATD; j += 2) {
                    acc0 += a[(size_t)j * PW] * sm[j];
                    acc1 += a[(size_t)(j + 1) * PW] * sm[j + 1];
                }
                g_yw[b * PW + o] = acc0 + acc1;
                __syncthreads();
            } else {
                int b = u - 512;
                // pg = cat[:, 0:DOF]
                if (t < DOF) sm[t] = g_cat[b * CATD + t];
                __syncthreads();
                const float* a = g_Ag + (size_t)b * DOF * PG + t;
                float acc = bg_b[t];
#pragma unroll
                for (int j = 0; j < DOF; j++) acc += a[j * PG] * sm[j];
                g_xg[b * PG + t] = acc;
                __syncthreads();
            }
        }
        gridbar();

        // -------- Phase B: fc + tanh.  w: 32 tiles, g: 16 tiles ----------------------
        for (int u = blockIdx.x; u < 48; u += gb) {
            if (u < 32) {
                int n0 = (u & 7) * 64, m0 = (u >> 3) * 64;
                gemm_tile(g_yw, PW, PW, fcw_W, nullptr, 0, 0, nullptr,
                          fcw_b, nullptr, g_y2, PW, nullptr, 0, PW, 1, m0, n0, sm);
            } else {
                int v = u - 32;
                int n0 = (v & 3) * 64, m0 = (v >> 2) * 64;
                gemm_tile(g_xg, PG, PG, fcg_W, nullptr, 0, 0, nullptr,
                          fcg_b, nullptr, g_x2, PG, nullptr, 0, PG, 1, m0, n0, sm);
            }
        }
        gridbar();

        // -------- Phase C: gates layer 0.  w: 128 tiles, g: 64 tiles -----------------
        for (int u = blockIdx.x; u < 192; u += gb) {
            if (u < 128) {
                int n0 = (u & 31) * 64, m0 = (u >> 5) * 64;
                gemm_tile(g_y2, PW, PW, lw_Wih, g_wh, HW, HW, lw_Whh,
                          lw_bih, lw_bhh, g_gatesW, 4 * HW, nullptr, 0,
                          4 * HW, 0, m0, n0, sm);
            } else {
                int v = u - 128;
                int n0 = (v & 15) * 64, m0 = (v >> 4) * 64;
                gemm_tile(g_x2, PG, PG, lg_Wih, g_gh, HG, HG, lg_Whh,
                          lg_bih, lg_bhh, g_gatesG, 4 * HG, nullptr, 0,
                          4 * HG, 0, m0, n0, sm);
            }
        }
        gridbar();

        // -------- Phase D: pointwise layer 0 -----------------------------------------
        for (int u = blockIdx.x; u < 768; u += gb) {
            int idx = u * 256 + t;
            const float* gg; float* h; float* c; int H; int li;
            if (idx < B * HG) { gg = g_gatesG; h = g_gh; c = g_gc; H = HG; li = idx; }
            else { gg = g_gatesW; h = g_wh; c = g_wc; H = HW; li = idx - B * HG; }
            int b = li / H, uo = li - b * H;
            const float* g4 = gg + (size_t)b * 4 * H;
            float ig = sigf(g4[uo]);
            float fg = sigf(g4[H + uo]);
            float gn = tanhf(g4[2 * H + uo]);
            float og = sigf(g4[3 * H + uo]);
            float cn = fg * c[li] + ig * gn;
            c[li] = cn;
            h[li] = og * tanhf(cn);
        }
        gridbar();

        // -------- Phase E: gates layer 1 ---------------------------------------------
        for (int u = blockIdx.x; u < 192; u += gb) {
            if (u < 128) {
                int n0 = (u & 31) * 64, m0 = (u >> 5) * 64;
                gemm_tile(g_wh, HW, HW, lw_Wih + (size_t)4 * HW * PW,
                          g_wh + B * HW, HW, HW, lw_Whh + (size_t)4 * HW * HW,
                          lw_bih + 4 * HW, lw_bhh + 4 * HW, g_gatesW, 4 * HW,
                          nullptr, 0, 4 * HW, 0, m0, n0, sm);
            } else {
                int v = u - 128;
                int n0 = (v & 15) * 64, m0 = (v >> 4) * 64;
                gemm_tile(g_gh, HG, HG, lg_Wih + (size_t)4 * HG * PG,
                          g_gh + B * HG, HG, HG, lg_Whh + (size_t)4 * HG * HG,
                          lg_bih + 4 * HG, lg_bhh + 4 * HG, g_gatesG, 4 * HG,
                          nullptr, 0, 4 * HG, 0, m0, n0, sm);
            }
        }
        gridbar();

        // -------- Phase F: pointwise layer 1 -----------------------------------------
        for (int u = blockIdx.x; u < 768; u += gb) {
            int idx = u * 256 + t;
            const float* gg; float* h; float* c; int H; int li;
            if (idx < B * HG) { gg = g_gatesG; h = g_gh + B * HG; c = g_gc + B * HG; H = HG; li = idx; }
            else { gg = g_gatesW; h = g_wh + B * HW; c = g_wc + B * HW; H = HW; li = idx - B * HG; }
            int b = li / H, uo = li - b * H;
            const float* g4 = gg + (size_t)b * 4 * H;
            float ig = sigf(g4[uo]);
            float fg = sigf(g4[H + uo]);
            float gn = tanhf(g4[2 * H + uo]);
            float og = sigf(g4[3 * H + uo]);
            float cn = fg * c[li] + ig * gn;
            c[li] = cn;
            h[li] = og * tanhf(cn);
        }
        gridbar();

        // -------- Phase G: output heads.  w: 20 tiles (N=300), g: 4 tiles (N=6) ------
        for (int u = blockIdx.x; u < 24; u += gb) {
            if (u < 20) {
                int n0 = (u % 5) * 64, m0 = (u / 5) * 64;
                gemm_tile(g_wh + B * HW, HW, HW, ow_W, nullptr, 0, 0, nullptr,
                          ow_b, nullptr, ws + (size_t)(s + 1) * WSZ, MS * WSZ,
                          g_cat + DOF, CATD, WSZ, 0, m0, n0, sm);
            } else {
                int m0 = (u - 20) * 64;
                gemm_tile(g_gh + B * HG, HG, HG, og_W, nullptr, 0, 0, nullptr,
                          og_b, nullptr, goals + (size_t)(s + 1) * DOF, MS * DOF,
                          g_cat, CATD, DOF, 0, m0, 0, sm);
            }
        }
        gridbar();
    }
}

// ---------------- host ----------------
extern "C" void kernel_launch(void* const* d_in, const int* in_sizes, int n_in,
                              void* d_out, int out_size) {
    const float* ctx    = (const float*)d_in[0];
    const float* goal0  = (const float*)d_in[1];
    const float* w0     = (const float*)d_in[2];
    const float* bg_W   = (const float*)d_in[3];
    const float* bg_b   = (const float*)d_in[4];
    const float* bw_W   = (const float*)d_in[5];
    const float* bw_b   = (const float*)d_in[6];
    const float* fcg_W  = (const float*)d_in[7];
    const float* fcg_b  = (const float*)d_in[8];
    const float* fcw_W  = (const float*)d_in[9];
    const float* fcw_b  = (const float*)d_in[10];
    const float* lg_Wih = (const float*)d_in[11];
    const float* lg_Whh = (const float*)d_in[12];
    const float* lg_bih = (const float*)d_in[13];
    const float* lg_bhh = (const float*)d_in[14];
    const float* lw_Wih = (const float*)d_in[15];
    const float* lw_Whh = (const float*)d_in[16];
    const float* lw_bih = (const float*)d_in[17];
    const float* lw_bhh = (const float*)d_in[18];
    const float* og_W   = (const float*)d_in[19];
    const float* og_b   = (const float*)d_in[20];
    const float* ow_W   = (const float*)d_in[21];
    const float* ow_b   = (const float*)d_in[22];

    float* out   = (float*)d_out;
    float* goals = out;                        // [B][MS][DOF]
    float* ws    = out + (size_t)B * MS * DOF; // [B][MS][WSZ]

    float *Wt, *Gt, *Aw, *Ag;
    cudaGetSymbolAddress((void**)&Wt, g_Wt);
    cudaGetSymbolAddress((void**)&Gt, g_Gt);
    cudaGetSymbolAddress((void**)&Aw, g_Aw);
    cudaGetSymbolAddress((void**)&Ag, g_Ag);

    dim3 tblk(32, 32);
    transpose_oij_jio<<<dim3(CTXD, PW / 32, (CATD + 31) / 32), tblk>>>(bw_W, Wt, PW, CTXD, CATD);
    transpose_oij_jio<<<dim3(CTXD, PG / 32, 1), tblk>>>(bg_W, Gt, PG, CTXD, DOF);

    gemm_nn_batched<<<dim3(PW / 64, B / 128, CATD), 256>>>(
        ctx, CTXD, Wt, (size_t)CTXD * PW, Aw, CATD * PW, PW, PW, CTXD);
    gemm_nn_batched<<<dim3(PG / 64, B / 128, DOF), 256>>>(
        ctx, CTXD, Gt, (size_t)CTXD * PG, Ag, DOF * PG, PG, PG, CTXD);

    init_k<<<(2 * B * HW) / 256, 256>>>(goal0, w0, goals, ws);

    step_megakernel<<<NBLK, 256>>>(
        bg_b, bw_b, fcg_W, fcg_b, fcw_W, fcw_b,
        lg_Wih, lg_Whh, lg_bih, lg_bhh,
        lw_Wih, lw_Whh, lw_bih, lw_bhh,
        og_W, og_b, ow_W, ow_b, goals, ws);

    (void)in_sizes; (void)n_in; (void)out_size;
}

// round 5
// speedup vs baseline: 2.0032x; 1.9777x over previous
#include <cuda_runtime.h>
#include <math.h>

#define B    256
#define CTXD 512
#define DOF  6
#define WSZ  300
#define CATD 306
#define PG   256
#define PW   512
#define HG   256
#define HW   512
#define MS   20
#define NSTEPS 19

// ---------------- device scratch ----------------
__device__ float g_Wt[(size_t)CATD * CTXD * PW];   // [j][i][o]
__device__ float g_Gt[(size_t)DOF  * CTXD * PG];   // [j][i][o]
__device__ float g_Aw[(size_t)B * CATD * PW];      // [b][j][o]
__device__ float g_Ag[(size_t)B * DOF  * PG];      // [b][j][o]
__device__ float g_xg[B * PG];
__device__ float g_x2[B * PG];
__device__ float g_yw[B * PW];
__device__ float g_y2[B * PW];
__device__ float g_cat[B * CATD];
// ping-pong h state: [2][B*H]; c state updated in place
__device__ float g_gh0[2 * B * HG];
__device__ float g_gh1[2 * B * HG];
__device__ float g_gc0[B * HG];
__device__ float g_gc1[B * HG];
__device__ float g_wh0[2 * B * HW];
__device__ float g_wh1[2 * B * HW];
__device__ float g_wc0[B * HW];
__device__ float g_wc1[B * HW];

__device__ __forceinline__ float sigf(float x) { return 1.f / (1.f + expf(-x)); }

// ---------------- transpose (o,i,j) -> (j,i,o) ----------------
__global__ void transpose_oij_jio(const float* __restrict__ in, float* __restrict__ out,
                                  int O, int I, int J) {
    __shared__ float tile[32][33];
    int i  = blockIdx.x;
    int o0 = blockIdx.y * 32;
    int j0 = blockIdx.z * 32;
    int tx = threadIdx.x, ty = threadIdx.y;
    int o = o0 + ty, j = j0 + tx;
    if (o < O && j < J)
        tile[ty][tx] = in[(size_t)o * I * J + (size_t)i * J + j];
    __syncthreads();
    int jo = j0 + ty, oo = o0 + tx;
    if (jo < J && oo < O)
        out[(size_t)jo * I * O + (size_t)i * O + oo] = tile[tx][ty];
}

// ---------------- precompute GEMM with register prefetch ----------------
// C_z[m,n] = sum_k A[m,k] * B_z[k,n]; BM=128, BN=64, BK=16, 256 thr, 8x4/thr.
__global__ __launch_bounds__(256, 2) void gemm_nn_batched(
        const float* __restrict__ A, int lda,
        const float* __restrict__ Bm, size_t bStrideZ,
        float* __restrict__ C, int ldc, int cStrideZ,
        int N, int K) {
    __shared__ float As[16][132];
    __shared__ float Bs[16][68];
    int z = blockIdx.z;
    const float* Bz = Bm + (size_t)z * bStrideZ;
    float* Cz = C + (size_t)z * cStrideZ;
    int m0 = blockIdx.y * 128, n0 = blockIdx.x * 64;
    int t = threadIdx.x;
    int tx = t & 15, ty = t >> 4;
    float acc[8][4];
#pragma unroll
    for (int i = 0; i < 8; i++)
#pragma unroll
        for (int j = 0; j < 4; j++) acc[i][j] = 0.f;

    float pa[8], pb[4];
#pragma unroll
    for (int i = 0; i < 8; i++) {
        int idx = t + i * 256;
        pa[i] = __ldg(&A[(size_t)(m0 + (idx >> 4)) * lda + (idx & 15)]);
    }
#pragma unroll
    for (int i = 0; i < 4; i++) {
        int idx = t + i * 256;
        pb[i] = __ldg(&Bz[(size_t)(idx >> 6) * N + n0 + (idx & 63)]);
    }
    for (int k0 = 0; k0 < K; k0 += 16) {
#pragma unroll
        for (int i = 0; i < 8; i++) {
            int idx = t + i * 256;
            As[idx & 15][idx >> 4] = pa[i];
        }
#pragma unroll
        for (int i = 0; i < 4; i++) {
            int idx = t + i * 256;
            Bs[idx >> 6][idx & 63] = pb[i];
        }
        __syncthreads();
        if (k0 + 16 < K) {
            int kn = k0 + 16;
#pragma unroll
            for (int i = 0; i < 8; i++) {
                int idx = t + i * 256;
                pa[i] = __ldg(&A[(size_t)(m0 + (idx >> 4)) * lda + kn + (idx & 15)]);
            }
#pragma unroll
            for (int i = 0; i < 4; i++) {
                int idx = t + i * 256;
                pb[i] = __ldg(&Bz[(size_t)(kn + (idx >> 6)) * N + n0 + (idx & 63)]);
            }
        }
#pragma unroll
        for (int kk = 0; kk < 16; kk++) {
            float a[8], bb[4];
            *(float4*)&a[0] = *(const float4*)&As[kk][ty * 8];
            *(float4*)&a[4] = *(const float4*)&As[kk][ty * 8 + 4];
            *(float4*)&bb[0] = *(const float4*)&Bs[kk][tx * 4];
#pragma unroll
            for (int i = 0; i < 8; i++)
#pragma unroll
                for (int j = 0; j < 4; j++) acc[i][j] += a[i] * bb[j];
        }
        __syncthreads();
    }
#pragma unroll
    for (int i = 0; i < 8; i++)
#pragma unroll
        for (int j = 0; j < 4; j++)
            Cz[(size_t)(m0 + ty * 8 + i) * ldc + n0 + tx * 4 + j] = acc[i][j];
}

// ---------------- init ----------------
__global__ void init_k(const float* __restrict__ goal0, const float* __restrict__ w0,
                       float* __restrict__ outGoals, float* __restrict__ outWs) {
    int idx = blockIdx.x * blockDim.x + threadIdx.x;
    if (idx < 2 * B * HW) { g_wh0[idx] = 0.f; g_wh1[idx] = 0.f; }
    if (idx < B * HW)     { g_wc0[idx] = 0.f; g_wc1[idx] = 0.f; }
    if (idx < 2 * B * HG) { g_gh0[idx] = 0.f; g_gh1[idx] = 0.f; }
    if (idx < B * HG)     { g_gc0[idx] = 0.f; g_gc1[idx] = 0.f; }
    if (idx < B * DOF) {
        int b = idx / DOF, d = idx - b * DOF;
        float v = goal0[idx];
        g_cat[b * CATD + d] = v;
        outGoals[(size_t)b * MS * DOF + d] = v;
    }
    if (idx < B * WSZ) {
        int b = idx / WSZ, d = idx - b * WSZ;
        float v = w0[idx];
        g_cat[b * CATD + DOF + d] = v;
        outWs[(size_t)b * MS * WSZ + d] = v;
    }
}

// ---------------- 64x64 TN GEMM tile, reg prefetch, 3 modes --------------------------
// MODE 0: C = tanh(A@W^T + b1)
// MODE 1: fused LSTM gates, dual-K (A@Wih^T + Hold@Whh^T), columns gate-interleaved:
//         tile col c -> h-unit n0+(c>>2), gate c&3 (i,f,g,o). Epilogue does pointwise.
//         C = c_state (in/out), C2 = h_new. b1=bih, b2=bhh.
// MODE 2: C (and C2) = A@W^T + b1, N-guarded.
template<int MODE>
__device__ __forceinline__ void gemm64(
        const float* __restrict__ A, int lda, int K,
        const float* __restrict__ W,
        const float* __restrict__ A2, int K2, const float* __restrict__ W2,
        const float* __restrict__ b1, const float* __restrict__ b2,
        float* C, int ldc, float* C2, int ldc2,
        int N, int H, int m0, int n0, float* sm) {
    float (*As)[68] = (float(*)[68])sm;
    float (*Ws)[68] = (float(*)[68])(sm + 16 * 68);
    int t = threadIdx.x;
    int tx = t & 15, ty = t >> 4;
    float acc[4][4];
#pragma unroll
    for (int i = 0; i < 4; i++)
#pragma unroll
        for (int j = 0; j < 4; j++) acc[i][j] = 0.f;

    const int nch0 = K >> 4;
    const int nch  = nch0 + ((MODE == 1) ? (K2 >> 4) : 0);

    float pa[4], pw[4];
    auto lf = [&](int ch) {
        const float* Ac; const float* Wc; int ldac, Kc, k0;
        if (MODE == 1 && ch >= nch0) {
            Ac = A2; Wc = W2; ldac = K2; Kc = K2; k0 = (ch - nch0) << 4;
        } else {
            Ac = A; Wc = W; ldac = lda; Kc = K; k0 = ch << 4;
        }
#pragma unroll
        for (int i = 0; i < 4; i++) {
            int idx = t + (i << 8);
            int r = idx >> 4, c = idx & 15;
            pa[i] = Ac[(size_t)(m0 + r) * ldac + k0 + c];
            int rg;
            if (MODE == 1) rg = (r & 3) * H + n0 + (r >> 2);
            else           rg = n0 + r;
            pw[i] = (MODE == 2 && rg >= N) ? 0.f : __ldg(Wc + (size_t)rg * Kc + k0 + c);
        }
    };
    lf(0);
    for (int ch = 0; ch < nch; ch++) {
#pragma unroll
        for (int i = 0; i < 4; i++) {
            int idx = t + (i << 8);
            As[idx & 15][idx >> 4] = pa[i];
            Ws[idx & 15][idx >> 4] = pw[i];
        }
        __syncthreads();
        if (ch + 1 < nch) lf(ch + 1);
#pragma unroll
        for (int kk = 0; kk < 16; kk++) {
            float a[4], w[4];
            *(float4*)&a[0] = *(const float4*)&As[kk][ty * 4];
            *(float4*)&w[0] = *(const float4*)&Ws[kk][tx * 4];
#pragma unroll
            for (int i = 0; i < 4; i++)
#pragma unroll
                for (int j = 0; j < 4; j++) acc[i][j] += a[i] * w[j];
        }
        __syncthreads();
    }

    if (MODE == 1) {
        int u = n0 + tx;
        float bi = __ldg(b1 + u)         + __ldg(b2 + u);
        float bf = __ldg(b1 + H + u)     + __ldg(b2 + H + u);
        float bgg = __ldg(b1 + 2 * H + u) + __ldg(b2 + 2 * H + u);
        float bo = __ldg(b1 + 3 * H + u) + __ldg(b2 + 3 * H + u);
#pragma unroll
        for (int i = 0; i < 4; i++) {
            int m = m0 + ty * 4 + i;
            float ig = sigf(acc[i][0] + bi);
            float fg = sigf(acc[i][1] + bf);
            float gg = tanhf(acc[i][2] + bgg);
            float og = sigf(acc[i][3] + bo);
            int li = m * H + u;
            float cn = fg * C[li] + ig * gg;
            C[li] = cn;
            C2[li] = og * tanhf(cn);
        }
    } else {
#pragma unroll
        for (int i = 0; i < 4; i++) {
            int m = m0 + ty * 4 + i;
#pragma unroll
            for (int j = 0; j < 4; j++) {
                int n = n0 + tx * 4 + j;
                if (MODE == 0) {
                    C[(size_t)m * ldc + n] = tanhf(acc[i][j] + __ldg(b1 + n));
                } else if (n < N) {
                    float v = acc[i][j] + __ldg(b1 + n);
                    C[(size_t)m * ldc + n] = v;
                    C2[(size_t)m * ldc2 + n] = v;
                }
            }
        }
    }
}

// ---------------- phase kernels ----------------
// Phase A: bilinear  y = Aw.cat + bw_b ; x = Ag.pg + bg_b
__global__ __launch_bounds__(256) void bilinear_k(const float* __restrict__ bw_b,
                                                  const float* __restrict__ bg_b) {
    __shared__ float sc[CATD];
    int b = blockIdx.x, part = blockIdx.y;
    int t = threadIdx.x;
    for (int k = t; k < CATD; k += 256) sc[k] = g_cat[b * CATD + k];
    __syncthreads();
    if (part < 2) {
        int o = part * 256 + t;
        const float* a = g_Aw + (size_t)b * CATD * PW + o;
        float acc0 = __ldg(&bw_b[o]), acc1 = 0.f;
#pragma unroll 6
        for (int j = 0; j < CATD; j += 2) {
            acc0 += a[(size_t)j * PW] * sc[j];
            acc1 += a[(size_t)(j + 1) * PW] * sc[j + 1];
        }
        g_yw[b * PW + o] = acc0 + acc1;
    } else {
        int o = t;
        const float* a = g_Ag + (size_t)b * DOF * PG + o;
        float acc = __ldg(&bg_b[o]);
#pragma unroll
        for (int j = 0; j < DOF; j++) acc += a[j * PG] * sc[j];
        g_xg[b * PG + o] = acc;
    }
}

// Phase B: fc + tanh.  blocks 0..15: g (16 tiles), 16..47: w (32 tiles)
__global__ __launch_bounds__(256) void fc_k(const float* __restrict__ fcw_W,
                                            const float* __restrict__ fcw_b,
                                            const float* __restrict__ fcg_W,
                                            const float* __restrict__ fcg_b) {
    __shared__ float sm[2 * 16 * 68];
    int u = blockIdx.x;
    if (u < 16) {
        int n0 = (u & 3) * 64, m0 = (u >> 2) * 64;
        gemm64<0>(g_xg, PG, PG, fcg_W, nullptr, 0, nullptr, fcg_b, nullptr,
                  g_x2, PG, nullptr, 0, PG, 0, m0, n0, sm);
    } else {
        int v = u - 16;
        int n0 = (v & 7) * 64, m0 = (v >> 3) * 64;
        gemm64<0>(g_yw, PW, PW, fcw_W, nullptr, 0, nullptr, fcw_b, nullptr,
                  g_y2, PW, nullptr, 0, PW, 0, m0, n0, sm);
    }
}

// Gates (one LSTM layer, both chains) fused with pointwise.
// blocks 0..63: g (64 tiles), 64..191: w (128 tiles)
__global__ __launch_bounds__(256) void gates_k(
        const float* __restrict__ gA, const float* __restrict__ gHold,
        const float* __restrict__ gWih, const float* __restrict__ gWhh,
        const float* __restrict__ gbih, const float* __restrict__ gbhh,
        float* gC, float* gHnew, int gKin,
        const float* __restrict__ wA, const float* __restrict__ wHold,
        const float* __restrict__ wWih, const float* __restrict__ wWhh,
        const float* __restrict__ wbih, const float* __restrict__ wbhh,
        float* wC, float* wHnew, int wKin) {
    __shared__ float sm[2 * 16 * 68];
    int u = blockIdx.x;
    if (u < 64) {
        int h0 = (u & 15) * 16, m0 = (u >> 4) * 64;
        gemm64<1>(gA, gKin, gKin, gWih, gHold, HG, gWhh,
                  gbih, gbhh, gC, 0, gHnew, 0, 0, HG, m0, h0, sm);
    } else {
        int v = u - 64;
        int h0 = (v & 31) * 16, m0 = (v >> 5) * 64;
        gemm64<1>(wA, wKin, wKin, wWih, wHold, HW, wWhh,
                  wbih, wbhh, wC, 0, wHnew, 0, 0, HW, m0, h0, sm);
    }
}

// Output heads. blocks 0..3: g (4 m-tiles, N=6), 4..23: w (20 tiles, N=300)
__global__ __launch_bounds__(256) void heads_k(
        const float* __restrict__ gH, const float* __restrict__ og_W,
        const float* __restrict__ og_b, float* goalsOut,
        const float* __restrict__ wH, const float* __restrict__ ow_W,
        const float* __restrict__ ow_b, float* wsOut) {
    __shared__ float sm[2 * 16 * 68];
    int u = blockIdx.x;
    if (u < 4) {
        int m0 = u * 64;
        gemm64<2>(gH, HG, HG, og_W, nullptr, 0, nullptr, og_b, nullptr,
                  goalsOut, MS * DOF, g_cat, CATD, DOF, 0, m0, 0, sm);
    } else {
        int v = u - 4;
        int n0 = (v % 5) * 64, m0 = (v / 5) * 64;
        gemm64<2>(wH, HW, HW, ow_W, nullptr, 0, nullptr, ow_b, nullptr,
                  wsOut, MS * WSZ, g_cat + DOF, CATD, WSZ, 0, m0, n0, sm);
    }
}

// ---------------- host ----------------
extern "C" void kernel_launch(void* const* d_in, const int* in_sizes, int n_in,
                              void* d_out, int out_size) {
    const float* ctx    = (const float*)d_in[0];
    const float* goal0  = (const float*)d_in[1];
    const float* w0     = (const float*)d_in[2];
    const float* bg_W   = (const float*)d_in[3];
    const float* bg_b   = (const float*)d_in[4];
    const float* bw_W   = (const float*)d_in[5];
    const float* bw_b   = (const float*)d_in[6];
    const float* fcg_W  = (const float*)d_in[7];
    const float* fcg_b  = (const float*)d_in[8];
    const float* fcw_W  = (const float*)d_in[9];
    const float* fcw_b  = (const float*)d_in[10];
    const float* lg_Wih = (const float*)d_in[11];
    const float* lg_Whh = (const float*)d_in[12];
    const float* lg_bih = (const float*)d_in[13];
    const float* lg_bhh = (const float*)d_in[14];
    const float* lw_Wih = (const float*)d_in[15];
    const float* lw_Whh = (const float*)d_in[16];
    const float* lw_bih = (const float*)d_in[17];
    const float* lw_bhh = (const float*)d_in[18];
    const float* og_W   = (const float*)d_in[19];
    const float* og_b   = (const float*)d_in[20];
    const float* ow_W   = (const float*)d_in[21];
    const float* ow_b   = (const float*)d_in[22];

    float* out   = (float*)d_out;
    float* goals = out;                        // [B][MS][DOF]
    float* ws    = out + (size_t)B * MS * DOF; // [B][MS][WSZ]

    float *Wt, *Gt, *Aw, *Ag, *gh0, *gh1, *gc0, *gc1, *wh0, *wh1, *wc0, *wc1;
    cudaGetSymbolAddress((void**)&Wt, g_Wt);
    cudaGetSymbolAddress((void**)&Gt, g_Gt);
    cudaGetSymbolAddress((void**)&Aw, g_Aw);
    cudaGetSymbolAddress((void**)&Ag, g_Ag);
    cudaGetSymbolAddress((void**)&gh0, g_gh0);
    cudaGetSymbolAddress((void**)&gh1, g_gh1);
    cudaGetSymbolAddress((void**)&gc0, g_gc0);
    cudaGetSymbolAddress((void**)&gc1, g_gc1);
    cudaGetSymbolAddress((void**)&wh0, g_wh0);
    cudaGetSymbolAddress((void**)&wh1, g_wh1);
    cudaGetSymbolAddress((void**)&wc0, g_wc0);
    cudaGetSymbolAddress((void**)&wc1, g_wc1);

    float *xg, *x2, *yw, *y2;
    cudaGetSymbolAddress((void**)&xg, g_xg);
    cudaGetSymbolAddress((void**)&x2, g_x2);
    cudaGetSymbolAddress((void**)&yw, g_yw);
    cudaGetSymbolAddress((void**)&y2, g_y2);

    dim3 tblk(32, 32);
    transpose_oij_jio<<<dim3(CTXD, PW / 32, (CATD + 31) / 32), tblk>>>(bw_W, Wt, PW, CTXD, CATD);
    transpose_oij_jio<<<dim3(CTXD, PG / 32, 1), tblk>>>(bg_W, Gt, PG, CTXD, DOF);

    gemm_nn_batched<<<dim3(PW / 64, B / 128, CATD), 256>>>(
        ctx, CTXD, Wt, (size_t)CTXD * PW, Aw, CATD * PW, PW, PW, CTXD);
    gemm_nn_batched<<<dim3(PG / 64, B / 128, DOF), 256>>>(
        ctx, CTXD, Gt, (size_t)CTXD * PG, Ag, DOF * PG, PG, PG, CTXD);

    init_k<<<(2 * B * HW) / 256, 256>>>(goal0, w0, goals, ws);

    for (int s = 0; s < NSTEPS; s++) {
        const int p = s & 1;
        float* gh0r = gh0 + p * (B * HG);
        float* gh0w = gh0 + (p ^ 1) * (B * HG);
        float* gh1r = gh1 + p * (B * HG);
        float* gh1w = gh1 + (p ^ 1) * (B * HG);
        float* wh0r = wh0 + p * (B * HW);
        float* wh0w = wh0 + (p ^ 1) * (B * HW);
        float* wh1r = wh1 + p * (B * HW);
        float* wh1w = wh1 + (p ^ 1) * (B * HW);

        bilinear_k<<<dim3(B, 3), 256>>>(bw_b, bg_b);

        fc_k<<<48, 256>>>(fcw_W, fcw_b, fcg_W, fcg_b);

        gates_k<<<192, 256>>>(
            x2, gh0r, lg_Wih, lg_Whh, lg_bih, lg_bhh, gc0, gh0w, PG,
            y2, wh0r, lw_Wih, lw_Whh, lw_bih, lw_bhh, wc0, wh0w, PW);

        gates_k<<<192, 256>>>(
            gh0w, gh1r, lg_Wih + (size_t)4 * HG * PG, lg_Whh + (size_t)4 * HG * HG,
            lg_bih + 4 * HG, lg_bhh + 4 * HG, gc1, gh1w, HG,
            wh0w, wh1r, lw_Wih + (size_t)4 * HW * PW, lw_Whh + (size_t)4 * HW * HW,
            lw_bih + 4 * HW, lw_bhh + 4 * HW, wc1, wh1w, HW);

        heads_k<<<24, 256>>>(gh1w, og_W, og_b, goals + (size_t)(s + 1) * DOF,
                             wh1w, ow_W, ow_b, ws + (size_t)(s + 1) * WSZ);
    }
    (void)in_sizes; (void)n_in; (void)out_size;
}

// round 7
// speedup vs baseline: 2.1698x; 1.0831x over previous
#include <cuda_runtime.h>
#include <cuda_bf16.h>
#include <math.h>
#include <stdint.h>

#define B    256
#define CTXD 512
#define DOF  6
#define WSZ  300
#define CATD 306
#define PG   256
#define PW   512
#define HG   256
#define HW   512
#define MS   20
#define NSTEPS 19

// ---------------- device scratch ----------------
__device__ __nv_bfloat16 g_Whi[(size_t)CATD * PW * CTXD];  // [j][o][i]
__device__ __nv_bfloat16 g_Wlo[(size_t)CATD * PW * CTXD];
__device__ __nv_bfloat16 g_ctx_hi[B * CTXD];
__device__ __nv_bfloat16 g_ctx_lo[B * CTXD];
__device__ float g_Gt[(size_t)DOF * CTXD * PG];            // [j][i][o]
__device__ float g_Aw[(size_t)B * CATD * PW];              // [b][j][o]
__device__ float g_Ag[(size_t)B * DOF * PG];               // [b][j][o]
__device__ float g_xg[B * PG];
__device__ float g_x2[B * PG];
__device__ float g_yw[B * PW];
__device__ float g_y2[B * PW];
__device__ float g_cat[B * CATD];
__device__ float g_gh0[2 * B * HG];
__device__ float g_gh1[2 * B * HG];
__device__ float g_gc0[B * HG];
__device__ float g_gc1[B * HG];
__device__ float g_wh0[2 * B * HW];
__device__ float g_wh1[2 * B * HW];
__device__ float g_wc0[B * HW];
__device__ float g_wc1[B * HW];

__device__ __forceinline__ float sigf(float x) { return 1.f / (1.f + expf(-x)); }

__device__ __forceinline__ uint32_t smem_u32(const void* p) {
    uint32_t a;
    asm("{ .reg .u64 tmp; cvta.to.shared.u64 tmp, %1; cvt.u32.u64 %0, tmp; }" : "=r"(a) : "l"(p));
    return a;
}

// ---------------- split ctx into bf16 hi/lo ----------------
__global__ void split_ctx(const float* __restrict__ ctx) {
    int i = blockIdx.x * 256 + threadIdx.x;
    float x = ctx[i];
    __nv_bfloat16 hi = __float2bfloat16(x);
    g_ctx_hi[i] = hi;
    g_ctx_lo[i] = __float2bfloat16(x - __bfloat162float(hi));
}

// ---------------- transpose bw_W (o,i,j) -> hi/lo [j][o][i] ----------------
__global__ void transpose_bw_split(const float* __restrict__ in) {
    __shared__ float tile[32][33];
    int i0 = blockIdx.x * 32;
    int o  = blockIdx.y;
    int j0 = blockIdx.z * 32;
    int tx = threadIdx.x, ty = threadIdx.y;
    int j = j0 + tx;
    if (j < CATD)
        tile[ty][tx] = in[(size_t)o * CTXD * CATD + (size_t)(i0 + ty) * CATD + j];
    __syncthreads();
    int jw = j0 + ty;
    if (jw < CATD) {
        float v = tile[tx][ty];
        __nv_bfloat16 hi = __float2bfloat16(v);
        __nv_bfloat16 lo = __float2bfloat16(v - __bfloat162float(hi));
        size_t base = ((size_t)jw * PW + o) * CTXD + i0 + tx;
        g_Whi[base] = hi;
        g_Wlo[base] = lo;
    }
}

// ---------------- mma.sync bf16 precompute: Aw[b][j][o] = ctx[b,:] . W[j][o][:] -----
// grid (PW/64, B/128, CATD), 256 threads (8 warps, 4x2), 128x64 C tile.
#define A_STRIDE 72
#define B_STRIDE 72

__global__ __launch_bounds__(256) void aw_mma_kernel() {
    __shared__ __nv_bfloat16 sA[128 * A_STRIDE];
    __shared__ __nv_bfloat16 sB[64 * B_STRIDE];
    int t = threadIdx.x;
    int lane = t & 31, wid = t >> 5;
    int warp_m = wid & 3, warp_n = wid >> 2;    // 4 x 2
    int n0 = blockIdx.x * 64;
    int m0 = blockIdx.y * 128;
    int j  = blockIdx.z;

    float acc[2][4][4];
#pragma unroll
    for (int a = 0; a < 2; a++)
#pragma unroll
        for (int b = 0; b < 4; b++)
#pragma unroll
            for (int c = 0; c < 4; c++) acc[a][b][c] = 0.f;

    const __nv_bfloat16* Bhi = g_Whi + (size_t)j * PW * CTXD;
    const __nv_bfloat16* Blo = g_Wlo + (size_t)j * PW * CTXD;

    // ldmatrix lane addressing (computed once)
    int a_mloc = (lane < 16) ? lane : lane - 16;
    int a_koff = (lane >> 4) * 8;
    int b_nfsel = lane >> 4;          // which nfrag within pair
    int b_khalf = (lane >> 3) & 1;    // k lo/hi 8
    int b_nloc = lane & 7;

    for (int pass = 0; pass < 3; pass++) {
        const __nv_bfloat16* Ag = (pass == 2) ? g_ctx_lo : g_ctx_hi;
        const __nv_bfloat16* Bg = (pass == 1) ? Blo : Bhi;
        for (int k0 = 0; k0 < CTXD; k0 += 64) {
            // load A 128x64 bf16 (1024 16B segs / 256 thr = 4 each)
#pragma unroll
            for (int i = 0; i < 4; i++) {
                int idx = t + i * 256;
                int r = idx >> 3, sg = idx & 7;
                *(uint4*)&sA[r * A_STRIDE + sg * 8] =
                    *(const uint4*)(Ag + (size_t)(m0 + r) * CTXD + k0 + sg * 8);
            }
            // load B 64x64 bf16 (512 segs / 256 thr = 2 each)
#pragma unroll
            for (int i = 0; i < 2; i++) {
                int idx = t + i * 256;
                int r = idx >> 3, sg = idx & 7;
                *(uint4*)&sB[r * B_STRIDE + sg * 8] =
                    *(const uint4*)(Bg + (size_t)(n0 + r) * CTXD + k0 + sg * 8);
            }
            __syncthreads();
#pragma unroll
            for (int kk = 0; kk < 4; kk++) {
                int kb = kk * 16;
                uint32_t a[2][4];
#pragma unroll
                for (int mf = 0; mf < 2; mf++) {
                    uint32_t addr = smem_u32(&sA[(warp_m * 32 + mf * 16 + a_mloc) * A_STRIDE + kb + a_koff]);
                    asm volatile("ldmatrix.sync.aligned.m8n8.x4.shared.b16 {%0,%1,%2,%3}, [%4];"
                                 : "=r"(a[mf][0]), "=r"(a[mf][1]), "=r"(a[mf][2]), "=r"(a[mf][3])
                                 : "r"(addr));
                }
                uint32_t bfr[4][2];
#pragma unroll
                for (int bp = 0; bp < 2; bp++) {
                    uint32_t addr = smem_u32(&sB[(warp_n * 32 + bp * 16 + b_nfsel * 8 + b_nloc) * B_STRIDE + kb + b_khalf * 8]);
                    asm volatile("ldmatrix.sync.aligned.m8n8.x4.shared.b16 {%0,%1,%2,%3}, [%4];"
                                 : "=r"(bfr[bp * 2][0]), "=r"(bfr[bp * 2][1]),
                                   "=r"(bfr[bp * 2 + 1][0]), "=r"(bfr[bp * 2 + 1][1])
                                 : "r"(addr));
                }
#pragma unroll
                for (int mf = 0; mf < 2; mf++)
#pragma unroll
                    for (int nf = 0; nf < 4; nf++) {
                        asm volatile(
                            "mma.sync.aligned.m16n8k16.row.col.f32.bf16.bf16.f32 "
                            "{%0,%1,%2,%3}, {%4,%5,%6,%7}, {%8,%9}, {%0,%1,%2,%3};"
                            : "+f"(acc[mf][nf][0]), "+f"(acc[mf][nf][1]),
                              "+f"(acc[mf][nf][2]), "+f"(acc[mf][nf][3])
                            : "r"(a[mf][0]), "r"(a[mf][1]), "r"(a[mf][2]), "r"(a[mf][3]),
                              "r"(bfr[nf][0]), "r"(bfr[nf][1]));
                    }
            }
            __syncthreads();
        }
    }

    // epilogue: thread (g,tg): rows g,g+8; cols 2tg,2tg+1 per 8-col nfrag
    int g = lane >> 2, tg = lane & 3;
#pragma unroll
    for (int mf = 0; mf < 2; mf++) {
        int row0 = m0 + warp_m * 32 + mf * 16 + g;
#pragma unroll
        for (int nf = 0; nf < 4; nf++) {
            int col = n0 + warp_n * 32 + nf * 8 + tg * 2;
            float* d0 = g_Aw + ((size_t)row0 * CATD + j) * PW + col;
            float* d1 = g_Aw + ((size_t)(row0 + 8) * CATD + j) * PW + col;
            d0[0] = acc[mf][nf][0]; d0[1] = acc[mf][nf][1];
            d1[0] = acc[mf][nf][2]; d1[1] = acc[mf][nf][3];
        }
    }
}

// ---------------- transpose (o,i,j) -> (j,i,o) for bg_W ----------------
__global__ void transpose_oij_jio(const float* __restrict__ in, float* __restrict__ out,
                                  int O, int I, int J) {
    __shared__ float tile[32][33];
    int i  = blockIdx.x;
    int o0 = blockIdx.y * 32;
    int j0 = blockIdx.z * 32;
    int tx = threadIdx.x, ty = threadIdx.y;
    int o = o0 + ty, j = j0 + tx;
    if (o < O && j < J)
        tile[ty][tx] = in[(size_t)o * I * J + (size_t)i * J + j];
    __syncthreads();
    int jo = j0 + ty, oo = o0 + tx;
    if (jo < J && oo < O)
        out[(size_t)jo * I * O + (size_t)i * O + oo] = tile[tx][ty];
}

// ---------------- fp32 SIMT GEMM for Ag (tiny) ----------------
__global__ __launch_bounds__(256, 2) void gemm_nn_batched(
        const float* __restrict__ A, int lda,
        const float* __restrict__ Bm, size_t bStrideZ,
        float* __restrict__ C, int ldc, int cStrideZ,
        int N, int K) {
    __shared__ float As[16][132];
    __shared__ float Bs[16][68];
    int z = blockIdx.z;
    const float* Bz = Bm + (size_t)z * bStrideZ;
    float* Cz = C + (size_t)z * cStrideZ;
    int m0 = blockIdx.y * 128, n0 = blockIdx.x * 64;
    int t = threadIdx.x;
    int tx = t & 15, ty = t >> 4;
    float acc[8][4];
#pragma unroll
    for (int i = 0; i < 8; i++)
#pragma unroll
        for (int j = 0; j < 4; j++) acc[i][j] = 0.f;

    float pa[8], pb[4];
#pragma unroll
    for (int i = 0; i < 8; i++) {
        int idx = t + i * 256;
        pa[i] = __ldg(&A[(size_t)(m0 + (idx >> 4)) * lda + (idx & 15)]);
    }
#pragma unroll
    for (int i = 0; i < 4; i++) {
        int idx = t + i * 256;
        pb[i] = __ldg(&Bz[(size_t)(idx >> 6) * N + n0 + (idx & 63)]);
    }
    for (int k0 = 0; k0 < K; k0 += 16) {
#pragma unroll
        for (int i = 0; i < 8; i++) {
            int idx = t + i * 256;
            As[idx & 15][idx >> 4] = pa[i];
        }
#pragma unroll
        for (int i = 0; i < 4; i++) {
            int idx = t + i * 256;
            Bs[idx >> 6][idx & 63] = pb[i];
        }
        __syncthreads();
        if (k0 + 16 < K) {
            int kn = k0 + 16;
#pragma unroll
            for (int i = 0; i < 8; i++) {
                int idx = t + i * 256;
                pa[i] = __ldg(&A[(size_t)(m0 + (idx >> 4)) * lda + kn + (idx & 15)]);
            }
#pragma unroll
            for (int i = 0; i < 4; i++) {
                int idx = t + i * 256;
                pb[i] = __ldg(&Bz[(size_t)(kn + (idx >> 6)) * N + n0 + (idx & 63)]);
            }
        }
#pragma unroll
        for (int kk = 0; kk < 16; kk++) {
            float a[8], bb[4];
            *(float4*)&a[0] = *(const float4*)&As[kk][ty * 8];
            *(float4*)&a[4] = *(const float4*)&As[kk][ty * 8 + 4];
            *(float4*)&bb[0] = *(const float4*)&Bs[kk][tx * 4];
#pragma unroll
            for (int i = 0; i < 8; i++)
#pragma unroll
                for (int j = 0; j < 4; j++) acc[i][j] += a[i] * bb[j];
        }
        __syncthreads();
    }
#pragma unroll
    for (int i = 0; i < 8; i++)
#pragma unroll
        for (int j = 0; j < 4; j++)
            Cz[(size_t)(m0 + ty * 8 + i) * ldc + n0 + tx * 4 + j] = acc[i][j];
}

// ---------------- init ----------------
__global__ void init_k(const float* __restrict__ goal0, const float* __restrict__ w0,
                       float* __restrict__ outGoals, float* __restrict__ outWs) {
    int idx = blockIdx.x * blockDim.x + threadIdx.x;
    if (idx < 2 * B * HW) { g_wh0[idx] = 0.f; g_wh1[idx] = 0.f; }
    if (idx < B * HW)     { g_wc0[idx] = 0.f; g_wc1[idx] = 0.f; }
    if (idx < 2 * B * HG) { g_gh0[idx] = 0.f; g_gh1[idx] = 0.f; }
    if (idx < B * HG)     { g_gc0[idx] = 0.f; g_gc1[idx] = 0.f; }
    if (idx < B * DOF) {
        int b = idx / DOF, d = idx - b * DOF;
        float v = goal0[idx];
        g_cat[b * CATD + d] = v;
        outGoals[(size_t)b * MS * DOF + d] = v;
    }
    if (idx < B * WSZ) {
        int b = idx / WSZ, d = idx - b * WSZ;
        float v = w0[idx];
        g_cat[b * CATD + DOF + d] = v;
        outWs[(size_t)b * MS * WSZ + d] = v;
    }
}

// ---------------- 64x64 TN GEMM tile, reg prefetch, 3 modes (from R5) ----------------
template<int MODE>
__device__ __forceinline__ void gemm64(
        const float* __restrict__ A, int lda, int K,
        const float* __restrict__ W,
        const float* __restrict__ A2, int K2, const float* __restrict__ W2,
        const float* __restrict__ b1, const float* __restrict__ b2,
        float* C, int ldc, float* C2, int ldc2,
        int N, int H, int m0, int n0, float* sm) {
    float (*As)[68] = (float(*)[68])sm;
    float (*Ws)[68] = (float(*)[68])(sm + 16 * 68);
    int t = threadIdx.x;
    int tx = t & 15, ty = t >> 4;
    float acc[4][4];
#pragma unroll
    for (int i = 0; i < 4; i++)
#pragma unroll
        for (int j = 0; j < 4; j++) acc[i][j] = 0.f;

    const int nch0 = K >> 4;
    const int nch  = nch0 + ((MODE == 1) ? (K2 >> 4) : 0);

    float pa[4], pw[4];
    auto lf = [&](int ch) {
        const float* Ac; const float* Wc; int ldac, Kc, k0;
        if (MODE == 1 && ch >= nch0) {
            Ac = A2; Wc = W2; ldac = K2; Kc = K2; k0 = (ch - nch0) << 4;
        } else {
            Ac = A; Wc = W; ldac = lda; Kc = K; k0 = ch << 4;
        }
#pragma unroll
        for (int i = 0; i < 4; i++) {
            int idx = t + (i << 8);
            int r = idx >> 4, c = idx & 15;
            pa[i] = Ac[(size_t)(m0 + r) * ldac + k0 + c];
            int rg;
            if (MODE == 1) rg = (r & 3) * H + n0 + (r >> 2);
            else           rg = n0 + r;
            pw[i] = (MODE == 2 && rg >= N) ? 0.f : __ldg(Wc + (size_t)rg * Kc + k0 + c);
        }
    };
    lf(0);
    for (int ch = 0; ch < nch; ch++) {
#pragma unroll
        for (int i = 0; i < 4; i++) {
            int idx = t + (i << 8);
            As[idx & 15][idx >> 4] = pa[i];
            Ws[idx & 15][idx >> 4] = pw[i];
        }
        __syncthreads();
        if (ch + 1 < nch) lf(ch + 1);
#pragma unroll
        for (int kk = 0; kk < 16; kk++) {
            float a[4], w[4];
            *(float4*)&a[0] = *(const float4*)&As[kk][ty * 4];
            *(float4*)&w[0] = *(const float4*)&Ws[kk][tx * 4];
#pragma unroll
            for (int i = 0; i < 4; i++)
#pragma unroll
                for (int j = 0; j < 4; j++) acc[i][j] += a[i] * w[j];
        }
        __syncthreads();
    }

    if (MODE == 1) {
        int u = n0 + tx;
        float bi  = __ldg(b1 + u)          + __ldg(b2 + u);
        float bf  = __ldg(b1 + H + u)      + __ldg(b2 + H + u);
        float bgg = __ldg(b1 + 2 * H + u)  + __ldg(b2 + 2 * H + u);
        float bo  = __ldg(b1 + 3 * H + u)  + __ldg(b2 + 3 * H + u);
#pragma unroll
        for (int i = 0; i < 4; i++) {
            int m = m0 + ty * 4 + i;
            float ig = sigf(acc[i][0] + bi);
            float fg = sigf(acc[i][1] + bf);
            float gg = tanhf(acc[i][2] + bgg);
            float og = sigf(acc[i][3] + bo);
            int li = m * H + u;
            float cn = fg * C[li] + ig * gg;
            C[li] = cn;
            C2[li] = og * tanhf(cn);
        }
    } else {
#pragma unroll
        for (int i = 0; i < 4; i++) {
            int m = m0 + ty * 4 + i;
#pragma unroll
            for (int j = 0; j < 4; j++) {
                int n = n0 + tx * 4 + j;
                if (MODE == 0) {
                    C[(size_t)m * ldc + n] = tanhf(acc[i][j] + __ldg(b1 + n));
                } else if (n < N) {
                    float v = acc[i][j] + __ldg(b1 + n);
                    C[(size_t)m * ldc + n] = v;
                    C2[(size_t)m * ldc2 + n] = v;
                }
            }
        }
    }
}

// ---------------- phase kernels (from R5) ----------------
__global__ __launch_bounds__(256) void bilinear_k(const float* __restrict__ bw_b,
                                                  const float* __restrict__ bg_b) {
    __shared__ float sc[CATD];
    int b = blockIdx.x, part = blockIdx.y;
    int t = threadIdx.x;
    for (int k = t; k < CATD; k += 256) sc[k] = g_cat[b * CATD + k];
    __syncthreads();
    if (part < 2) {
        int o = part * 256 + t;
        const float* a = g_Aw + (size_t)b * CATD * PW + o;
        float acc0 = __ldg(&bw_b[o]), acc1 = 0.f;
#pragma unroll 6
        for (int j = 0; j < CATD; j += 2) {
            acc0 += a[(size_t)j * PW] * sc[j];
            acc1 += a[(size_t)(j + 1) * PW] * sc[j + 1];
        }
        g_yw[b * PW + o] = acc0 + acc1;
    } else {
        int o = t;
        const float* a = g_Ag + (size_t)b * DOF * PG + o;
        float acc = __ldg(&bg_b[o]);
#pragma unroll
        for (int j = 0; j < DOF; j++) acc += a[j * PG] * sc[j];
        g_xg[b * PG + o] = acc;
    }
}

__global__ __launch_bounds__(256) void fc_k(const float* __restrict__ fcw_W,
                                            const float* __restrict__ fcw_b,
                                            const float* __restrict__ fcg_W,
                                            const float* __restrict__ fcg_b) {
    __shared__ float sm[2 * 16 * 68];
    int u = blockIdx.x;
    if (u < 16) {
        int n0 = (u & 3) * 64, m0 = (u >> 2) * 64;
        gemm64<0>(g_xg, PG, PG, fcg_W, nullptr, 0, nullptr, fcg_b, nullptr,
                  g_x2, PG, nullptr, 0, PG, 0, m0, n0, sm);
    } else {
        int v = u - 16;
        int n0 = (v & 7) * 64, m0 = (v >> 3) * 64;
        gemm64<0>(g_yw, PW, PW, fcw_W, nullptr, 0, nullptr, fcw_b, nullptr,
                  g_y2, PW, nullptr, 0, PW, 0, m0, n0, sm);
    }
}

__global__ __launch_bounds__(256) void gates_k(
        const float* __restrict__ gA, const float* __restrict__ gHold,
        const float* __restrict__ gWih, const float* __restrict__ gWhh,
        const float* __restrict__ gbih, const float* __restrict__ gbhh,
        float* gC, float* gHnew, int gKin,
        const float* __restrict__ wA, const float* __restrict__ wHold,
        const float* __restrict__ wWih, const float* __restrict__ wWhh,
        const float* __restrict__ wbih, const float* __restrict__ wbhh,
        float* wC, float* wHnew, int wKin) {
    __shared__ float sm[2 * 16 * 68];
    int u = blockIdx.x;
    if (u < 64) {
        int h0 = (u & 15) * 16, m0 = (u >> 4) * 64;
        gemm64<1>(gA, gKin, gKin, gWih, gHold, HG, gWhh,
                  gbih, gbhh, gC, 0, gHnew, 0, 0, HG, m0, h0, sm);
    } else {
        int v = u - 64;
        int h0 = (v & 31) * 16, m0 = (v >> 5) * 64;
        gemm64<1>(wA, wKin, wKin, wWih, wHold, HW, wWhh,
                  wbih, wbhh, wC, 0, wHnew, 0, 0, HW, m0, h0, sm);
    }
}

__global__ __launch_bounds__(256) void heads_k(
        const float* __restrict__ gH, const float* __restrict__ og_W,
        const float* __restrict__ og_b, float* goalsOut,
        const float* __restrict__ wH, const float* __restrict__ ow_W,
        const float* __restrict__ ow_b, float* wsOut) {
    __shared__ float sm[2 * 16 * 68];
    int u = blockIdx.x;
    if (u < 4) {
        int m0 = u * 64;
        gemm64<2>(gH, HG, HG, og_W, nullptr, 0, nullptr, og_b, nullptr,
                  goalsOut, MS * DOF, g_cat, CATD, DOF, 0, m0, 0, sm);
    } else {
        int v = u - 4;
        int n0 = (v % 5) * 64, m0 = (v / 5) * 64;
        gemm64<2>(wH, HW, HW, ow_W, nullptr, 0, nullptr, ow_b, nullptr,
                  wsOut, MS * WSZ, g_cat + DOF, CATD, WSZ, 0, m0, n0, sm);
    }
}

// ---------------- host ----------------
extern "C" void kernel_launch(void* const* d_in, const int* in_sizes, int n_in,
                              void* d_out, int out_size) {
    const float* ctx    = (const float*)d_in[0];
    const float* goal0  = (const float*)d_in[1];
    const float* w0     = (const float*)d_in[2];
    const float* bg_W   = (const float*)d_in[3];
    const float* bg_b   = (const float*)d_in[4];
    const float* bw_W   = (const float*)d_in[5];
    const float* bw_b   = (const float*)d_in[6];
    const float* fcg_W  = (const float*)d_in[7];
    const float* fcg_b  = (const float*)d_in[8];
    const float* fcw_W  = (const float*)d_in[9];
    const float* fcw_b  = (const float*)d_in[10];
    const float* lg_Wih = (const float*)d_in[11];
    const float* lg_Whh = (const float*)d_in[12];
    const float* lg_bih = (const float*)d_in[13];
    const float* lg_bhh = (const float*)d_in[14];
    const float* lw_Wih = (const float*)d_in[15];
    const float* lw_Whh = (const float*)d_in[16];
    const float* lw_bih = (const float*)d_in[17];
    const float* lw_bhh = (const float*)d_in[18];
    const float* og_W   = (const float*)d_in[19];
    const float* og_b   = (const float*)d_in[20];
    const float* ow_W   = (const float*)d_in[21];
    const float* ow_b   = (const float*)d_in[22];

    float* out   = (float*)d_out;
    float* goals = out;
    float* ws    = out + (size_t)B * MS * DOF;

    float *Gt, *Ag, *gh0, *gh1, *gc0, *gc1, *wh0, *wh1, *wc0, *wc1, *xg, *x2, *yw, *y2;
    cudaGetSymbolAddress((void**)&Gt, g_Gt);
    cudaGetSymbolAddress((void**)&Ag, g_Ag);
    cudaGetSymbolAddress((void**)&gh0, g_gh0);
    cudaGetSymbolAddress((void**)&gh1, g_gh1);
    cudaGetSymbolAddress((void**)&gc0, g_gc0);
    cudaGetSymbolAddress((void**)&gc1, g_gc1);
    cudaGetSymbolAddress((void**)&wh0, g_wh0);
    cudaGetSymbolAddress((void**)&wh1, g_wh1);
    cudaGetSymbolAddress((void**)&wc0, g_wc0);
    cudaGetSymbolAddress((void**)&wc1, g_wc1);
    cudaGetSymbolAddress((void**)&xg, g_xg);
    cudaGetSymbolAddress((void**)&x2, g_x2);
    cudaGetSymbolAddress((void**)&yw, g_yw);
    cudaGetSymbolAddress((void**)&y2, g_y2);

    // precompute path (bf16 split + HMMA)
    split_ctx<<<(B * CTXD) / 256, 256>>>(ctx);
    transpose_bw_split<<<dim3(CTXD / 32, PW, (CATD + 31) / 32), dim3(32, 32)>>>(bw_W);
    aw_mma_kernel<<<dim3(PW / 64, B / 128, CATD), 256>>>();

    dim3 tblk(32, 32);
    transpose_oij_jio<<<dim3(CTXD, PG / 32, 1), tblk>>>(bg_W, Gt, PG, CTXD, DOF);
    gemm_nn_batched<<<dim3(PG / 64, B / 128, DOF), 256>>>(
        ctx, CTXD, Gt, (size_t)CTXD * PG, Ag, DOF * PG, PG, PG, CTXD);

    init_k<<<(2 * B * HW) / 256, 256>>>(goal0, w0, goals, ws);

    for (int s = 0; s < NSTEPS; s++) {
        const int p = s & 1;
        float* gh0r = gh0 + p * (B * HG);
        float* gh0w = gh0 + (p ^ 1) * (B * HG);
        float* gh1r = gh1 + p * (B * HG);
        float* gh1w = gh1 + (p ^ 1) * (B * HG);
        float* wh0r = wh0 + p * (B * HW);
        float* wh0w = wh0 + (p ^ 1) * (B * HW);
        float* wh1r = wh1 + p * (B * HW);
        float* wh1w = wh1 + (p ^ 1) * (B * HW);

        bilinear_k<<<dim3(B, 3), 256>>>(bw_b, bg_b);
        fc_k<<<48, 256>>>(fcw_W, fcw_b, fcg_W, fcg_b);
        gates_k<<<192, 256>>>(
            x2, gh0r, lg_Wih, lg_Whh, lg_bih, lg_bhh, gc0, gh0w, PG,
            y2, wh0r, lw_Wih, lw_Whh, lw_bih, lw_bhh, wc0, wh0w, PW);
        gates_k<<<192, 256>>>(
            gh0w, gh1r, lg_Wih + (size_t)4 * HG * PG, lg_Whh + (size_t)4 * HG * HG,
            lg_bih + 4 * HG, lg_bhh + 4 * HG, gc1, gh1w, HG,
            wh0w, wh1r, lw_Wih + (size_t)4 * HW * PW, lw_Whh + (size_t)4 * HW * HW,
            lw_bih + 4 * HW, lw_bhh + 4 * HW, wc1, wh1w, HW);
        heads_k<<<24, 256>>>(gh1w, og_W, og_b, goals + (size_t)(s + 1) * DOF,
                             wh1w, ow_W, ow_b, ws + (size_t)(s + 1) * WSZ);
    }
    (void)in_sizes; (void)n_in; (void)out_size;
}

// round 8
// speedup vs baseline: 2.8189x; 1.2992x over previous
#include <cuda_runtime.h>
#include <cuda_bf16.h>
#include <math.h>
#include <stdint.h>

#define B    256
#define CTXD 512
#define DOF  6
#define WSZ  300
#define CATD 306
#define PG   256
#define PW   512
#define HG   256
#define HW   512
#define MS   20
#define NSTEPS 19

typedef __nv_bfloat16 bf16;

// ---------------- device scratch ----------------
__device__ bf16 g_Whi[(size_t)CATD * PW * CTXD];  // [j][o][i]
__device__ bf16 g_Wlo[(size_t)CATD * PW * CTXD];
__device__ bf16 g_ctx_hi[B * CTXD];
__device__ bf16 g_ctx_lo[B * CTXD];
__device__ float g_Gt[(size_t)DOF * CTXD * PG];
__device__ float g_Aw[(size_t)B * CATD * PW];
__device__ float g_Ag[(size_t)B * DOF * PG];
__device__ float g_xg[B * PG];
__device__ float g_x2[B * PG];
__device__ bf16  g_x2h[B * PG];
__device__ bf16  g_x2l[B * PG];
__device__ float g_yw[B * PW];
__device__ float g_y2[B * PW];
__device__ bf16  g_y2h[B * PW];
__device__ bf16  g_y2l[B * PW];
__device__ float g_cat[B * CATD];
__device__ float g_gh0[2 * B * HG];
__device__ float g_gh1[2 * B * HG];
__device__ bf16  g_gh0h[2 * B * HG];
__device__ bf16  g_gh0l[2 * B * HG];
__device__ bf16  g_gh1h[2 * B * HG];
__device__ bf16  g_gh1l[2 * B * HG];
__device__ float g_gc0[B * HG];
__device__ float g_gc1[B * HG];
__device__ float g_wh0[2 * B * HW];
__device__ float g_wh1[2 * B * HW];
__device__ bf16  g_wh0h[2 * B * HW];
__device__ bf16  g_wh0l[2 * B * HW];
__device__ bf16  g_wh1h[2 * B * HW];
__device__ bf16  g_wh1l[2 * B * HW];
__device__ float g_wc0[B * HW];
__device__ float g_wc1[B * HW];
// packed gate-interleaved weights: row = u*4+gate, cols = Kin (Wih) then H (Whh)
__device__ bf16  g_WgL0h[4 * HG * (PG + HG)];
__device__ bf16  g_WgL0l[4 * HG * (PG + HG)];
__device__ bf16  g_WgL1h[4 * HG * (HG + HG)];
__device__ bf16  g_WgL1l[4 * HG * (HG + HG)];
__device__ bf16  g_WwL0h[(size_t)4 * HW * (PW + HW)];
__device__ bf16  g_WwL0l[(size_t)4 * HW * (PW + HW)];
__device__ bf16  g_WwL1h[(size_t)4 * HW * (HW + HW)];
__device__ bf16  g_WwL1l[(size_t)4 * HW * (HW + HW)];
__device__ float g_BgL0[4 * HG];
__device__ float g_BgL1[4 * HG];
__device__ float g_BwL0[4 * HW];
__device__ float g_BwL1[4 * HW];

__device__ __forceinline__ float sigf(float x) { return 1.f / (1.f + expf(-x)); }

__device__ __forceinline__ uint32_t smem_u32(const void* p) {
    uint32_t a;
    asm("{ .reg .u64 tmp; cvta.to.shared.u64 tmp, %1; cvt.u32.u64 %0, tmp; }" : "=r"(a) : "l"(p));
    return a;
}

// ---------------- split ctx into bf16 hi/lo ----------------
__global__ void split_ctx(const float* __restrict__ ctx) {
    int i = blockIdx.x * 256 + threadIdx.x;
    float x = ctx[i];
    bf16 hi = __float2bfloat16(x);
    g_ctx_hi[i] = hi;
    g_ctx_lo[i] = __float2bfloat16(x - __bfloat162float(hi));
}

// ---------------- transpose bw_W (o,i,j) -> hi/lo [j][o][i] ----------------
__global__ void transpose_bw_split(const float* __restrict__ in) {
    __shared__ float tile[32][33];
    int i0 = blockIdx.x * 32;
    int o  = blockIdx.y;
    int j0 = blockIdx.z * 32;
    int tx = threadIdx.x, ty = threadIdx.y;
    int j = j0 + tx;
    if (j < CATD)
        tile[ty][tx] = in[(size_t)o * CTXD * CATD + (size_t)(i0 + ty) * CATD + j];
    __syncthreads();
    int jw = j0 + ty;
    if (jw < CATD) {
        float v = tile[tx][ty];
        bf16 hi = __float2bfloat16(v);
        bf16 lo = __float2bfloat16(v - __bfloat162float(hi));
        size_t base = ((size_t)jw * PW + o) * CTXD + i0 + tx;
        g_Whi[base] = hi;
        g_Wlo[base] = lo;
    }
}

// ---------------- pack LSTM weights: gate-interleaved bf16 hi/lo + combined bias ----
__global__ void pack_w(const float* __restrict__ Wih, const float* __restrict__ Whh,
                       const float* __restrict__ bih, const float* __restrict__ bhh,
                       bf16* __restrict__ outH, bf16* __restrict__ outL,
                       float* __restrict__ outB, int H, int Kin) {
    int Kcat = Kin + H;
    size_t idx = (size_t)blockIdx.x * 256 + threadIdx.x;
    int r = (int)(idx / Kcat), k = (int)(idx % Kcat);
    int u = r >> 2, gate = r & 3, src = gate * H + u;
    float v = (k < Kin) ? Wih[(size_t)src * Kin + k] : Whh[(size_t)src * H + (k - Kin)];
    bf16 hi = __float2bfloat16(v);
    outH[idx] = hi;
    outL[idx] = __float2bfloat16(v - __bfloat162float(hi));
    if (k == 0) outB[r] = bih[src] + bhh[src];
}

// ---------------- mma.sync bf16 precompute (from R7, passing) ----------------
#define A_STRIDE 72
#define B_STRIDE 72

__global__ __launch_bounds__(256) void aw_mma_kernel() {
    __shared__ bf16 sA[128 * A_STRIDE];
    __shared__ bf16 sB[64 * B_STRIDE];
    int t = threadIdx.x;
    int lane = t & 31, wid = t >> 5;
    int warp_m = wid & 3, warp_n = wid >> 2;
    int n0 = blockIdx.x * 64;
    int m0 = blockIdx.y * 128;
    int j  = blockIdx.z;

    float acc[2][4][4];
#pragma unroll
    for (int a = 0; a < 2; a++)
#pragma unroll
        for (int b = 0; b < 4; b++)
#pragma unroll
            for (int c = 0; c < 4; c++) acc[a][b][c] = 0.f;

    const bf16* Bhi = g_Whi + (size_t)j * PW * CTXD;
    const bf16* Blo = g_Wlo + (size_t)j * PW * CTXD;

    int a_mloc = lane & 15;
    int a_koff = (lane >> 4) * 8;
    int b_nfsel = lane >> 4;
    int b_khalf = (lane >> 3) & 1;
    int b_nloc = lane & 7;

    for (int pass = 0; pass < 3; pass++) {
        const bf16* Ag = (pass == 2) ? g_ctx_lo : g_ctx_hi;
        const bf16* Bg = (pass == 1) ? Blo : Bhi;
        for (int k0 = 0; k0 < CTXD; k0 += 64) {
#pragma unroll
            for (int i = 0; i < 4; i++) {
                int idx = t + i * 256;
                int r = idx >> 3, sg = idx & 7;
                *(uint4*)&sA[r * A_STRIDE + sg * 8] =
                    *(const uint4*)(Ag + (size_t)(m0 + r) * CTXD + k0 + sg * 8);
            }
#pragma unroll
            for (int i = 0; i < 2; i++) {
                int idx = t + i * 256;
                int r = idx >> 3, sg = idx & 7;
                *(uint4*)&sB[r * B_STRIDE + sg * 8] =
                    *(const uint4*)(Bg + (size_t)(n0 + r) * CTXD + k0 + sg * 8);
            }
            __syncthreads();
#pragma unroll
            for (int kk = 0; kk < 4; kk++) {
                int kb = kk * 16;
                uint32_t a[2][4];
#pragma unroll
                for (int mf = 0; mf < 2; mf++) {
                    uint32_t addr = smem_u32(&sA[(warp_m * 32 + mf * 16 + a_mloc) * A_STRIDE + kb + a_koff]);
                    asm volatile("ldmatrix.sync.aligned.m8n8.x4.shared.b16 {%0,%1,%2,%3}, [%4];"
                                 : "=r"(a[mf][0]), "=r"(a[mf][1]), "=r"(a[mf][2]), "=r"(a[mf][3])
                                 : "r"(addr));
                }
                uint32_t bfr[4][2];
#pragma unroll
                for (int bp = 0; bp < 2; bp++) {
                    uint32_t addr = smem_u32(&sB[(warp_n * 32 + bp * 16 + b_nfsel * 8 + b_nloc) * B_STRIDE + kb + b_khalf * 8]);
                    asm volatile("ldmatrix.sync.aligned.m8n8.x4.shared.b16 {%0,%1,%2,%3}, [%4];"
                                 : "=r"(bfr[bp * 2][0]), "=r"(bfr[bp * 2][1]),
                                   "=r"(bfr[bp * 2 + 1][0]), "=r"(bfr[bp * 2 + 1][1])
                                 : "r"(addr));
                }
#pragma unroll
                for (int mf = 0; mf < 2; mf++)
#pragma unroll
                    for (int nf = 0; nf < 4; nf++) {
                        asm volatile(
                            "mma.sync.aligned.m16n8k16.row.col.f32.bf16.bf16.f32 "
                            "{%0,%1,%2,%3}, {%4,%5,%6,%7}, {%8,%9}, {%0,%1,%2,%3};"
                            : "+f"(acc[mf][nf][0]), "+f"(acc[mf][nf][1]),
                              "+f"(acc[mf][nf][2]), "+f"(acc[mf][nf][3])
                            : "r"(a[mf][0]), "r"(a[mf][1]), "r"(a[mf][2]), "r"(a[mf][3]),
                              "r"(bfr[nf][0]), "r"(bfr[nf][1]));
                    }
            }
            __syncthreads();
        }
    }

    int g = lane >> 2, tg = lane & 3;
#pragma unroll
    for (int mf = 0; mf < 2; mf++) {
        int row0 = m0 + warp_m * 32 + mf * 16 + g;
#pragma unroll
        for (int nf = 0; nf < 4; nf++) {
            int col = n0 + warp_n * 32 + nf * 8 + tg * 2;
            float* d0 = g_Aw + ((size_t)row0 * CATD + j) * PW + col;
            float* d1 = g_Aw + ((size_t)(row0 + 8) * CATD + j) * PW + col;
            d0[0] = acc[mf][nf][0]; d0[1] = acc[mf][nf][1];
            d1[0] = acc[mf][nf][2]; d1[1] = acc[mf][nf][3];
        }
    }
}

// ---------------- gates HMMA: dual-K (act||hold) x packed W, fused LSTM pointwise ----
__device__ __forceinline__ void gates_tile(
        const bf16* __restrict__ ActH, const bf16* __restrict__ ActL, int Kin,
        const bf16* __restrict__ HoldH, const bf16* __restrict__ HoldL,
        const bf16* __restrict__ WH, const bf16* __restrict__ WL,
        const float* __restrict__ biasCat,
        float* C, float* Hf, bf16* Hh, bf16* Hl,
        int H, int m0, int n0c, bf16* sm) {
    bf16* sAh = sm;
    bf16* sAl = sm + 64 * 72;
    bf16* sWh = sm + 2 * 64 * 72;
    bf16* sWl = sm + 3 * 64 * 72;
    int t = threadIdx.x, lane = t & 31, wid = t >> 5;
    int warp_m = wid & 1, warp_n = wid >> 1;
    int a_mloc = lane & 15;
    int a_koff = (lane >> 4) * 8;
    int b_nfsel = lane >> 4, b_khalf = (lane >> 3) & 1, b_nloc = lane & 7;

    float acc[2][4][4];
#pragma unroll
    for (int a = 0; a < 2; a++)
#pragma unroll
        for (int b = 0; b < 4; b++)
#pragma unroll
            for (int c = 0; c < 4; c++) acc[a][b][c] = 0.f;

    int Kcat = Kin + H;
    int nch = Kcat >> 6;
    for (int ch = 0; ch < nch; ch++) {
        int k0 = ch << 6;
        const bf16 *srcH, *srcL; int ld, off;
        if (k0 < Kin) { srcH = ActH; srcL = ActL; ld = Kin; off = k0; }
        else          { srcH = HoldH; srcL = HoldL; ld = H; off = k0 - Kin; }
#pragma unroll
        for (int i = 0; i < 4; i++) {
            int idx = t + i * 128;
            int r = idx >> 3, sg = idx & 7;
            *(uint4*)&sAh[r * 72 + sg * 8] = *(const uint4*)(srcH + (size_t)(m0 + r) * ld + off + sg * 8);
            *(uint4*)&sAl[r * 72 + sg * 8] = *(const uint4*)(srcL + (size_t)(m0 + r) * ld + off + sg * 8);
            *(uint4*)&sWh[r * 72 + sg * 8] = *(const uint4*)(WH + (size_t)(n0c + r) * Kcat + k0 + sg * 8);
            *(uint4*)&sWl[r * 72 + sg * 8] = *(const uint4*)(WL + (size_t)(n0c + r) * Kcat + k0 + sg * 8);
        }
        __syncthreads();
#pragma unroll
        for (int kk = 0; kk < 4; kk++) {
            int kb = kk * 16;
            uint32_t ah[2][4], al[2][4], wh[4][2], wl[4][2];
#pragma unroll
            for (int mf = 0; mf < 2; mf++) {
                uint32_t addr = smem_u32(&sAh[(warp_m * 32 + mf * 16 + a_mloc) * 72 + kb + a_koff]);
                asm volatile("ldmatrix.sync.aligned.m8n8.x4.shared.b16 {%0,%1,%2,%3}, [%4];"
                             : "=r"(ah[mf][0]), "=r"(ah[mf][1]), "=r"(ah[mf][2]), "=r"(ah[mf][3])
                             : "r"(addr));
                addr = smem_u32(&sAl[(warp_m * 32 + mf * 16 + a_mloc) * 72 + kb + a_koff]);
                asm volatile("ldmatrix.sync.aligned.m8n8.x4.shared.b16 {%0,%1,%2,%3}, [%4];"
                             : "=r"(al[mf][0]), "=r"(al[mf][1]), "=r"(al[mf][2]), "=r"(al[mf][3])
                             : "r"(addr));
            }
#pragma unroll
            for (int bp = 0; bp < 2; bp++) {
                uint32_t addr = smem_u32(&sWh[(warp_n * 32 + bp * 16 + b_nfsel * 8 + b_nloc) * 72 + kb + b_khalf * 8]);
                asm volatile("ldmatrix.sync.aligned.m8n8.x4.shared.b16 {%0,%1,%2,%3}, [%4];"
                             : "=r"(wh[bp * 2][0]), "=r"(wh[bp * 2][1]),
                               "=r"(wh[bp * 2 + 1][0]), "=r"(wh[bp * 2 + 1][1])
                             : "r"(addr));
                addr = smem_u32(&sWl[(warp_n * 32 + bp * 16 + b_nfsel * 8 + b_nloc) * 72 + kb + b_khalf * 8]);
                asm volatile("ldmatrix.sync.aligned.m8n8.x4.shared.b16 {%0,%1,%2,%3}, [%4];"
                             : "=r"(wl[bp * 2][0]), "=r"(wl[bp * 2][1]),
                               "=r"(wl[bp * 2 + 1][0]), "=r"(wl[bp * 2 + 1][1])
                             : "r"(addr));
            }
#pragma unroll
            for (int mf = 0; mf < 2; mf++)
#pragma unroll
                for (int nf = 0; nf < 4; nf++) {
                    asm volatile(
                        "mma.sync.aligned.m16n8k16.row.col.f32.bf16.bf16.f32 "
                        "{%0,%1,%2,%3}, {%4,%5,%6,%7}, {%8,%9}, {%0,%1,%2,%3};"
                        : "+f"(acc[mf][nf][0]), "+f"(acc[mf][nf][1]),
                          "+f"(acc[mf][nf][2]), "+f"(acc[mf][nf][3])
                        : "r"(ah[mf][0]), "r"(ah[mf][1]), "r"(ah[mf][2]), "r"(ah[mf][3]),
                          "r"(wh[nf][0]), "r"(wh[nf][1]));
                    asm volatile(
                        "mma.sync.aligned.m16n8k16.row.col.f32.bf16.bf16.f32 "
                        "{%0,%1,%2,%3}, {%4,%5,%6,%7}, {%8,%9}, {%0,%1,%2,%3};"
                        : "+f"(acc[mf][nf][0]), "+f"(acc[mf][nf][1]),
                          "+f"(acc[mf][nf][2]), "+f"(acc[mf][nf][3])
                        : "r"(ah[mf][0]), "r"(ah[mf][1]), "r"(ah[mf][2]), "r"(ah[mf][3]),
                          "r"(wl[nf][0]), "r"(wl[nf][1]));
                    asm volatile(
                        "mma.sync.aligned.m16n8k16.row.col.f32.bf16.bf16.f32 "
                        "{%0,%1,%2,%3}, {%4,%5,%6,%7}, {%8,%9}, {%0,%1,%2,%3};"
                        : "+f"(acc[mf][nf][0]), "+f"(acc[mf][nf][1]),
                          "+f"(acc[mf][nf][2]), "+f"(acc[mf][nf][3])
                        : "r"(al[mf][0]), "r"(al[mf][1]), "r"(al[mf][2]), "r"(al[mf][3]),
                          "r"(wh[nf][0]), "r"(wh[nf][1]));
                }
        }
        __syncthreads();
    }

    // epilogue: packed col pc = n0c + warp_n*32 + nf*8 + tg*2; gate = pc&3, u = pc>>2
    int g = lane >> 2, tg = lane & 3;
#pragma unroll
    for (int mf = 0; mf < 2; mf++) {
        int row = m0 + warp_m * 32 + mf * 16 + g;
#pragma unroll
        for (int nf = 0; nf < 4; nf++) {
            float* a = acc[mf][nf];
            float s0 = (tg & 1) ? a[0] : a[2];
            float r0 = __shfl_xor_sync(0xffffffffu, s0, 1);
            float s1 = (tg & 1) ? a[1] : a[3];
            float r1 = __shfl_xor_sync(0xffffffffu, s1, 1);
            int base = n0c + warp_n * 32 + nf * 8;
            int u_ = (base >> 2) + (tg >> 1);
            int rowi = (tg & 1) ? row + 8 : row;
            float iv, fv, gv, ov;
            if (tg & 1) { iv = r0; fv = r1; gv = a[2]; ov = a[3]; }
            else        { iv = a[0]; fv = a[1]; gv = r0; ov = r1; }
            float4 bb = *(const float4*)(biasCat + u_ * 4);
            float i_ = sigf(iv + bb.x), f_ = sigf(fv + bb.y);
            float g_ = tanhf(gv + bb.z), o_ = sigf(ov + bb.w);
            int li = rowi * H + u_;
            float cn = f_ * C[li] + i_ * g_;
            C[li] = cn;
            float h = o_ * tanhf(cn);
            Hf[li] = h;
            bf16 hh = __float2bfloat16(h);
            Hh[li] = hh;
            Hl[li] = __float2bfloat16(h - __bfloat162float(hh));
        }
    }
}

__global__ __launch_bounds__(128) void gates_hmma(
        const bf16* gActH, const bf16* gActL, int gKin,
        const bf16* gHoldH, const bf16* gHoldL,
        const bf16* gWH, const bf16* gWL, const float* gB,
        float* gC, float* gHf, bf16* gHh, bf16* gHl,
        const bf16* wActH, const bf16* wActL, int wKin,
        const bf16* wHoldH, const bf16* wHoldL,
        const bf16* wWH, const bf16* wWL, const float* wB,
        float* wC, float* wHf, bf16* wHh, bf16* wHl) {
    __shared__ bf16 sm[4 * 64 * 72];
    int u = blockIdx.x;
    if (u < 64) {
        int mt = u >> 4, nt = u & 15;
        gates_tile(gActH, gActL, gKin, gHoldH, gHoldL, gWH, gWL, gB,
                   gC, gHf, gHh, gHl, HG, mt * 64, nt * 64, sm);
    } else {
        int v = u - 64;
        int mt = v >> 5, nt = v & 31;
        gates_tile(wActH, wActL, wKin, wHoldH, wHoldL, wWH, wWL, wB,
                   wC, wHf, wHh, wHl, HW, mt * 64, nt * 64, sm);
    }
}

// ---------------- transpose (o,i,j) -> (j,i,o) for bg_W ----------------
__global__ void transpose_oij_jio(const float* __restrict__ in, float* __restrict__ out,
                                  int O, int I, int J) {
    __shared__ float tile[32][33];
    int i  = blockIdx.x;
    int o0 = blockIdx.y * 32;
    int j0 = blockIdx.z * 32;
    int tx = threadIdx.x, ty = threadIdx.y;
    int o = o0 + ty, j = j0 + tx;
    if (o < O && j < J)
        tile[ty][tx] = in[(size_t)o * I * J + (size_t)i * J + j];
    __syncthreads();
    int jo = j0 + ty, oo = o0 + tx;
    if (jo < J && oo < O)
        out[(size_t)jo * I * O + (size_t)i * O + oo] = tile[tx][ty];
}

// ---------------- fp32 SIMT GEMM for Ag (tiny) ----------------
__global__ __launch_bounds__(256, 2) void gemm_nn_batched(
        const float* __restrict__ A, int lda,
        const float* __restrict__ Bm, size_t bStrideZ,
        float* __restrict__ C, int ldc, int cStrideZ,
        int N, int K) {
    __shared__ float As[16][132];
    __shared__ float Bs[16][68];
    int z = blockIdx.z;
    const float* Bz = Bm + (size_t)z * bStrideZ;
    float* Cz = C + (size_t)z * cStrideZ;
    int m0 = blockIdx.y * 128, n0 = blockIdx.x * 64;
    int t = threadIdx.x;
    int tx = t & 15, ty = t >> 4;
    float acc[8][4];
#pragma unroll
    for (int i = 0; i < 8; i++)
#pragma unroll
        for (int j = 0; j < 4; j++) acc[i][j] = 0.f;

    float pa[8], pb[4];
#pragma unroll
    for (int i = 0; i < 8; i++) {
        int idx = t + i * 256;
        pa[i] = __ldg(&A[(size_t)(m0 + (idx >> 4)) * lda + (idx & 15)]);
    }
#pragma unroll
    for (int i = 0; i < 4; i++) {
        int idx = t + i * 256;
        pb[i] = __ldg(&Bz[(size_t)(idx >> 6) * N + n0 + (idx & 63)]);
    }
    for (int k0 = 0; k0 < K; k0 += 16) {
#pragma unroll
        for (int i = 0; i < 8; i++) {
            int idx = t + i * 256;
            As[idx & 15][idx >> 4] = pa[i];
        }
#pragma unroll
        for (int i = 0; i < 4; i++) {
            int idx = t + i * 256;
            Bs[idx >> 6][idx & 63] = pb[i];
        }
        __syncthreads();
        if (k0 + 16 < K) {
            int kn = k0 + 16;
#pragma unroll
            for (int i = 0; i < 8; i++) {
                int idx = t + i * 256;
                pa[i] = __ldg(&A[(size_t)(m0 + (idx >> 4)) * lda + kn + (idx & 15)]);
            }
#pragma unroll
            for (int i = 0; i < 4; i++) {
                int idx = t + i * 256;
                pb[i] = __ldg(&Bz[(size_t)(kn + (idx >> 6)) * N + n0 + (idx & 63)]);
            }
        }
#pragma unroll
        for (int kk = 0; kk < 16; kk++) {
            float a[8], bb[4];
            *(float4*)&a[0] = *(const float4*)&As[kk][ty * 8];
            *(float4*)&a[4] = *(const float4*)&As[kk][ty * 8 + 4];
            *(float4*)&bb[0] = *(const float4*)&Bs[kk][tx * 4];
#pragma unroll
            for (int i = 0; i < 8; i++)
#pragma unroll
                for (int j = 0; j < 4; j++) acc[i][j] += a[i] * bb[j];
        }
        __syncthreads();
    }
#pragma unroll
    for (int i = 0; i < 8; i++)
#pragma unroll
        for (int j = 0; j < 4; j++)
            Cz[(size_t)(m0 + ty * 8 + i) * ldc + n0 + tx * 4 + j] = acc[i][j];
}

// ---------------- init ----------------
__global__ void init_k(const float* __restrict__ goal0, const float* __restrict__ w0,
                       float* __restrict__ outGoals, float* __restrict__ outWs) {
    int idx = blockIdx.x * blockDim.x + threadIdx.x;
    if (idx < 2 * B * HW) {
        g_wh0[idx] = 0.f; g_wh1[idx] = 0.f;
        g_wh0h[idx] = __float2bfloat16(0.f); g_wh0l[idx] = __float2bfloat16(0.f);
        g_wh1h[idx] = __float2bfloat16(0.f); g_wh1l[idx] = __float2bfloat16(0.f);
    }
    if (idx < B * HW) { g_wc0[idx] = 0.f; g_wc1[idx] = 0.f; }
    if (idx < 2 * B * HG) {
        g_gh0[idx] = 0.f; g_gh1[idx] = 0.f;
        g_gh0h[idx] = __float2bfloat16(0.f); g_gh0l[idx] = __float2bfloat16(0.f);
        g_gh1h[idx] = __float2bfloat16(0.f); g_gh1l[idx] = __float2bfloat16(0.f);
    }
    if (idx < B * HG) { g_gc0[idx] = 0.f; g_gc1[idx] = 0.f; }
    if (idx < B * DOF) {
        int b = idx / DOF, d = idx - b * DOF;
        float v = goal0[idx];
        g_cat[b * CATD + d] = v;
        outGoals[(size_t)b * MS * DOF + d] = v;
    }
    if (idx < B * WSZ) {
        int b = idx / WSZ, d = idx - b * WSZ;
        float v = w0[idx];
        g_cat[b * CATD + DOF + d] = v;
        outWs[(size_t)b * MS * WSZ + d] = v;
    }
}

// ---------------- 64x64 TN GEMM tile (fp32), MODE 0: tanh+split, MODE 2: dual-dest ---
template<int MODE>
__device__ __forceinline__ void gemm64(
        const float* __restrict__ A, int lda, int K,
        const float* __restrict__ W,
        const float* __restrict__ b1,
        float* C, int ldc, float* C2, int ldc2,
        bf16* Chi, bf16* Clo,
        int N, int m0, int n0, float* sm) {
    float (*As)[68] = (float(*)[68])sm;
    float (*Ws)[68] = (float(*)[68])(sm + 16 * 68);
    int t = threadIdx.x;
    int tx = t & 15, ty = t >> 4;
    float acc[4][4];
#pragma unroll
    for (int i = 0; i < 4; i++)
#pragma unroll
        for (int j = 0; j < 4; j++) acc[i][j] = 0.f;

    const int nch = K >> 4;
    float pa[4], pw[4];
    auto lf = [&](int ch) {
        int k0 = ch << 4;
#pragma unroll
        for (int i = 0; i < 4; i++) {
            int idx = t + (i << 8);
            int r = idx >> 4, c = idx & 15;
            pa[i] = A[(size_t)(m0 + r) * lda + k0 + c];
            int rg = n0 + r;
            pw[i] = (MODE == 2 && rg >= N) ? 0.f : __ldg(W + (size_t)rg * K + k0 + c);
        }
    };
    lf(0);
    for (int ch = 0; ch < nch; ch++) {
#pragma unroll
        for (int i = 0; i < 4; i++) {
            int idx = t + (i << 8);
            As[idx & 15][idx >> 4] = pa[i];
            Ws[idx & 15][idx >> 4] = pw[i];
        }
        __syncthreads();
        if (ch + 1 < nch) lf(ch + 1);
#pragma unroll
        for (int kk = 0; kk < 16; kk++) {
            float a[4], w[4];
            *(float4*)&a[0] = *(const float4*)&As[kk][ty * 4];
            *(float4*)&w[0] = *(const float4*)&Ws[kk][tx * 4];
#pragma unroll
            for (int i = 0; i < 4; i++)
#pragma unroll
                for (int j = 0; j < 4; j++) acc[i][j] += a[i] * w[j];
        }
        __syncthreads();
    }

#pragma unroll
    for (int i = 0; i < 4; i++) {
        int m = m0 + ty * 4 + i;
#pragma unroll
        for (int j = 0; j < 4; j++) {
            int n = n0 + tx * 4 + j;
            if (MODE == 0) {
                float v = tanhf(acc[i][j] + __ldg(b1 + n));
                C[(size_t)m * ldc + n] = v;
                bf16 hi = __float2bfloat16(v);
                Chi[(size_t)m * ldc + n] = hi;
                Clo[(size_t)m * ldc + n] = __float2bfloat16(v - __bfloat162float(hi));
            } else if (n < N) {
                float v = acc[i][j] + __ldg(b1 + n);
                C[(size_t)m * ldc + n] = v;
                C2[(size_t)m * ldc2 + n] = v;
            }
        }
    }
}

// ---------------- phase kernels ----------------
__global__ __launch_bounds__(256) void bilinear_k(const float* __restrict__ bw_b,
                                                  const float* __restrict__ bg_b) {
    __shared__ float sc[CATD];
    int b = blockIdx.x, part = blockIdx.y;
    int t = threadIdx.x;
    for (int k = t; k < CATD; k += 256) sc[k] = g_cat[b * CATD + k];
    __syncthreads();
    if (part < 2) {
        int o = part * 256 + t;
        const float* a = g_Aw + (size_t)b * CATD * PW + o;
        float acc0 = __ldg(&bw_b[o]), acc1 = 0.f;
#pragma unroll 6
        for (int j = 0; j < CATD; j += 2) {
            acc0 += a[(size_t)j * PW] * sc[j];
            acc1 += a[(size_t)(j + 1) * PW] * sc[j + 1];
        }
        g_yw[b * PW + o] = acc0 + acc1;
    } else {
        int o = t;
        const float* a = g_Ag + (size_t)b * DOF * PG + o;
        float acc = __ldg(&bg_b[o]);
#pragma unroll
        for (int j = 0; j < DOF; j++) acc += a[j * PG] * sc[j];
        g_xg[b * PG + o] = acc;
    }
}

__global__ __launch_bounds__(256) void fc_k(const float* __restrict__ fcw_W,
                                            const float* __restrict__ fcw_b,
                                            const float* __restrict__ fcg_W,
                                            const float* __restrict__ fcg_b) {
    __shared__ float sm[2 * 16 * 68];
    int u = blockIdx.x;
    if (u < 16) {
        int n0 = (u & 3) * 64, m0 = (u >> 2) * 64;
        gemm64<0>(g_xg, PG, PG, fcg_W, fcg_b, g_x2, PG, nullptr, 0,
                  g_x2h, g_x2l, PG, m0, n0, sm);
    } else {
        int v = u - 16;
        int n0 = (v & 7) * 64, m0 = (v >> 3) * 64;
        gemm64<0>(g_yw, PW, PW, fcw_W, fcw_b, g_y2, PW, nullptr, 0,
                  g_y2h, g_y2l, PW, m0, n0, sm);
    }
}

__global__ __launch_bounds__(256) void heads_k(
        const float* __restrict__ gH, const float* __restrict__ og_W,
        const float* __restrict__ og_b, float* goalsOut,
        const float* __restrict__ wH, const float* __restrict__ ow_W,
        const float* __restrict__ ow_b, float* wsOut) {
    __shared__ float sm[2 * 16 * 68];
    int u = blockIdx.x;
    if (u < 4) {
        int m0 = u * 64;
        gemm64<2>(gH, HG, HG, og_W, og_b, goalsOut, MS * DOF, g_cat, CATD,
                  nullptr, nullptr, DOF, m0, 0, sm);
    } else {
        int v = u - 4;
        int n0 = (v % 5) * 64, m0 = (v / 5) * 64;
        gemm64<2>(wH, HW, HW, ow_W, ow_b, wsOut, MS * WSZ, g_cat + DOF, CATD,
                  nullptr, nullptr, WSZ, m0, n0, sm);
    }
}

// ---------------- host ----------------
extern "C" void kernel_launch(void* const* d_in, const int* in_sizes, int n_in,
                              void* d_out, int out_size) {
    const float* ctx    = (const float*)d_in[0];
    const float* goal0  = (const float*)d_in[1];
    const float* w0     = (const float*)d_in[2];
    const float* bg_W   = (const float*)d_in[3];
    const float* bg_b   = (const float*)d_in[4];
    const float* bw_W   = (const float*)d_in[5];
    const float* bw_b   = (const float*)d_in[6];
    const float* fcg_W  = (const float*)d_in[7];
    const float* fcg_b  = (const float*)d_in[8];
    const float* fcw_W  = (const float*)d_in[9];
    const float* fcw_b  = (const float*)d_in[10];
    const float* lg_Wih = (const float*)d_in[11];
    const float* lg_Whh = (const float*)d_in[12];
    const float* lg_bih = (const float*)d_in[13];
    const float* lg_bhh = (const float*)d_in[14];
    const float* lw_Wih = (const float*)d_in[15];
    const float* lw_Whh = (const float*)d_in[16];
    const float* lw_bih = (const float*)d_in[17];
    const float* lw_bhh = (const float*)d_in[18];
    const float* og_W   = (const float*)d_in[19];
    const float* og_b   = (const float*)d_in[20];
    const float* ow_W   = (const float*)d_in[21];
    const float* ow_b   = (const float*)d_in[22];

    float* out   = (float*)d_out;
    float* goals = out;
    float* ws    = out + (size_t)B * MS * DOF;

    float *Gt, *Ag, *gh0, *gh1, *gc0, *gc1, *wh0, *wh1, *wc0, *wc1;
    bf16 *gh0h, *gh0l, *gh1h, *gh1l, *wh0h, *wh0l, *wh1h, *wh1l;
    bf16 *x2h, *x2l, *y2h, *y2l;
    bf16 *WgL0h, *WgL0l, *WgL1h, *WgL1l, *WwL0h, *WwL0l, *WwL1h, *WwL1l;
    float *BgL0, *BgL1, *BwL0, *BwL1, *xg, *x2, *yw, *y2;
    cudaGetSymbolAddress((void**)&Gt, g_Gt);
    cudaGetSymbolAddress((void**)&Ag, g_Ag);
    cudaGetSymbolAddress((void**)&gh0, g_gh0);
    cudaGetSymbolAddress((void**)&gh1, g_gh1);
    cudaGetSymbolAddress((void**)&gc0, g_gc0);
    cudaGetSymbolAddress((void**)&gc1, g_gc1);
    cudaGetSymbolAddress((void**)&wh0, g_wh0);
    cudaGetSymbolAddress((void**)&wh1, g_wh1);
    cudaGetSymbolAddress((void**)&wc0, g_wc0);
    cudaGetSymbolAddress((void**)&wc1, g_wc1);
    cudaGetSymbolAddress((void**)&gh0h, g_gh0h);
    cudaGetSymbolAddress((void**)&gh0l, g_gh0l);
    cudaGetSymbolAddress((void**)&gh1h, g_gh1h);
    cudaGetSymbolAddress((void**)&gh1l, g_gh1l);
    cudaGetSymbolAddress((void**)&wh0h, g_wh0h);
    cudaGetSymbolAddress((void**)&wh0l, g_wh0l);
    cudaGetSymbolAddress((void**)&wh1h, g_wh1h);
    cudaGetSymbolAddress((void**)&wh1l, g_wh1l);
    cudaGetSymbolAddress((void**)&x2h, g_x2h);
    cudaGetSymbolAddress((void**)&x2l, g_x2l);
    cudaGetSymbolAddress((void**)&y2h, g_y2h);
    cudaGetSymbolAddress((void**)&y2l, g_y2l);
    cudaGetSymbolAddress((void**)&WgL0h, g_WgL0h);
    cudaGetSymbolAddress((void**)&WgL0l, g_WgL0l);
    cudaGetSymbolAddress((void**)&WgL1h, g_WgL1h);
    cudaGetSymbolAddress((void**)&WgL1l, g_WgL1l);
    cudaGetSymbolAddress((void**)&WwL0h, g_WwL0h);
    cudaGetSymbolAddress((void**)&WwL0l, g_WwL0l);
    cudaGetSymbolAddress((void**)&WwL1h, g_WwL1h);
    cudaGetSymbolAddress((void**)&WwL1l, g_WwL1l);
    cudaGetSymbolAddress((void**)&BgL0, g_BgL0);
    cudaGetSymbolAddress((void**)&BgL1, g_BgL1);
    cudaGetSymbolAddress((void**)&BwL0, g_BwL0);
    cudaGetSymbolAddress((void**)&BwL1, g_BwL1);
    cudaGetSymbolAddress((void**)&xg, g_xg);
    cudaGetSymbolAddress((void**)&x2, g_x2);
    cudaGetSymbolAddress((void**)&yw, g_yw);
    cudaGetSymbolAddress((void**)&y2, g_y2);

    // precompute path
    split_ctx<<<(B * CTXD) / 256, 256>>>(ctx);
    transpose_bw_split<<<dim3(CTXD / 32, PW, (CATD + 31) / 32), dim3(32, 32)>>>(bw_W);
    aw_mma_kernel<<<dim3(PW / 64, B / 128, CATD), 256>>>();

    dim3 tblk(32, 32);
    transpose_oij_jio<<<dim3(CTXD, PG / 32, 1), tblk>>>(bg_W, Gt, PG, CTXD, DOF);
    gemm_nn_batched<<<dim3(PG / 64, B / 128, DOF), 256>>>(
        ctx, CTXD, Gt, (size_t)CTXD * PG, Ag, DOF * PG, PG, PG, CTXD);

    // pack LSTM weights (gate-interleaved bf16 hi/lo + combined bias)
    pack_w<<<(4 * HG * (PG + HG)) / 256, 256>>>(lg_Wih, lg_Whh, lg_bih, lg_bhh,
                                                WgL0h, WgL0l, BgL0, HG, PG);
    pack_w<<<(4 * HG * (HG + HG)) / 256, 256>>>(lg_Wih + (size_t)4 * HG * PG,
                                                lg_Whh + (size_t)4 * HG * HG,
                                                lg_bih + 4 * HG, lg_bhh + 4 * HG,
                                                WgL1h, WgL1l, BgL1, HG, HG);
    pack_w<<<(4 * HW * (PW + HW)) / 256, 256>>>(lw_Wih, lw_Whh, lw_bih, lw_bhh,
                                                WwL0h, WwL0l, BwL0, HW, PW);
    pack_w<<<(4 * HW * (HW + HW)) / 256, 256>>>(lw_Wih + (size_t)4 * HW * PW,
                                                lw_Whh + (size_t)4 * HW * HW,
                                                lw_bih + 4 * HW, lw_bhh + 4 * HW,
                                                WwL1h, WwL1l, BwL1, HW, HW);

    init_k<<<(2 * B * HW) / 256, 256>>>(goal0, w0, goals, ws);

    const int BHG = B * HG, BHW = B * HW;
    for (int s = 0; s < NSTEPS; s++) {
        const int p = s & 1;
        const int q = p ^ 1;

        bilinear_k<<<dim3(B, 3), 256>>>(bw_b, bg_b);
        fc_k<<<48, 256>>>(fcw_W, fcw_b, fcg_W, fcg_b);

        // layer 0: act = fc outputs; hold = h0 prev
        gates_hmma<<<192, 128>>>(
            x2h, x2l, PG, gh0h + p * BHG, gh0l + p * BHG,
            WgL0h, WgL0l, BgL0, gc0, gh0 + q * BHG, gh0h + q * BHG, gh0l + q * BHG,
            y2h, y2l, PW, wh0h + p * BHW, wh0l + p * BHW,
            WwL0h, WwL0l, BwL0, wc0, wh0 + q * BHW, wh0h + q * BHW, wh0l + q * BHW);

        // layer 1: act = new h0; hold = h1 prev
        gates_hmma<<<192, 128>>>(
            gh0h + q * BHG, gh0l + q * BHG, HG, gh1h + p * BHG, gh1l + p * BHG,
            WgL1h, WgL1l, BgL1, gc1, gh1 + q * BHG, gh1h + q * BHG, gh1l + q * BHG,
            wh0h + q * BHW, wh0l + q * BHW, HW, wh1h + p * BHW, wh1l + p * BHW,
            WwL1h, WwL1l, BwL1, wc1, wh1 + q * BHW, wh1h + q * BHW, wh1l + q * BHW);

        heads_k<<<24, 256>>>(gh1 + q * BHG, og_W, og_b, goals + (size_t)(s + 1) * DOF,
                             wh1 + q * BHW, ow_W, ow_b, ws + (size_t)(s + 1) * WSZ);
    }
    (void)in_sizes; (void)n_in; (void)out_size;
}

// round 9
// speedup vs baseline: 3.3192x; 1.1775x over previous
#include <cuda_runtime.h>
#include <cuda_bf16.h>
#include <math.h>
#include <stdint.h>

#define B    256
#define CTXD 512
#define DOF  6
#define WSZ  300
#define WSZP 320
#define CATD 306
#define PG   256
#define PW   512
#define HG   256
#define HW   512
#define MS   20
#define NSTEPS 19

typedef __nv_bfloat16 bf16;

// ---------------- device scratch ----------------
__device__ bf16 g_Whi[(size_t)CATD * PW * CTXD];  // [j][o][i]
__device__ bf16 g_Wlo[(size_t)CATD * PW * CTXD];
__device__ bf16 g_ctx_hi[B * CTXD];
__device__ bf16 g_ctx_lo[B * CTXD];
__device__ float g_Gt[(size_t)DOF * CTXD * PG];
__device__ float g_Aw[(size_t)B * CATD * PW];
__device__ float g_Ag[(size_t)B * DOF * PG];
__device__ bf16  g_ywh[B * PW];
__device__ bf16  g_ywl[B * PW];
__device__ bf16  g_xgh[B * PG];
__device__ bf16  g_xgl[B * PG];
__device__ bf16  g_x2h[B * PG];
__device__ bf16  g_x2l[B * PG];
__device__ bf16  g_y2h[B * PW];
__device__ bf16  g_y2l[B * PW];
__device__ float g_cat[B * CATD];
__device__ float g_gh1[2 * B * HG];
__device__ bf16  g_gh0h[2 * B * HG];
__device__ bf16  g_gh0l[2 * B * HG];
__device__ bf16  g_gh1h[2 * B * HG];
__device__ bf16  g_gh1l[2 * B * HG];
__device__ float g_gh0f[B * HG];     // unused f32 sink for L0 h
__device__ float g_gc0[B * HG];
__device__ float g_gc1[B * HG];
__device__ float g_wh0f[B * HW];
__device__ float g_wh1[2 * B * HW];
__device__ bf16  g_wh0h[2 * B * HW];
__device__ bf16  g_wh0l[2 * B * HW];
__device__ bf16  g_wh1h[2 * B * HW];
__device__ bf16  g_wh1l[2 * B * HW];
__device__ float g_wc0[B * HW];
__device__ float g_wc1[B * HW];
// packed gate-interleaved LSTM weights
__device__ bf16  g_WgL0h[4 * HG * (PG + HG)];
__device__ bf16  g_WgL0l[4 * HG * (PG + HG)];
__device__ bf16  g_WgL1h[4 * HG * (HG + HG)];
__device__ bf16  g_WgL1l[4 * HG * (HG + HG)];
__device__ bf16  g_WwL0h[(size_t)4 * HW * (PW + HW)];
__device__ bf16  g_WwL0l[(size_t)4 * HW * (PW + HW)];
__device__ bf16  g_WwL1h[(size_t)4 * HW * (HW + HW)];
__device__ bf16  g_WwL1l[(size_t)4 * HW * (HW + HW)];
__device__ float g_BgL0[4 * HG];
__device__ float g_BgL1[4 * HG];
__device__ float g_BwL0[4 * HW];
__device__ float g_BwL1[4 * HW];
// packed plain weights (fc, ow)
__device__ bf16  g_FwH[PW * PW];
__device__ bf16  g_FwL[PW * PW];
__device__ bf16  g_FgH[PG * PG];
__device__ bf16  g_FgL[PG * PG];
__device__ bf16  g_OwH[WSZP * HW];
__device__ bf16  g_OwL[WSZP * HW];

__device__ __forceinline__ float sigf(float x) { return 1.f / (1.f + expf(-x)); }

__device__ __forceinline__ uint32_t smem_u32(const void* p) {
    uint32_t a;
    asm("{ .reg .u64 tmp; cvta.to.shared.u64 tmp, %1; cvt.u32.u64 %0, tmp; }" : "=r"(a) : "l"(p));
    return a;
}

#define LDM4(r0, r1, r2, r3, addr) \
    asm volatile("ldmatrix.sync.aligned.m8n8.x4.shared.b16 {%0,%1,%2,%3}, [%4];" \
                 : "=r"(r0), "=r"(r1), "=r"(r2), "=r"(r3) : "r"(addr))
#define MMA_BF16(acc, af, bf0, bf1) \
    asm volatile("mma.sync.aligned.m16n8k16.row.col.f32.bf16.bf16.f32 " \
                 "{%0,%1,%2,%3}, {%4,%5,%6,%7}, {%8,%9}, {%0,%1,%2,%3};" \
                 : "+f"((acc)[0]), "+f"((acc)[1]), "+f"((acc)[2]), "+f"((acc)[3]) \
                 : "r"((af)[0]), "r"((af)[1]), "r"((af)[2]), "r"((af)[3]), \
                   "r"(bf0), "r"(bf1))

// ---------------- split ctx into bf16 hi/lo ----------------
__global__ void split_ctx(const float* __restrict__ ctx) {
    int i = blockIdx.x * 256 + threadIdx.x;
    float x = ctx[i];
    bf16 hi = __float2bfloat16(x);
    g_ctx_hi[i] = hi;
    g_ctx_lo[i] = __float2bfloat16(x - __bfloat162float(hi));
}

// ---------------- transpose bw_W (o,i,j) -> hi/lo [j][o][i] ----------------
__global__ void transpose_bw_split(const float* __restrict__ in) {
    __shared__ float tile[32][33];
    int i0 = blockIdx.x * 32;
    int o  = blockIdx.y;
    int j0 = blockIdx.z * 32;
    int tx = threadIdx.x, ty = threadIdx.y;
    int j = j0 + tx;
    if (j < CATD)
        tile[ty][tx] = in[(size_t)o * CTXD * CATD + (size_t)(i0 + ty) * CATD + j];
    __syncthreads();
    int jw = j0 + ty;
    if (jw < CATD) {
        float v = tile[tx][ty];
        bf16 hi = __float2bfloat16(v);
        bf16 lo = __float2bfloat16(v - __bfloat162float(hi));
        size_t base = ((size_t)jw * PW + o) * CTXD + i0 + tx;
        g_Whi[base] = hi;
        g_Wlo[base] = lo;
    }
}

// ---------------- pack LSTM weights (gate-interleaved) ----------------
__global__ void pack_w(const float* __restrict__ Wih, const float* __restrict__ Whh,
                       const float* __restrict__ bih, const float* __restrict__ bhh,
                       bf16* __restrict__ outH, bf16* __restrict__ outL,
                       float* __restrict__ outB, int H, int Kin) {
    int Kcat = Kin + H;
    size_t idx = (size_t)blockIdx.x * 256 + threadIdx.x;
    int r = (int)(idx / Kcat), k = (int)(idx % Kcat);
    int u = r >> 2, gate = r & 3, src = gate * H + u;
    float v = (k < Kin) ? Wih[(size_t)src * Kin + k] : Whh[(size_t)src * H + (k - Kin)];
    bf16 hi = __float2bfloat16(v);
    outH[idx] = hi;
    outL[idx] = __float2bfloat16(v - __bfloat162float(hi));
    if (k == 0) outB[r] = bih[src] + bhh[src];
}

// ---------------- pack plain weights (zero-padded rows) ----------------
__global__ void pack_plain(const float* __restrict__ W, bf16* __restrict__ outH,
                           bf16* __restrict__ outL, int N, int K) {
    size_t idx = (size_t)blockIdx.x * 256 + threadIdx.x;
    int r = (int)(idx / K), k = (int)(idx % K);
    float v = (r < N) ? W[(size_t)r * K + k] : 0.f;
    bf16 hi = __float2bfloat16(v);
    outH[idx] = hi;
    outL[idx] = __float2bfloat16(v - __bfloat162float(hi));
}

// ---------------- aw precompute: merged-pass HMMA (128x64 tile, 256 thr) ----------
__global__ __launch_bounds__(256) void aw_mma_kernel() {
    extern __shared__ bf16 smd[];
    bf16* sAh = smd;
    bf16* sAl = smd + 128 * 72;
    bf16* sBh = smd + 2 * 128 * 72;
    bf16* sBl = smd + 2 * 128 * 72 + 64 * 72;
    int t = threadIdx.x;
    int lane = t & 31, wid = t >> 5;
    int warp_m = wid & 3, warp_n = wid >> 2;
    int n0 = blockIdx.x * 64;
    int m0 = blockIdx.y * 128;
    int j  = blockIdx.z;

    float acc[2][4][4];
#pragma unroll
    for (int a = 0; a < 2; a++)
#pragma unroll
        for (int b = 0; b < 4; b++)
#pragma unroll
            for (int c = 0; c < 4; c++) acc[a][b][c] = 0.f;

    const bf16* Bhi = g_Whi + (size_t)j * PW * CTXD;
    const bf16* Blo = g_Wlo + (size_t)j * PW * CTXD;

    int a_mloc = lane & 15;
    int a_koff = (lane >> 4) * 8;
    int b_nfsel = lane >> 4;
    int b_khalf = (lane >> 3) & 1;
    int b_nloc = lane & 7;

    for (int k0 = 0; k0 < CTXD; k0 += 64) {
#pragma unroll
        for (int i = 0; i < 4; i++) {
            int idx = t + i * 256;
            int r = idx >> 3, sg = idx & 7;
            *(uint4*)&sAh[r * 72 + sg * 8] = *(const uint4*)(g_ctx_hi + (size_t)(m0 + r) * CTXD + k0 + sg * 8);
            *(uint4*)&sAl[r * 72 + sg * 8] = *(const uint4*)(g_ctx_lo + (size_t)(m0 + r) * CTXD + k0 + sg * 8);
        }
#pragma unroll
        for (int i = 0; i < 2; i++) {
            int idx = t + i * 256;
            int r = idx >> 3, sg = idx & 7;
            *(uint4*)&sBh[r * 72 + sg * 8] = *(const uint4*)(Bhi + (size_t)(n0 + r) * CTXD + k0 + sg * 8);
            *(uint4*)&sBl[r * 72 + sg * 8] = *(const uint4*)(Blo + (size_t)(n0 + r) * CTXD + k0 + sg * 8);
        }
        __syncthreads();
#pragma unroll
        for (int kk = 0; kk < 4; kk++) {
            int kb = kk * 16;
            uint32_t ah[2][4], al[2][4], bh[4][2], bl[4][2];
#pragma unroll
            for (int mf = 0; mf < 2; mf++) {
                uint32_t addr = smem_u32(&sAh[(warp_m * 32 + mf * 16 + a_mloc) * 72 + kb + a_koff]);
                LDM4(ah[mf][0], ah[mf][1], ah[mf][2], ah[mf][3], addr);
                addr = smem_u32(&sAl[(warp_m * 32 + mf * 16 + a_mloc) * 72 + kb + a_koff]);
                LDM4(al[mf][0], al[mf][1], al[mf][2], al[mf][3], addr);
            }
#pragma unroll
            for (int bp = 0; bp < 2; bp++) {
                uint32_t addr = smem_u32(&sBh[(warp_n * 32 + bp * 16 + b_nfsel * 8 + b_nloc) * 72 + kb + b_khalf * 8]);
                LDM4(bh[bp * 2][0], bh[bp * 2][1], bh[bp * 2 + 1][0], bh[bp * 2 + 1][1], addr);
                addr = smem_u32(&sBl[(warp_n * 32 + bp * 16 + b_nfsel * 8 + b_nloc) * 72 + kb + b_khalf * 8]);
                LDM4(bl[bp * 2][0], bl[bp * 2][1], bl[bp * 2 + 1][0], bl[bp * 2 + 1][1], addr);
            }
#pragma unroll
            for (int mf = 0; mf < 2; mf++)
#pragma unroll
                for (int nf = 0; nf < 4; nf++) {
                    MMA_BF16(acc[mf][nf], ah[mf], bh[nf][0], bh[nf][1]);
                    MMA_BF16(acc[mf][nf], ah[mf], bl[nf][0], bl[nf][1]);
                    MMA_BF16(acc[mf][nf], al[mf], bh[nf][0], bh[nf][1]);
                }
        }
        __syncthreads();
    }

    int g = lane >> 2, tg = lane & 3;
#pragma unroll
    for (int mf = 0; mf < 2; mf++) {
        int row0 = m0 + warp_m * 32 + mf * 16 + g;
#pragma unroll
        for (int nf = 0; nf < 4; nf++) {
            int col = n0 + warp_n * 32 + nf * 8 + tg * 2;
            float* d0 = g_Aw + ((size_t)row0 * CATD + j) * PW + col;
            float* d1 = g_Aw + ((size_t)(row0 + 8) * CATD + j) * PW + col;
            d0[0] = acc[mf][nf][0]; d0[1] = acc[mf][nf][1];
            d1[0] = acc[mf][nf][2]; d1[1] = acc[mf][nf][3];
        }
    }
}

// ---------------- gates HMMA: 64x32 tile, 128 thr, fused LSTM pointwise ----------
__device__ __forceinline__ void gates_tile32(
        const bf16* __restrict__ ActH, const bf16* __restrict__ ActL, int Kin,
        const bf16* __restrict__ HoldH, const bf16* __restrict__ HoldL,
        const bf16* __restrict__ WH, const bf16* __restrict__ WL,
        const float* __restrict__ biasCat,
        float* C, float* Hf, bf16* Hh, bf16* Hl,
        int H, int m0, int n0c, bf16* sm) {
    bf16* sAh = sm;
    bf16* sAl = sm + 64 * 72;
    bf16* sWh = sm + 2 * 64 * 72;
    bf16* sWl = sm + 2 * 64 * 72 + 32 * 72;
    int t = threadIdx.x, lane = t & 31, wid = t >> 5;
    int warp_m = wid & 1, warp_n = wid >> 1;
    int a_mloc = lane & 15;
    int a_koff = (lane >> 4) * 8;
    int b_nfsel = lane >> 4, b_khalf = (lane >> 3) & 1, b_nloc = lane & 7;

    float acc[2][2][4];
#pragma unroll
    for (int a = 0; a < 2; a++)
#pragma unroll
        for (int b = 0; b < 2; b++)
#pragma unroll
            for (int c = 0; c < 4; c++) acc[a][b][c] = 0.f;

    int Kcat = Kin + H;
    int nch = Kcat >> 6;
    for (int ch = 0; ch < nch; ch++) {
        int k0 = ch << 6;
        const bf16 *srcH, *srcL; int ld, off;
        if (k0 < Kin) { srcH = ActH; srcL = ActL; ld = Kin; off = k0; }
        else          { srcH = HoldH; srcL = HoldL; ld = H; off = k0 - Kin; }
#pragma unroll
        for (int i = 0; i < 4; i++) {
            int idx = t + i * 128;
            int r = idx >> 3, sg = idx & 7;
            *(uint4*)&sAh[r * 72 + sg * 8] = *(const uint4*)(srcH + (size_t)(m0 + r) * ld + off + sg * 8);
            *(uint4*)&sAl[r * 72 + sg * 8] = *(const uint4*)(srcL + (size_t)(m0 + r) * ld + off + sg * 8);
        }
#pragma unroll
        for (int i = 0; i < 2; i++) {
            int idx = t + i * 128;
            int r = idx >> 3, sg = idx & 7;
            *(uint4*)&sWh[r * 72 + sg * 8] = *(const uint4*)(WH + (size_t)(n0c + r) * Kcat + k0 + sg * 8);
            *(uint4*)&sWl[r * 72 + sg * 8] = *(const uint4*)(WL + (size_t)(n0c + r) * Kcat + k0 + sg * 8);
        }
        __syncthreads();
#pragma unroll
        for (int kk = 0; kk < 4; kk++) {
            int kb = kk * 16;
            uint32_t ah[2][4], al[2][4], wh[2][2], wl[2][2];
#pragma unroll
            for (int mf = 0; mf < 2; mf++) {
                uint32_t addr = smem_u32(&sAh[(warp_m * 32 + mf * 16 + a_mloc) * 72 + kb + a_koff]);
                LDM4(ah[mf][0], ah[mf][1], ah[mf][2], ah[mf][3], addr);
                addr = smem_u32(&sAl[(warp_m * 32 + mf * 16 + a_mloc) * 72 + kb + a_koff]);
                LDM4(al[mf][0], al[mf][1], al[mf][2], al[mf][3], addr);
            }
            {
                uint32_t addr = smem_u32(&sWh[(warp_n * 16 + b_nfsel * 8 + b_nloc) * 72 + kb + b_khalf * 8]);
                LDM4(wh[0][0], wh[0][1], wh[1][0], wh[1][1], addr);
                addr = smem_u32(&sWl[(warp_n * 16 + b_nfsel * 8 + b_nloc) * 72 + kb + b_khalf * 8]);
                LDM4(wl[0][0], wl[0][1], wl[1][0], wl[1][1], addr);
            }
#pragma unroll
            for (int mf = 0; mf < 2; mf++)
#pragma unroll
                for (int nf = 0; nf < 2; nf++) {
                    MMA_BF16(acc[mf][nf], ah[mf], wh[nf][0], wh[nf][1]);
                    MMA_BF16(acc[mf][nf], ah[mf], wl[nf][0], wl[nf][1]);
                    MMA_BF16(acc[mf][nf], al[mf], wh[nf][0], wh[nf][1]);
                }
        }
        __syncthreads();
    }

    int g = lane >> 2, tg = lane & 3;
#pragma unroll
    for (int mf = 0; mf < 2; mf++) {
        int row = m0 + warp_m * 32 + mf * 16 + g;
#pragma unroll
        for (int nf = 0; nf < 2; nf++) {
            float* a = acc[mf][nf];
            float s0 = (tg & 1) ? a[0] : a[2];
            float r0 = __shfl_xor_sync(0xffffffffu, s0, 1);
            float s1 = (tg & 1) ? a[1] : a[3];
            float r1 = __shfl_xor_sync(0xffffffffu, s1, 1);
            int base = n0c + warp_n * 16 + nf * 8;
            int u_ = (base >> 2) + (tg >> 1);
            int rowi = (tg & 1) ? row + 8 : row;
            float iv, fv, gv, ov;
            if (tg & 1) { iv = r0; fv = r1; gv = a[2]; ov = a[3]; }
            else        { iv = a[0]; fv = a[1]; gv = r0; ov = r1; }
            float4 bb = *(const float4*)(biasCat + u_ * 4);
            float i_ = sigf(iv + bb.x), f_ = sigf(fv + bb.y);
            float g_ = tanhf(gv + bb.z), o_ = sigf(ov + bb.w);
            int li = rowi * H + u_;
            float cn = f_ * C[li] + i_ * g_;
            C[li] = cn;
            float h = o_ * tanhf(cn);
            if (Hf) Hf[li] = h;
            bf16 hh = __float2bfloat16(h);
            Hh[li] = hh;
            Hl[li] = __float2bfloat16(h - __bfloat162float(hh));
        }
    }
}

__global__ __launch_bounds__(128) void gates_hmma(
        const bf16* gActH, const bf16* gActL, int gKin,
        const bf16* gHoldH, const bf16* gHoldL,
        const bf16* gWH, const bf16* gWL, const float* gB,
        float* gC, float* gHf, bf16* gHh, bf16* gHl,
        const bf16* wActH, const bf16* wActL, int wKin,
        const bf16* wHoldH, const bf16* wHoldL,
        const bf16* wWH, const bf16* wWL, const float* wB,
        float* wC, float* wHf, bf16* wHh, bf16* wHl) {
    __shared__ bf16 sm[2 * 64 * 72 + 2 * 32 * 72];
    int u = blockIdx.x;
    if (u < 128) {
        int mt = u >> 5, nt = u & 31;
        gates_tile32(gActH, gActL, gKin, gHoldH, gHoldL, gWH, gWL, gB,
                     gC, gHf, gHh, gHl, HG, mt * 64, nt * 32, sm);
    } else {
        int v = u - 128;
        int mt = v >> 6, nt = v & 63;
        gates_tile32(wActH, wActL, wKin, wHoldH, wHoldL, wWH, wWL, wB,
                     wC, wHf, wHh, wHl, HW, mt * 64, nt * 32, sm);
    }
}

// ---------------- fc HMMA tile: 64x64, 128 thr, tanh + split epilogue -------------
__device__ __forceinline__ void fc_tile(
        const bf16* __restrict__ ActH, const bf16* __restrict__ ActL, int K,
        const bf16* __restrict__ WH, const bf16* __restrict__ WL,
        const float* __restrict__ bias,
        bf16* Hh, bf16* Hl, int ldc, int m0, int n0, bf16* sm) {
    bf16* sAh = sm;
    bf16* sAl = sm + 64 * 72;
    bf16* sWh = sm + 2 * 64 * 72;
    bf16* sWl = sm + 3 * 64 * 72;
    int t = threadIdx.x, lane = t & 31, wid = t >> 5;
    int warp_m = wid & 1, warp_n = wid >> 1;
    int a_mloc = lane & 15;
    int a_koff = (lane >> 4) * 8;
    int b_nfsel = lane >> 4, b_khalf = (lane >> 3) & 1, b_nloc = lane & 7;

    float acc[2][4][4];
#pragma unroll
    for (int a = 0; a < 2; a++)
#pragma unroll
        for (int b = 0; b < 4; b++)
#pragma unroll
            for (int c = 0; c < 4; c++) acc[a][b][c] = 0.f;

    int nch = K >> 6;
    for (int ch = 0; ch < nch; ch++) {
        int k0 = ch << 6;
#pragma unroll
        for (int i = 0; i < 4; i++) {
            int idx = t + i * 128;
            int r = idx >> 3, sg = idx & 7;
            *(uint4*)&sAh[r * 72 + sg * 8] = *(const uint4*)(ActH + (size_t)(m0 + r) * K + k0 + sg * 8);
            *(uint4*)&sAl[r * 72 + sg * 8] = *(const uint4*)(ActL + (size_t)(m0 + r) * K + k0 + sg * 8);
            *(uint4*)&sWh[r * 72 + sg * 8] = *(const uint4*)(WH + (size_t)(n0 + r) * K + k0 + sg * 8);
            *(uint4*)&sWl[r * 72 + sg * 8] = *(const uint4*)(WL + (size_t)(n0 + r) * K + k0 + sg * 8);
        }
        __syncthreads();
#pragma unroll
        for (int kk = 0; kk < 4; kk++) {
            int kb = kk * 16;
            uint32_t ah[2][4], al[2][4], wh[4][2], wl[4][2];
#pragma unroll
            for (int mf = 0; mf < 2; mf++) {
                uint32_t addr = smem_u32(&sAh[(warp_m * 32 + mf * 16 + a_mloc) * 72 + kb + a_koff]);
                LDM4(ah[mf][0], ah[mf][1], ah[mf][2], ah[mf][3], addr);
                addr = smem_u32(&sAl[(warp_m * 32 + mf * 16 + a_mloc) * 72 + kb + a_koff]);
                LDM4(al[mf][0], al[mf][1], al[mf][2], al[mf][3], addr);
            }
#pragma unroll
            for (int bp = 0; bp < 2; bp++) {
                uint32_t addr = smem_u32(&sWh[(warp_n * 32 + bp * 16 + b_nfsel * 8 + b_nloc) * 72 + kb + b_khalf * 8]);
                LDM4(wh[bp * 2][0], wh[bp * 2][1], wh[bp * 2 + 1][0], wh[bp * 2 + 1][1], addr);
                addr = smem_u32(&sWl[(warp_n * 32 + bp * 16 + b_nfsel * 8 + b_nloc) * 72 + kb + b_khalf * 8]);
                LDM4(wl[bp * 2][0], wl[bp * 2][1], wl[bp * 2 + 1][0], wl[bp * 2 + 1][1], addr);
            }
#pragma unroll
            for (int mf = 0; mf < 2; mf++)
#pragma unroll
                for (int nf = 0; nf < 4; nf++) {
                    MMA_BF16(acc[mf][nf], ah[mf], wh[nf][0], wh[nf][1]);
                    MMA_BF16(acc[mf][nf], ah[mf], wl[nf][0], wl[nf][1]);
                    MMA_BF16(acc[mf][nf], al[mf], wh[nf][0], wh[nf][1]);
                }
        }
        __syncthreads();
    }

    int g = lane >> 2, tg = lane & 3;
#pragma unroll
    for (int mf = 0; mf < 2; mf++) {
        int row0 = m0 + warp_m * 32 + mf * 16 + g;
#pragma unroll
        for (int nf = 0; nf < 4; nf++) {
            int col = n0 + warp_n * 32 + nf * 8 + tg * 2;
            float b0 = __ldg(bias + col), b1 = __ldg(bias + col + 1);
            float v00 = tanhf(acc[mf][nf][0] + b0);
            float v01 = tanhf(acc[mf][nf][1] + b1);
            float v10 = tanhf(acc[mf][nf][2] + b0);
            float v11 = tanhf(acc[mf][nf][3] + b1);
            size_t o0 = (size_t)row0 * ldc + col;
            size_t o1 = (size_t)(row0 + 8) * ldc + col;
            bf16 h;
            h = __float2bfloat16(v00); Hh[o0] = h; Hl[o0] = __float2bfloat16(v00 - __bfloat162float(h));
            h = __float2bfloat16(v01); Hh[o0 + 1] = h; Hl[o0 + 1] = __float2bfloat16(v01 - __bfloat162float(h));
            h = __float2bfloat16(v10); Hh[o1] = h; Hl[o1] = __float2bfloat16(v10 - __bfloat162float(h));
            h = __float2bfloat16(v11); Hh[o1 + 1] = h; Hl[o1 + 1] = __float2bfloat16(v11 - __bfloat162float(h));
        }
    }
}

__global__ __launch_bounds__(128) void fc_hmma(const float* __restrict__ fcw_b,
                                               const float* __restrict__ fcg_b) {
    __shared__ bf16 sm[4 * 64 * 72];
    int u = blockIdx.x;
    if (u < 16) {
        int m0 = (u >> 2) * 64, n0 = (u & 3) * 64;
        fc_tile(g_xgh, g_xgl, PG, g_FgH, g_FgL, fcg_b, g_x2h, g_x2l, PG, m0, n0, sm);
    } else {
        int v = u - 16;
        int m0 = (v >> 3) * 64, n0 = (v & 7) * 64;
        fc_tile(g_ywh, g_ywl, PW, g_FwH, g_FwL, fcw_b, g_y2h, g_y2l, PW, m0, n0, sm);
    }
}

// ---------------- heads: HMMA w-part (64x64 guard) + dot g-part ----------------
__global__ __launch_bounds__(128) void heads_k(
        const float* __restrict__ gH, const float* __restrict__ og_W,
        const float* __restrict__ og_b, float* goalsOut,
        const bf16* __restrict__ wHh, const bf16* __restrict__ wHl,
        const float* __restrict__ ow_b, float* wsOut) {
    __shared__ bf16 sm[4 * 64 * 72];
    int u = blockIdx.x;
    if (u < 20) {
        int m0 = (u / 5) * 64, n0 = (u % 5) * 64;
        // HMMA tile, guard col < WSZ, dual f32 dest (ws + cat)
        bf16* sAh = sm;
        bf16* sAl = sm + 64 * 72;
        bf16* sWh = sm + 2 * 64 * 72;
        bf16* sWl = sm + 3 * 64 * 72;
        int t = threadIdx.x, lane = t & 31, wid = t >> 5;
        int warp_m = wid & 1, warp_n = wid >> 1;
        int a_mloc = lane & 15;
        int a_koff = (lane >> 4) * 8;
        int b_nfsel = lane >> 4, b_khalf = (lane >> 3) & 1, b_nloc = lane & 7;
        float acc[2][4][4];
#pragma unroll
        for (int a = 0; a < 2; a++)
#pragma unroll
            for (int b = 0; b < 4; b++)
#pragma unroll
                for (int c = 0; c < 4; c++) acc[a][b][c] = 0.f;
        for (int ch = 0; ch < HW / 64; ch++) {
            int k0 = ch << 6;
#pragma unroll
            for (int i = 0; i < 4; i++) {
                int idx = t + i * 128;
                int r = idx >> 3, sg = idx & 7;
                *(uint4*)&sAh[r * 72 + sg * 8] = *(const uint4*)(wHh + (size_t)(m0 + r) * HW + k0 + sg * 8);
                *(uint4*)&sAl[r * 72 + sg * 8] = *(const uint4*)(wHl + (size_t)(m0 + r) * HW + k0 + sg * 8);
                *(uint4*)&sWh[r * 72 + sg * 8] = *(const uint4*)(g_OwH + (size_t)(n0 + r) * HW + k0 + sg * 8);
                *(uint4*)&sWl[r * 72 + sg * 8] = *(const uint4*)(g_OwL + (size_t)(n0 + r) * HW + k0 + sg * 8);
            }
            __syncthreads();
#pragma unroll
            for (int kk = 0; kk < 4; kk++) {
                int kb = kk * 16;
                uint32_t ah[2][4], al[2][4], wh[4][2], wl[4][2];
#pragma unroll
                for (int mf = 0; mf < 2; mf++) {
                    uint32_t addr = smem_u32(&sAh[(warp_m * 32 + mf * 16 + a_mloc) * 72 + kb + a_koff]);
                    LDM4(ah[mf][0], ah[mf][1], ah[mf][2], ah[mf][3], addr);
                    addr = smem_u32(&sAl[(warp_m * 32 + mf * 16 + a_mloc) * 72 + kb + a_koff]);
                    LDM4(al[mf][0], al[mf][1], al[mf][2], al[mf][3], addr);
                }
#pragma unroll
                for (int bp = 0; bp < 2; bp++) {
                    uint32_t addr = smem_u32(&sWh[(warp_n * 32 + bp * 16 + b_nfsel * 8 + b_nloc) * 72 + kb + b_khalf * 8]);
                    LDM4(wh[bp * 2][0], wh[bp * 2][1], wh[bp * 2 + 1][0], wh[bp * 2 + 1][1], addr);
                    addr = smem_u32(&sWl[(warp_n * 32 + bp * 16 + b_nfsel * 8 + b_nloc) * 72 + kb + b_khalf * 8]);
                    LDM4(wl[bp * 2][0], wl[bp * 2][1], wl[bp * 2 + 1][0], wl[bp * 2 + 1][1], addr);
                }
#pragma unroll
                for (int mf = 0; mf < 2; mf++)
#pragma unroll
                    for (int nf = 0; nf < 4; nf++) {
                        MMA_BF16(acc[mf][nf], ah[mf], wh[nf][0], wh[nf][1]);
                        MMA_BF16(acc[mf][nf], ah[mf], wl[nf][0], wl[nf][1]);
                        MMA_BF16(acc[mf][nf], al[mf], wh[nf][0], wh[nf][1]);
                    }
            }
            __syncthreads();
        }
        int g = lane >> 2, tg = lane & 3;
#pragma unroll
        for (int mf = 0; mf < 2; mf++) {
            int row0 = m0 + warp_m * 32 + mf * 16 + g;
#pragma unroll
            for (int nf = 0; nf < 4; nf++) {
                int col = n0 + warp_n * 32 + nf * 8 + tg * 2;
                if (col < WSZ) {
                    float b0 = __ldg(ow_b + col), b1 = __ldg(ow_b + col + 1);
                    float v00 = acc[mf][nf][0] + b0, v01 = acc[mf][nf][1] + b1;
                    float v10 = acc[mf][nf][2] + b0, v11 = acc[mf][nf][3] + b1;
                    int r1 = row0 + 8;
                    wsOut[(size_t)row0 * (MS * WSZ) + col] = v00;
                    wsOut[(size_t)row0 * (MS * WSZ) + col + 1] = v01;
                    wsOut[(size_t)r1 * (MS * WSZ) + col] = v10;
                    wsOut[(size_t)r1 * (MS * WSZ) + col + 1] = v11;
                    g_cat[row0 * CATD + DOF + col] = v00;
                    g_cat[row0 * CATD + DOF + col + 1] = v01;
                    g_cat[r1 * CATD + DOF + col] = v10;
                    g_cat[r1 * CATD + DOF + col + 1] = v11;
                }
            }
        }
    } else {
        int gi = (u - 20) * 128 + threadIdx.x;      // 0..1535
        int m = gi / DOF, d = gi - m * DOF;
        const float* a = gH + m * HG;
        const float* w = og_W + d * HG;
        float s = __ldg(og_b + d);
#pragma unroll 8
        for (int k = 0; k < HG; k++) s += a[k] * __ldg(w + k);
        goalsOut[(size_t)m * (MS * DOF) + d] = s;
        g_cat[m * CATD + d] = s;
    }
}

// ---------------- transpose (o,i,j) -> (j,i,o) for bg_W ----------------
__global__ void transpose_oij_jio(const float* __restrict__ in, float* __restrict__ out,
                                  int O, int I, int J) {
    __shared__ float tile[32][33];
    int i  = blockIdx.x;
    int o0 = blockIdx.y * 32;
    int j0 = blockIdx.z * 32;
    int tx = threadIdx.x, ty = threadIdx.y;
    int o = o0 + ty, j = j0 + tx;
    if (o < O && j < J)
        tile[ty][tx] = in[(size_t)o * I * J + (size_t)i * J + j];
    __syncthreads();
    int jo = j0 + ty, oo = o0 + tx;
    if (jo < J && oo < O)
        out[(size_t)jo * I * O + (size_t)i * O + oo] = tile[tx][ty];
}

// ---------------- fp32 SIMT GEMM for Ag (tiny) ----------------
__global__ __launch_bounds__(256, 2) void gemm_nn_batched(
        const float* __restrict__ A, int lda,
        const float* __restrict__ Bm, size_t bStrideZ,
        float* __restrict__ C, int ldc, int cStrideZ,
        int N, int K) {
    __shared__ float As[16][132];
    __shared__ float Bs[16][68];
    int z = blockIdx.z;
    const float* Bz = Bm + (size_t)z * bStrideZ;
    float* Cz = C + (size_t)z * cStrideZ;
    int m0 = blockIdx.y * 128, n0 = blockIdx.x * 64;
    int t = threadIdx.x;
    int tx = t & 15, ty = t >> 4;
    float acc[8][4];
#pragma unroll
    for (int i = 0; i < 8; i++)
#pragma unroll
        for (int j = 0; j < 4; j++) acc[i][j] = 0.f;

    float pa[8], pb[4];
#pragma unroll
    for (int i = 0; i < 8; i++) {
        int idx = t + i * 256;
        pa[i] = __ldg(&A[(size_t)(m0 + (idx >> 4)) * lda + (idx & 15)]);
    }
#pragma unroll
    for (int i = 0; i < 4; i++) {
        int idx = t + i * 256;
        pb[i] = __ldg(&Bz[(size_t)(idx >> 6) * N + n0 + (idx & 63)]);
    }
    for (int k0 = 0; k0 < K; k0 += 16) {
#pragma unroll
        for (int i = 0; i < 8; i++) {
            int idx = t + i * 256;
            As[idx & 15][idx >> 4] = pa[i];
        }
#pragma unroll
        for (int i = 0; i < 4; i++) {
            int idx = t + i * 256;
            Bs[idx >> 6][idx & 63] = pb[i];
        }
        __syncthreads();
        if (k0 + 16 < K) {
            int kn = k0 + 16;
#pragma unroll
            for (int i = 0; i < 8; i++) {
                int idx = t + i * 256;
                pa[i] = __ldg(&A[(size_t)(m0 + (idx >> 4)) * lda + kn + (idx & 15)]);
            }
#pragma unroll
            for (int i = 0; i < 4; i++) {
                int idx = t + i * 256;
                pb[i] = __ldg(&Bz[(size_t)(kn + (idx >> 6)) * N + n0 + (idx & 63)]);
            }
        }
#pragma unroll
        for (int kk = 0; kk < 16; kk++) {
            float a[8], bb[4];
            *(float4*)&a[0] = *(const float4*)&As[kk][ty * 8];
            *(float4*)&a[4] = *(const float4*)&As[kk][ty * 8 + 4];
            *(float4*)&bb[0] = *(const float4*)&Bs[kk][tx * 4];
#pragma unroll
            for (int i = 0; i < 8; i++)
#pragma unroll
                for (int j = 0; j < 4; j++) acc[i][j] += a[i] * bb[j];
        }
        __syncthreads();
    }
#pragma unroll
    for (int i = 0; i < 8; i++)
#pragma unroll
        for (int j = 0; j < 4; j++)
            Cz[(size_t)(m0 + ty * 8 + i) * ldc + n0 + tx * 4 + j] = acc[i][j];
}

// ---------------- init ----------------
__global__ void init_k(const float* __restrict__ goal0, const float* __restrict__ w0,
                       float* __restrict__ outGoals, float* __restrict__ outWs) {
    int idx = blockIdx.x * blockDim.x + threadIdx.x;
    bf16 z = __float2bfloat16(0.f);
    if (idx < 2 * B * HW) {
        g_wh1[idx] = 0.f;
        g_wh0h[idx] = z; g_wh0l[idx] = z;
        g_wh1h[idx] = z; g_wh1l[idx] = z;
    }
    if (idx < B * HW) { g_wc0[idx] = 0.f; g_wc1[idx] = 0.f; }
    if (idx < 2 * B * HG) {
        g_gh1[idx] = 0.f;
        g_gh0h[idx] = z; g_gh0l[idx] = z;
        g_gh1h[idx] = z; g_gh1l[idx] = z;
    }
    if (idx < B * HG) { g_gc0[idx] = 0.f; g_gc1[idx] = 0.f; }
    if (idx < B * DOF) {
        int b = idx / DOF, d = idx - b * DOF;
        float v = goal0[idx];
        g_cat[b * CATD + d] = v;
        outGoals[(size_t)b * MS * DOF + d] = v;
    }
    if (idx < B * WSZ) {
        int b = idx / WSZ, d = idx - b * WSZ;
        float v = w0[idx];
        g_cat[b * CATD + DOF + d] = v;
        outWs[(size_t)b * MS * WSZ + d] = v;
    }
}

// ---------------- bilinear: writes hi/lo bf16 directly ----------------
__global__ __launch_bounds__(256) void bilinear_k(const float* __restrict__ bw_b,
                                                  const float* __restrict__ bg_b) {
    __shared__ float sc[CATD];
    int b = blockIdx.x, part = blockIdx.y;
    int t = threadIdx.x;
    for (int k = t; k < CATD; k += 256) sc[k] = g_cat[b * CATD + k];
    __syncthreads();
    if (part < 2) {
        int o = part * 256 + t;
        const float* a = g_Aw + (size_t)b * CATD * PW + o;
        float acc0 = __ldg(&bw_b[o]), acc1 = 0.f;
#pragma unroll 6
        for (int j = 0; j < CATD; j += 2) {
            acc0 += a[(size_t)j * PW] * sc[j];
            acc1 += a[(size_t)(j + 1) * PW] * sc[j + 1];
        }
        float v = acc0 + acc1;
        bf16 hi = __float2bfloat16(v);
        g_ywh[b * PW + o] = hi;
        g_ywl[b * PW + o] = __float2bfloat16(v - __bfloat162float(hi));
    } else {
        int o = t;
        const float* a = g_Ag + (size_t)b * DOF * PG + o;
        float acc = __ldg(&bg_b[o]);
#pragma unroll
        for (int j = 0; j < DOF; j++) acc += a[j * PG] * sc[j];
        bf16 hi = __float2bfloat16(acc);
        g_xgh[b * PG + o] = hi;
        g_xgl[b * PG + o] = __float2bfloat16(acc - __bfloat162float(hi));
    }
}

// ---------------- host ----------------
extern "C" void kernel_launch(void* const* d_in, const int* in_sizes, int n_in,
                              void* d_out, int out_size) {
    const float* ctx    = (const float*)d_in[0];
    const float* goal0  = (const float*)d_in[1];
    const float* w0     = (const float*)d_in[2];
    const float* bg_W   = (const float*)d_in[3];
    const float* bg_b   = (const float*)d_in[4];
    const float* bw_W   = (const float*)d_in[5];
    const float* bw_b   = (const float*)d_in[6];
    const float* fcg_W  = (const float*)d_in[7];
    const float* fcg_b  = (const float*)d_in[8];
    const float* fcw_W  = (const float*)d_in[9];
    const float* fcw_b  = (const float*)d_in[10];
    const float* lg_Wih = (const float*)d_in[11];
    const float* lg_Whh = (const float*)d_in[12];
    const float* lg_bih = (const float*)d_in[13];
    const float* lg_bhh = (const float*)d_in[14];
    const float* lw_Wih = (const float*)d_in[15];
    const float* lw_Whh = (const float*)d_in[16];
    const float* lw_bih = (const float*)d_in[17];
    const float* lw_bhh = (const float*)d_in[18];
    const float* og_W   = (const float*)d_in[19];
    const float* og_b   = (const float*)d_in[20];
    const float* ow_W   = (const float*)d_in[21];
    const float* ow_b   = (const float*)d_in[22];

    float* out   = (float*)d_out;
    float* goals = out;
    float* ws    = out + (size_t)B * MS * DOF;

    float *Gt, *Ag, *gh1, *gc0, *gc1, *wh1, *wc0, *wc1, *gh0f, *wh0f;
    bf16 *gh0h, *gh0l, *gh1h, *gh1l, *wh0h, *wh0l, *wh1h, *wh1l;
    bf16 *WgL0h, *WgL0l, *WgL1h, *WgL1l, *WwL0h, *WwL0l, *WwL1h, *WwL1l;
    bf16 *FwH, *FwL, *FgH, *FgL, *OwH, *OwL;
    float *BgL0, *BgL1, *BwL0, *BwL1;
    bf16 *x2h, *x2l, *y2h, *y2l;
    cudaGetSymbolAddress((void**)&Gt, g_Gt);
    cudaGetSymbolAddress((void**)&Ag, g_Ag);
    cudaGetSymbolAddress((void**)&gh1, g_gh1);
    cudaGetSymbolAddress((void**)&gc0, g_gc0);
    cudaGetSymbolAddress((void**)&gc1, g_gc1);
    cudaGetSymbolAddress((void**)&wh1, g_wh1);
    cudaGetSymbolAddress((void**)&wc0, g_wc0);
    cudaGetSymbolAddress((void**)&wc1, g_wc1);
    cudaGetSymbolAddress((void**)&gh0f, g_gh0f);
    cudaGetSymbolAddress((void**)&wh0f, g_wh0f);
    cudaGetSymbolAddress((void**)&gh0h, g_gh0h);
    cudaGetSymbolAddress((void**)&gh0l, g_gh0l);
    cudaGetSymbolAddress((void**)&gh1h, g_gh1h);
    cudaGetSymbolAddress((void**)&gh1l, g_gh1l);
    cudaGetSymbolAddress((void**)&wh0h, g_wh0h);
    cudaGetSymbolAddress((void**)&wh0l, g_wh0l);
    cudaGetSymbolAddress((void**)&wh1h, g_wh1h);
    cudaGetSymbolAddress((void**)&wh1l, g_wh1l);
    cudaGetSymbolAddress((void**)&WgL0h, g_WgL0h);
    cudaGetSymbolAddress((void**)&WgL0l, g_WgL0l);
    cudaGetSymbolAddress((void**)&WgL1h, g_WgL1h);
    cudaGetSymbolAddress((void**)&WgL1l, g_WgL1l);
    cudaGetSymbolAddress((void**)&WwL0h, g_WwL0h);
    cudaGetSymbolAddress((void**)&WwL0l, g_WwL0l);
    cudaGetSymbolAddress((void**)&WwL1h, g_WwL1h);
    cudaGetSymbolAddress((void**)&WwL1l, g_WwL1l);
    cudaGetSymbolAddress((void**)&BgL0, g_BgL0);
    cudaGetSymbolAddress((void**)&BgL1, g_BgL1);
    cudaGetSymbolAddress((void**)&BwL0, g_BwL0);
    cudaGetSymbolAddress((void**)&BwL1, g_BwL1);
    cudaGetSymbolAddress((void**)&FwH, g_FwH);
    cudaGetSymbolAddress((void**)&FwL, g_FwL);
    cudaGetSymbolAddress((void**)&FgH, g_FgH);
    cudaGetSymbolAddress((void**)&FgL, g_FgL);
    cudaGetSymbolAddress((void**)&OwH, g_OwH);
    cudaGetSymbolAddress((void**)&OwL, g_OwL);
    cudaGetSymbolAddress((void**)&x2h, g_x2h);
    cudaGetSymbolAddress((void**)&x2l, g_x2l);
    cudaGetSymbolAddress((void**)&y2h, g_y2h);
    cudaGetSymbolAddress((void**)&y2l, g_y2l);

    static bool attr_set = false;
    if (!attr_set) {
        cudaFuncSetAttribute(aw_mma_kernel, cudaFuncAttributeMaxDynamicSharedMemorySize, 55296);
        attr_set = true;
    }

    // precompute path
    split_ctx<<<(B * CTXD) / 256, 256>>>(ctx);
    transpose_bw_split<<<dim3(CTXD / 32, PW, (CATD + 31) / 32), dim3(32, 32)>>>(bw_W);
    aw_mma_kernel<<<dim3(PW / 64, B / 128, CATD), 256, 55296>>>();

    dim3 tblk(32, 32);
    transpose_oij_jio<<<dim3(CTXD, PG / 32, 1), tblk>>>(bg_W, Gt, PG, CTXD, DOF);
    gemm_nn_batched<<<dim3(PG / 64, B / 128, DOF), 256>>>(
        ctx, CTXD, Gt, (size_t)CTXD * PG, Ag, DOF * PG, PG, PG, CTXD);

    // pack weights
    pack_w<<<(4 * HG * (PG + HG)) / 256, 256>>>(lg_Wih, lg_Whh, lg_bih, lg_bhh,
                                                WgL0h, WgL0l, BgL0, HG, PG);
    pack_w<<<(4 * HG * (HG + HG)) / 256, 256>>>(lg_Wih + (size_t)4 * HG * PG,
                                                lg_Whh + (size_t)4 * HG * HG,
                                                lg_bih + 4 * HG, lg_bhh + 4 * HG,
                                                WgL1h, WgL1l, BgL1, HG, HG);
    pack_w<<<(4 * HW * (PW + HW)) / 256, 256>>>(lw_Wih, lw_Whh, lw_bih, lw_bhh,
                                                WwL0h, WwL0l, BwL0, HW, PW);
    pack_w<<<(4 * HW * (HW + HW)) / 256, 256>>>(lw_Wih + (size_t)4 * HW * PW,
                                                lw_Whh + (size_t)4 * HW * HW,
                                                lw_bih + 4 * HW, lw_bhh + 4 * HW,
                                                WwL1h, WwL1l, BwL1, HW, HW);
    pack_plain<<<(PW * PW) / 256, 256>>>(fcw_W, FwH, FwL, PW, PW);
    pack_plain<<<(PG * PG) / 256, 256>>>(fcg_W, FgH, FgL, PG, PG);
    pack_plain<<<(WSZP * HW) / 256, 256>>>(ow_W, OwH, OwL, WSZ, HW);

    init_k<<<(2 * B * HW) / 256, 256>>>(goal0, w0, goals, ws);

    const int BHG = B * HG, BHW = B * HW;
    for (int s = 0; s < NSTEPS; s++) {
        const int p = s & 1;
        const int q = p ^ 1;

        bilinear_k<<<dim3(B, 3), 256>>>(bw_b, bg_b);
        fc_hmma<<<48, 128>>>(fcw_b, fcg_b);

        // layer 0
        gates_hmma<<<384, 128>>>(
            x2h, x2l, PG, gh0h + p * BHG, gh0l + p * BHG,
            WgL0h, WgL0l, BgL0, gc0, nullptr, gh0h + q * BHG, gh0l + q * BHG,
            y2h, y2l, PW, wh0h + p * BHW, wh0l + p * BHW,
            WwL0h, WwL0l, BwL0, wc0, nullptr, wh0h + q * BHW, wh0l + q * BHW);

        // layer 1
        gates_hmma<<<384, 128>>>(
            gh0h + q * BHG, gh0l + q * BHG, HG, gh1h + p * BHG, gh1l + p * BHG,
            WgL1h, WgL1l, BgL1, gc1, gh1 + q * BHG, gh1h + q * BHG, gh1l + q * BHG,
            wh0h + q * BHW, wh0l + q * BHW, HW, wh1h + p * BHW, wh1l + p * BHW,
            WwL1h, WwL1l, BwL1, wc1, nullptr, wh1h + q * BHW, wh1l + q * BHW);

        heads_k<<<32, 128>>>(gh1 + q * BHG, og_W, og_b, goals + (size_t)(s + 1) * DOF,
                             wh1h + q * BHW, wh1l + q * BHW, ow_b,
                             ws + (size_t)(s + 1) * WSZ);
    }
    (void)in_sizes; (void)n_in; (void)out_size; (void)gh0f; (void)wh0f; (void)wh1;
}

// round 10
// speedup vs baseline: 4.2150x; 1.2699x over previous
#include <cuda_runtime.h>
#include <cuda_bf16.h>
#include <math.h>
#include <stdint.h>

#define B    256
#define CTXD 512
#define DOF  6
#define WSZ  300
#define WSZP 320
#define CATD 306
#define PG   256
#define PW   512
#define HG   256
#define HW   512
#define MS   20
#define NSTEPS 19

typedef __nv_bfloat16 bf16;

// ---------------- device scratch ----------------
__device__ bf16 g_Whi[(size_t)CATD * PW * CTXD];  // [j][o][i]
__device__ bf16 g_Wlo[(size_t)CATD * PW * CTXD];
__device__ bf16 g_ctx_hi[B * CTXD];
__device__ bf16 g_ctx_lo[B * CTXD];
__device__ float g_Gt[(size_t)DOF * CTXD * PG];
__device__ float g_Aw[(size_t)B * CATD * PW];
__device__ float g_Ag[(size_t)B * DOF * PG];
__device__ bf16  g_ywh[B * PW];
__device__ bf16  g_ywl[B * PW];
__device__ bf16  g_xgh[B * PG];
__device__ bf16  g_xgl[B * PG];
__device__ bf16  g_x2h[B * PG];
__device__ bf16  g_x2l[B * PG];
__device__ bf16  g_y2h[B * PW];
__device__ bf16  g_y2l[B * PW];
__device__ float g_cat[B * CATD];
__device__ float g_gh1[2 * B * HG];
__device__ bf16  g_gh0h[2 * B * HG];
__device__ bf16  g_gh0l[2 * B * HG];
__device__ bf16  g_gh1h[2 * B * HG];
__device__ bf16  g_gh1l[2 * B * HG];
__device__ float g_gc0[B * HG];
__device__ float g_gc1[B * HG];
__device__ float g_wh1[2 * B * HW];
__device__ bf16  g_wh0h[2 * B * HW];
__device__ bf16  g_wh0l[2 * B * HW];
__device__ bf16  g_wh1h[2 * B * HW];
__device__ bf16  g_wh1l[2 * B * HW];
__device__ float g_wc0[B * HW];
__device__ float g_wc1[B * HW];
// packed gate-interleaved LSTM weights
__device__ bf16  g_WgL0h[4 * HG * (PG + HG)];
__device__ bf16  g_WgL0l[4 * HG * (PG + HG)];
__device__ bf16  g_WgL1h[4 * HG * (HG + HG)];
__device__ bf16  g_WgL1l[4 * HG * (HG + HG)];
__device__ bf16  g_WwL0h[(size_t)4 * HW * (PW + HW)];
__device__ bf16  g_WwL0l[(size_t)4 * HW * (PW + HW)];
__device__ bf16  g_WwL1h[(size_t)4 * HW * (HW + HW)];
__device__ bf16  g_WwL1l[(size_t)4 * HW * (HW + HW)];
__device__ float g_BgL0[4 * HG];
__device__ float g_BgL1[4 * HG];
__device__ float g_BwL0[4 * HW];
__device__ float g_BwL1[4 * HW];
// packed plain weights (fc, ow)
__device__ bf16  g_FwH[PW * PW];
__device__ bf16  g_FwL[PW * PW];
__device__ bf16  g_FgH[PG * PG];
__device__ bf16  g_FgL[PG * PG];
__device__ bf16  g_OwH[WSZP * HW];
__device__ bf16  g_OwL[WSZP * HW];

__device__ __forceinline__ float sigf(float x) { return 1.f / (1.f + expf(-x)); }

__device__ __forceinline__ uint32_t smem_u32(const void* p) {
    uint32_t a;
    asm("{ .reg .u64 tmp; cvta.to.shared.u64 tmp, %1; cvt.u32.u64 %0, tmp; }" : "=r"(a) : "l"(p));
    return a;
}

#define LDM4(r0, r1, r2, r3, addr) \
    asm volatile("ldmatrix.sync.aligned.m8n8.x4.shared.b16 {%0,%1,%2,%3}, [%4];" \
                 : "=r"(r0), "=r"(r1), "=r"(r2), "=r"(r3) : "r"(addr))
#define MMA_BF16(acc, af, bf0, bf1) \
    asm volatile("mma.sync.aligned.m16n8k16.row.col.f32.bf16.bf16.f32 " \
                 "{%0,%1,%2,%3}, {%4,%5,%6,%7}, {%8,%9}, {%0,%1,%2,%3};" \
                 : "+f"((acc)[0]), "+f"((acc)[1]), "+f"((acc)[2]), "+f"((acc)[3]) \
                 : "r"((af)[0]), "r"((af)[1]), "r"((af)[2]), "r"((af)[3]), \
                   "r"(bf0), "r"(bf1))

__device__ __forceinline__ void cp16(uint32_t saddr, const void* gptr) {
    asm volatile("cp.async.cg.shared.global [%0], [%1], 16;" :: "r"(saddr), "l"(gptr) : "memory");
}
#define CP_COMMIT() asm volatile("cp.async.commit_group;" ::: "memory")
#define CP_WAIT1()  asm volatile("cp.async.wait_group 1;" ::: "memory")
#define CP_WAIT0()  asm volatile("cp.async.wait_group 0;" ::: "memory")

// smem stage sizes (bf16 elements)
#define GATES_STG (2 * 64 * 72 + 2 * 32 * 72)   // 13824
#define FC_STG    (4 * 64 * 72)                  // 18432
#define AW_STG    (2 * 128 * 72 + 2 * 64 * 72)   // 27648
#define GATES_SMEM (2 * GATES_STG * 2)           // 55296 B
#define FC_SMEM    (2 * FC_STG * 2)              // 73728 B
#define AW_SMEM    (2 * AW_STG * 2)              // 110592 B

// ---------------- split ctx into bf16 hi/lo ----------------
__global__ void split_ctx(const float* __restrict__ ctx) {
    int i = blockIdx.x * 256 + threadIdx.x;
    float x = ctx[i];
    bf16 hi = __float2bfloat16(x);
    g_ctx_hi[i] = hi;
    g_ctx_lo[i] = __float2bfloat16(x - __bfloat162float(hi));
}

// ---------------- transpose bw_W (o,i,j) -> hi/lo [j][o][i] ----------------
__global__ void transpose_bw_split(const float* __restrict__ in) {
    __shared__ float tile[32][33];
    int i0 = blockIdx.x * 32;
    int o  = blockIdx.y;
    int j0 = blockIdx.z * 32;
    int tx = threadIdx.x, ty = threadIdx.y;
    int j = j0 + tx;
    if (j < CATD)
        tile[ty][tx] = in[(size_t)o * CTXD * CATD + (size_t)(i0 + ty) * CATD + j];
    __syncthreads();
    int jw = j0 + ty;
    if (jw < CATD) {
        float v = tile[tx][ty];
        bf16 hi = __float2bfloat16(v);
        bf16 lo = __float2bfloat16(v - __bfloat162float(hi));
        size_t base = ((size_t)jw * PW + o) * CTXD + i0 + tx;
        g_Whi[base] = hi;
        g_Wlo[base] = lo;
    }
}

// ---------------- pack LSTM weights (gate-interleaved) ----------------
__global__ void pack_w(const float* __restrict__ Wih, const float* __restrict__ Whh,
                       const float* __restrict__ bih, const float* __restrict__ bhh,
                       bf16* __restrict__ outH, bf16* __restrict__ outL,
                       float* __restrict__ outB, int H, int Kin) {
    int Kcat = Kin + H;
    size_t idx = (size_t)blockIdx.x * 256 + threadIdx.x;
    int r = (int)(idx / Kcat), k = (int)(idx % Kcat);
    int u = r >> 2, gate = r & 3, src = gate * H + u;
    float v = (k < Kin) ? Wih[(size_t)src * Kin + k] : Whh[(size_t)src * H + (k - Kin)];
    bf16 hi = __float2bfloat16(v);
    outH[idx] = hi;
    outL[idx] = __float2bfloat16(v - __bfloat162float(hi));
    if (k == 0) outB[r] = bih[src] + bhh[src];
}

// ---------------- pack plain weights (zero-padded rows) ----------------
__global__ void pack_plain(const float* __restrict__ W, bf16* __restrict__ outH,
                           bf16* __restrict__ outL, int N, int K) {
    size_t idx = (size_t)blockIdx.x * 256 + threadIdx.x;
    int r = (int)(idx / K), k = (int)(idx % K);
    float v = (r < N) ? W[(size_t)r * K + k] : 0.f;
    bf16 hi = __float2bfloat16(v);
    outH[idx] = hi;
    outL[idx] = __float2bfloat16(v - __bfloat162float(hi));
}

// ---------------- aw precompute: merged-pass HMMA, cp.async double-buffered ---------
__global__ __launch_bounds__(256) void aw_mma_kernel() {
    extern __shared__ bf16 smd[];
    int t = threadIdx.x;
    int lane = t & 31, wid = t >> 5;
    int warp_m = wid & 3, warp_n = wid >> 2;
    int n0 = blockIdx.x * 64;
    int m0 = blockIdx.y * 128;
    int j  = blockIdx.z;

    float acc[2][4][4];
#pragma unroll
    for (int a = 0; a < 2; a++)
#pragma unroll
        for (int b = 0; b < 4; b++)
#pragma unroll
            for (int c = 0; c < 4; c++) acc[a][b][c] = 0.f;

    const bf16* Bhi = g_Whi + (size_t)j * PW * CTXD;
    const bf16* Blo = g_Wlo + (size_t)j * PW * CTXD;

    int a_mloc = lane & 15;
    int a_koff = (lane >> 4) * 8;
    int b_nfsel = lane >> 4;
    int b_khalf = (lane >> 3) & 1;
    int b_nloc = lane & 7;

    auto issue = [&](int ch, int stage) {
        bf16* dAh = smd + stage * AW_STG;
        bf16* dAl = dAh + 128 * 72;
        bf16* dBh = dAl + 128 * 72;
        bf16* dBl = dBh + 64 * 72;
        int k0 = ch << 6;
#pragma unroll
        for (int i = 0; i < 4; i++) {
            int idx = t + i * 256;
            int r = idx >> 3, sg = idx & 7;
            cp16(smem_u32(&dAh[r * 72 + sg * 8]), g_ctx_hi + (size_t)(m0 + r) * CTXD + k0 + sg * 8);
            cp16(smem_u32(&dAl[r * 72 + sg * 8]), g_ctx_lo + (size_t)(m0 + r) * CTXD + k0 + sg * 8);
        }
#pragma unroll
        for (int i = 0; i < 2; i++) {
            int idx = t + i * 256;
            int r = idx >> 3, sg = idx & 7;
            cp16(smem_u32(&dBh[r * 72 + sg * 8]), Bhi + (size_t)(n0 + r) * CTXD + k0 + sg * 8);
            cp16(smem_u32(&dBl[r * 72 + sg * 8]), Blo + (size_t)(n0 + r) * CTXD + k0 + sg * 8);
        }
        CP_COMMIT();
    };

    const int nch = CTXD / 64;
    issue(0, 0);
    for (int ch = 0; ch < nch; ch++) {
        if (ch + 1 < nch) { issue(ch + 1, (ch + 1) & 1); CP_WAIT1(); }
        else { CP_WAIT0(); }
        __syncthreads();
        bf16* sAh = smd + (ch & 1) * AW_STG;
        bf16* sAl = sAh + 128 * 72;
        bf16* sBh = sAl + 128 * 72;
        bf16* sBl = sBh + 64 * 72;
#pragma unroll
        for (int kk = 0; kk < 4; kk++) {
            int kb = kk * 16;
            uint32_t ah[2][4], al[2][4], bh[4][2], bl[4][2];
#pragma unroll
            for (int mf = 0; mf < 2; mf++) {
                uint32_t addr = smem_u32(&sAh[(warp_m * 32 + mf * 16 + a_mloc) * 72 + kb + a_koff]);
                LDM4(ah[mf][0], ah[mf][1], ah[mf][2], ah[mf][3], addr);
                addr = smem_u32(&sAl[(warp_m * 32 + mf * 16 + a_mloc) * 72 + kb + a_koff]);
                LDM4(al[mf][0], al[mf][1], al[mf][2], al[mf][3], addr);
            }
#pragma unroll
            for (int bp = 0; bp < 2; bp++) {
                uint32_t addr = smem_u32(&sBh[(warp_n * 32 + bp * 16 + b_nfsel * 8 + b_nloc) * 72 + kb + b_khalf * 8]);
                LDM4(bh[bp * 2][0], bh[bp * 2][1], bh[bp * 2 + 1][0], bh[bp * 2 + 1][1], addr);
                addr = smem_u32(&sBl[(warp_n * 32 + bp * 16 + b_nfsel * 8 + b_nloc) * 72 + kb + b_khalf * 8]);
                LDM4(bl[bp * 2][0], bl[bp * 2][1], bl[bp * 2 + 1][0], bl[bp * 2 + 1][1], addr);
            }
#pragma unroll
            for (int mf = 0; mf < 2; mf++)
#pragma unroll
                for (int nf = 0; nf < 4; nf++) {
                    MMA_BF16(acc[mf][nf], ah[mf], bh[nf][0], bh[nf][1]);
                    MMA_BF16(acc[mf][nf], ah[mf], bl[nf][0], bl[nf][1]);
                    MMA_BF16(acc[mf][nf], al[mf], bh[nf][0], bh[nf][1]);
                }
        }
        __syncthreads();
    }

    int g = lane >> 2, tg = lane & 3;
#pragma unroll
    for (int mf = 0; mf < 2; mf++) {
        int row0 = m0 + warp_m * 32 + mf * 16 + g;
#pragma unroll
        for (int nf = 0; nf < 4; nf++) {
            int col = n0 + warp_n * 32 + nf * 8 + tg * 2;
            float* d0 = g_Aw + ((size_t)row0 * CATD + j) * PW + col;
            float* d1 = g_Aw + ((size_t)(row0 + 8) * CATD + j) * PW + col;
            d0[0] = acc[mf][nf][0]; d0[1] = acc[mf][nf][1];
            d1[0] = acc[mf][nf][2]; d1[1] = acc[mf][nf][3];
        }
    }
}

// ---------------- gates HMMA: 64x32 tile, cp.async pipelined, fused pointwise ------
__device__ __forceinline__ void gates_tile32(
        const bf16* __restrict__ ActH, const bf16* __restrict__ ActL, int Kin,
        const bf16* __restrict__ HoldH, const bf16* __restrict__ HoldL,
        const bf16* __restrict__ WH, const bf16* __restrict__ WL,
        const float* __restrict__ biasCat,
        float* C, float* Hf, bf16* Hh, bf16* Hl,
        int H, int m0, int n0c, bf16* smd) {
    int t = threadIdx.x, lane = t & 31, wid = t >> 5;
    int warp_m = wid & 1, warp_n = wid >> 1;
    int a_mloc = lane & 15;
    int a_koff = (lane >> 4) * 8;
    int b_nfsel = lane >> 4, b_khalf = (lane >> 3) & 1, b_nloc = lane & 7;

    float acc[2][2][4];
#pragma unroll
    for (int a = 0; a < 2; a++)
#pragma unroll
        for (int b = 0; b < 2; b++)
#pragma unroll
            for (int c = 0; c < 4; c++) acc[a][b][c] = 0.f;

    int Kcat = Kin + H;
    int nch = Kcat >> 6;

    auto issue = [&](int ch, int stage) {
        bf16* dAh = smd + stage * GATES_STG;
        bf16* dAl = dAh + 64 * 72;
        bf16* dWh = dAl + 64 * 72;
        bf16* dWl = dWh + 32 * 72;
        int k0 = ch << 6;
        const bf16 *srcH, *srcL; int ld, off;
        if (k0 < Kin) { srcH = ActH; srcL = ActL; ld = Kin; off = k0; }
        else          { srcH = HoldH; srcL = HoldL; ld = H; off = k0 - Kin; }
#pragma unroll
        for (int i = 0; i < 4; i++) {
            int idx = t + i * 128;
            int r = idx >> 3, sg = idx & 7;
            cp16(smem_u32(&dAh[r * 72 + sg * 8]), srcH + (size_t)(m0 + r) * ld + off + sg * 8);
            cp16(smem_u32(&dAl[r * 72 + sg * 8]), srcL + (size_t)(m0 + r) * ld + off + sg * 8);
        }
#pragma unroll
        for (int i = 0; i < 2; i++) {
            int idx = t + i * 128;
            int r = idx >> 3, sg = idx & 7;
            cp16(smem_u32(&dWh[r * 72 + sg * 8]), WH + (size_t)(n0c + r) * Kcat + k0 + sg * 8);
            cp16(smem_u32(&dWl[r * 72 + sg * 8]), WL + (size_t)(n0c + r) * Kcat + k0 + sg * 8);
        }
        CP_COMMIT();
    };

    issue(0, 0);
    for (int ch = 0; ch < nch; ch++) {
        if (ch + 1 < nch) { issue(ch + 1, (ch + 1) & 1); CP_WAIT1(); }
        else { CP_WAIT0(); }
        __syncthreads();
        bf16* sAh = smd + (ch & 1) * GATES_STG;
        bf16* sAl = sAh + 64 * 72;
        bf16* sWh = sAl + 64 * 72;
        bf16* sWl = sWh + 32 * 72;
#pragma unroll
        for (int kk = 0; kk < 4; kk++) {
            int kb = kk * 16;
            uint32_t ah[2][4], al[2][4], wh[2][2], wl[2][2];
#pragma unroll
            for (int mf = 0; mf < 2; mf++) {
                uint32_t addr = smem_u32(&sAh[(warp_m * 32 + mf * 16 + a_mloc) * 72 + kb + a_koff]);
                LDM4(ah[mf][0], ah[mf][1], ah[mf][2], ah[mf][3], addr);
                addr = smem_u32(&sAl[(warp_m * 32 + mf * 16 + a_mloc) * 72 + kb + a_koff]);
                LDM4(al[mf][0], al[mf][1], al[mf][2], al[mf][3], addr);
            }
            {
                uint32_t addr = smem_u32(&sWh[(warp_n * 16 + b_nfsel * 8 + b_nloc) * 72 + kb + b_khalf * 8]);
                LDM4(wh[0][0], wh[0][1], wh[1][0], wh[1][1], addr);
                addr = smem_u32(&sWl[(warp_n * 16 + b_nfsel * 8 + b_nloc) * 72 + kb + b_khalf * 8]);
                LDM4(wl[0][0], wl[0][1], wl[1][0], wl[1][1], addr);
            }
#pragma unroll
            for (int mf = 0; mf < 2; mf++)
#pragma unroll
                for (int nf = 0; nf < 2; nf++) {
                    MMA_BF16(acc[mf][nf], ah[mf], wh[nf][0], wh[nf][1]);
                    MMA_BF16(acc[mf][nf], ah[mf], wl[nf][0], wl[nf][1]);
                    MMA_BF16(acc[mf][nf], al[mf], wh[nf][0], wh[nf][1]);
                }
        }
        __syncthreads();
    }

    int g = lane >> 2, tg = lane & 3;
#pragma unroll
    for (int mf = 0; mf < 2; mf++) {
        int row = m0 + warp_m * 32 + mf * 16 + g;
#pragma unroll
        for (int nf = 0; nf < 2; nf++) {
            float* a = acc[mf][nf];
            float s0 = (tg & 1) ? a[0] : a[2];
            float r0 = __shfl_xor_sync(0xffffffffu, s0, 1);
            float s1 = (tg & 1) ? a[1] : a[3];
            float r1 = __shfl_xor_sync(0xffffffffu, s1, 1);
            int base = n0c + warp_n * 16 + nf * 8;
            int u_ = (base >> 2) + (tg >> 1);
            int rowi = (tg & 1) ? row + 8 : row;
            float iv, fv, gv, ov;
            if (tg & 1) { iv = r0; fv = r1; gv = a[2]; ov = a[3]; }
            else        { iv = a[0]; fv = a[1]; gv = r0; ov = r1; }
            float4 bb = *(const float4*)(biasCat + u_ * 4);
            float i_ = sigf(iv + bb.x), f_ = sigf(fv + bb.y);
            float g_ = tanhf(gv + bb.z), o_ = sigf(ov + bb.w);
            int li = rowi * H + u_;
            float cn = f_ * C[li] + i_ * g_;
            C[li] = cn;
            float h = o_ * tanhf(cn);
            if (Hf) Hf[li] = h;
            bf16 hh = __float2bfloat16(h);
            Hh[li] = hh;
            Hl[li] = __float2bfloat16(h - __bfloat162float(hh));
        }
    }
}

__global__ __launch_bounds__(128) void gates_hmma(
        const bf16* gActH, const bf16* gActL, int gKin,
        const bf16* gHoldH, const bf16* gHoldL,
        const bf16* gWH, const bf16* gWL, const float* gB,
        float* gC, float* gHf, bf16* gHh, bf16* gHl,
        const bf16* wActH, const bf16* wActL, int wKin,
        const bf16* wHoldH, const bf16* wHoldL,
        const bf16* wWH, const bf16* wWL, const float* wB,
        float* wC, float* wHf, bf16* wHh, bf16* wHl) {
    extern __shared__ bf16 smd[];
    int u = blockIdx.x;
    if (u < 128) {
        int mt = u >> 5, nt = u & 31;
        gates_tile32(gActH, gActL, gKin, gHoldH, gHoldL, gWH, gWL, gB,
                     gC, gHf, gHh, gHl, HG, mt * 64, nt * 32, smd);
    } else {
        int v = u - 128;
        int mt = v >> 6, nt = v & 63;
        gates_tile32(wActH, wActL, wKin, wHoldH, wHoldL, wWH, wWL, wB,
                     wC, wHf, wHh, wHl, HW, mt * 64, nt * 32, smd);
    }
}

// ---------------- generic 64x64 HMMA core with cp.async, returns acc ----------------
__device__ __forceinline__ void hmma64_core(
        const bf16* __restrict__ ActH, const bf16* __restrict__ ActL, int K,
        const bf16* __restrict__ WH, const bf16* __restrict__ WL,
        int m0, int n0, bf16* smd, float acc[2][4][4]) {
    int t = threadIdx.x, lane = t & 31, wid = t >> 5;
    int warp_m = wid & 1, warp_n = wid >> 1;
    int a_mloc = lane & 15;
    int a_koff = (lane >> 4) * 8;
    int b_nfsel = lane >> 4, b_khalf = (lane >> 3) & 1, b_nloc = lane & 7;

#pragma unroll
    for (int a = 0; a < 2; a++)
#pragma unroll
        for (int b = 0; b < 4; b++)
#pragma unroll
            for (int c = 0; c < 4; c++) acc[a][b][c] = 0.f;

    int nch = K >> 6;
    auto issue = [&](int ch, int stage) {
        bf16* dAh = smd + stage * FC_STG;
        bf16* dAl = dAh + 64 * 72;
        bf16* dWh = dAl + 64 * 72;
        bf16* dWl = dWh + 64 * 72;
        int k0 = ch << 6;
#pragma unroll
        for (int i = 0; i < 4; i++) {
            int idx = t + i * 128;
            int r = idx >> 3, sg = idx & 7;
            cp16(smem_u32(&dAh[r * 72 + sg * 8]), ActH + (size_t)(m0 + r) * K + k0 + sg * 8);
            cp16(smem_u32(&dAl[r * 72 + sg * 8]), ActL + (size_t)(m0 + r) * K + k0 + sg * 8);
            cp16(smem_u32(&dWh[r * 72 + sg * 8]), WH + (size_t)(n0 + r) * K + k0 + sg * 8);
            cp16(smem_u32(&dWl[r * 72 + sg * 8]), WL + (size_t)(n0 + r) * K + k0 + sg * 8);
        }
        CP_COMMIT();
    };

    issue(0, 0);
    for (int ch = 0; ch < nch; ch++) {
        if (ch + 1 < nch) { issue(ch + 1, (ch + 1) & 1); CP_WAIT1(); }
        else { CP_WAIT0(); }
        __syncthreads();
        bf16* sAh = smd + (ch & 1) * FC_STG;
        bf16* sAl = sAh + 64 * 72;
        bf16* sWh = sAl + 64 * 72;
        bf16* sWl = sWh + 64 * 72;
#pragma unroll
        for (int kk = 0; kk < 4; kk++) {
            int kb = kk * 16;
            uint32_t ah[2][4], al[2][4], wh[4][2], wl[4][2];
#pragma unroll
            for (int mf = 0; mf < 2; mf++) {
                uint32_t addr = smem_u32(&sAh[(warp_m * 32 + mf * 16 + a_mloc) * 72 + kb + a_koff]);
                LDM4(ah[mf][0], ah[mf][1], ah[mf][2], ah[mf][3], addr);
                addr = smem_u32(&sAl[(warp_m * 32 + mf * 16 + a_mloc) * 72 + kb + a_koff]);
                LDM4(al[mf][0], al[mf][1], al[mf][2], al[mf][3], addr);
            }
#pragma unroll
            for (int bp = 0; bp < 2; bp++) {
                uint32_t addr = smem_u32(&sWh[(warp_n * 32 + bp * 16 + b_nfsel * 8 + b_nloc) * 72 + kb + b_khalf * 8]);
                LDM4(wh[bp * 2][0], wh[bp * 2][1], wh[bp * 2 + 1][0], wh[bp * 2 + 1][1], addr);
                addr = smem_u32(&sWl[(warp_n * 32 + bp * 16 + b_nfsel * 8 + b_nloc) * 72 + kb + b_khalf * 8]);
                LDM4(wl[bp * 2][0], wl[bp * 2][1], wl[bp * 2 + 1][0], wl[bp * 2 + 1][1], addr);
            }
#pragma unroll
            for (int mf = 0; mf < 2; mf++)
#pragma unroll
                for (int nf = 0; nf < 4; nf++) {
                    MMA_BF16(acc[mf][nf], ah[mf], wh[nf][0], wh[nf][1]);
                    MMA_BF16(acc[mf][nf], ah[mf], wl[nf][0], wl[nf][1]);
                    MMA_BF16(acc[mf][nf], al[mf], wh[nf][0], wh[nf][1]);
                }
        }
        __syncthreads();
    }
}

// ---------------- fc: HMMA + tanh + split epilogue ----------------
__global__ __launch_bounds__(128) void fc_hmma(const float* __restrict__ fcw_b,
                                               const float* __restrict__ fcg_b) {
    extern __shared__ bf16 smd[];
    int u = blockIdx.x;
    const bf16 *ActH, *ActL, *WH, *WL;
    const float* bias;
    bf16 *Hh, *Hl;
    int K, ldc, m0, n0;
    if (u < 16) {
        m0 = (u >> 2) * 64; n0 = (u & 3) * 64;
        ActH = g_xgh; ActL = g_xgl; WH = g_FgH; WL = g_FgL;
        bias = fcg_b; Hh = g_x2h; Hl = g_x2l; K = PG; ldc = PG;
    } else {
        int v = u - 16;
        m0 = (v >> 3) * 64; n0 = (v & 7) * 64;
        ActH = g_ywh; ActL = g_ywl; WH = g_FwH; WL = g_FwL;
        bias = fcw_b; Hh = g_y2h; Hl = g_y2l; K = PW; ldc = PW;
    }
    float acc[2][4][4];
    hmma64_core(ActH, ActL, K, WH, WL, m0, n0, smd, acc);

    int lane = threadIdx.x & 31, wid = threadIdx.x >> 5;
    int warp_m = wid & 1, warp_n = wid >> 1;
    int g = lane >> 2, tg = lane & 3;
#pragma unroll
    for (int mf = 0; mf < 2; mf++) {
        int row0 = m0 + warp_m * 32 + mf * 16 + g;
#pragma unroll
        for (int nf = 0; nf < 4; nf++) {
            int col = n0 + warp_n * 32 + nf * 8 + tg * 2;
            float b0 = __ldg(bias + col), b1 = __ldg(bias + col + 1);
            float v00 = tanhf(acc[mf][nf][0] + b0);
            float v01 = tanhf(acc[mf][nf][1] + b1);
            float v10 = tanhf(acc[mf][nf][2] + b0);
            float v11 = tanhf(acc[mf][nf][3] + b1);
            size_t o0 = (size_t)row0 * ldc + col;
            size_t o1 = (size_t)(row0 + 8) * ldc + col;
            bf16 h;
            h = __float2bfloat16(v00); Hh[o0] = h; Hl[o0] = __float2bfloat16(v00 - __bfloat162float(h));
            h = __float2bfloat16(v01); Hh[o0 + 1] = h; Hl[o0 + 1] = __float2bfloat16(v01 - __bfloat162float(h));
            h = __float2bfloat16(v10); Hh[o1] = h; Hl[o1] = __float2bfloat16(v10 - __bfloat162float(h));
            h = __float2bfloat16(v11); Hh[o1 + 1] = h; Hl[o1 + 1] = __float2bfloat16(v11 - __bfloat162float(h));
        }
    }
}

// ---------------- heads: HMMA w-part + dot g-part ----------------
__global__ __launch_bounds__(128) void heads_k(
        const float* __restrict__ gH, const float* __restrict__ og_W,
        const float* __restrict__ og_b, float* goalsOut,
        const bf16* __restrict__ wHh, const bf16* __restrict__ wHl,
        const float* __restrict__ ow_b, float* wsOut) {
    extern __shared__ bf16 smd[];
    int u = blockIdx.x;
    if (u < 20) {
        int m0 = (u / 5) * 64, n0 = (u % 5) * 64;
        float acc[2][4][4];
        hmma64_core(wHh, wHl, HW, g_OwH, g_OwL, m0, n0, smd, acc);
        int lane = threadIdx.x & 31, wid = threadIdx.x >> 5;
        int warp_m = wid & 1, warp_n = wid >> 1;
        int g = lane >> 2, tg = lane & 3;
#pragma unroll
        for (int mf = 0; mf < 2; mf++) {
            int row0 = m0 + warp_m * 32 + mf * 16 + g;
#pragma unroll
            for (int nf = 0; nf < 4; nf++) {
                int col = n0 + warp_n * 32 + nf * 8 + tg * 2;
                if (col < WSZ) {
                    float b0 = __ldg(ow_b + col), b1 = __ldg(ow_b + col + 1);
                    float v00 = acc[mf][nf][0] + b0, v01 = acc[mf][nf][1] + b1;
                    float v10 = acc[mf][nf][2] + b0, v11 = acc[mf][nf][3] + b1;
                    int r1 = row0 + 8;
                    wsOut[(size_t)row0 * (MS * WSZ) + col] = v00;
                    wsOut[(size_t)row0 * (MS * WSZ) + col + 1] = v01;
                    wsOut[(size_t)r1 * (MS * WSZ) + col] = v10;
                    wsOut[(size_t)r1 * (MS * WSZ) + col + 1] = v11;
                    g_cat[row0 * CATD + DOF + col] = v00;
                    g_cat[row0 * CATD + DOF + col + 1] = v01;
                    g_cat[r1 * CATD + DOF + col] = v10;
                    g_cat[r1 * CATD + DOF + col + 1] = v11;
                }
            }
        }
    } else {
        int gi = (u - 20) * 128 + threadIdx.x;
        int m = gi / DOF, d = gi - m * DOF;
        const float* a = gH + m * HG;
        const float* w = og_W + d * HG;
        float s = __ldg(og_b + d);
#pragma unroll 8
        for (int k = 0; k < HG; k++) s += a[k] * __ldg(w + k);
        goalsOut[(size_t)m * (MS * DOF) + d] = s;
        g_cat[m * CATD + d] = s;
    }
}

// ---------------- transpose (o,i,j) -> (j,i,o) for bg_W ----------------
__global__ void transpose_oij_jio(const float* __restrict__ in, float* __restrict__ out,
                                  int O, int I, int J) {
    __shared__ float tile[32][33];
    int i  = blockIdx.x;
    int o0 = blockIdx.y * 32;
    int j0 = blockIdx.z * 32;
    int tx = threadIdx.x, ty = threadIdx.y;
    int o = o0 + ty, j = j0 + tx;
    if (o < O && j < J)
        tile[ty][tx] = in[(size_t)o * I * J + (size_t)i * J + j];
    __syncthreads();
    int jo = j0 + ty, oo = o0 + tx;
    if (jo < J && oo < O)
        out[(size_t)jo * I * O + (size_t)i * O + oo] = tile[tx][ty];
}

// ---------------- fp32 SIMT GEMM for Ag (tiny) ----------------
__global__ __launch_bounds__(256, 2) void gemm_nn_batched(
        const float* __restrict__ A, int lda,
        const float* __restrict__ Bm, size_t bStrideZ,
        float* __restrict__ C, int ldc, int cStrideZ,
        int N, int K) {
    __shared__ float As[16][132];
    __shared__ float Bs[16][68];
    int z = blockIdx.z;
    const float* Bz = Bm + (size_t)z * bStrideZ;
    float* Cz = C + (size_t)z * cStrideZ;
    int m0 = blockIdx.y * 128, n0 = blockIdx.x * 64;
    int t = threadIdx.x;
    int tx = t & 15, ty = t >> 4;
    float acc[8][4];
#pragma unroll
    for (int i = 0; i < 8; i++)
#pragma unroll
        for (int j = 0; j < 4; j++) acc[i][j] = 0.f;

    float pa[8], pb[4];
#pragma unroll
    for (int i = 0; i < 8; i++) {
        int idx = t + i * 256;
        pa[i] = __ldg(&A[(size_t)(m0 + (idx >> 4)) * lda + (idx & 15)]);
    }
#pragma unroll
    for (int i = 0; i < 4; i++) {
        int idx = t + i * 256;
        pb[i] = __ldg(&Bz[(size_t)(idx >> 6) * N + n0 + (idx & 63)]);
    }
    for (int k0 = 0; k0 < K; k0 += 16) {
#pragma unroll
        for (int i = 0; i < 8; i++) {
            int idx = t + i * 256;
            As[idx & 15][idx >> 4] = pa[i];
        }
#pragma unroll
        for (int i = 0; i < 4; i++) {
            int idx = t + i * 256;
            Bs[idx >> 6][idx & 63] = pb[i];
        }
        __syncthreads();
        if (k0 + 16 < K) {
            int kn = k0 + 16;
#pragma unroll
            for (int i = 0; i < 8; i++) {
                int idx = t + i * 256;
                pa[i] = __ldg(&A[(size_t)(m0 + (idx >> 4)) * lda + kn + (idx & 15)]);
            }
#pragma unroll
            for (int i = 0; i < 4; i++) {
                int idx = t + i * 256;
                pb[i] = __ldg(&Bz[(size_t)(kn + (idx >> 6)) * N + n0 + (idx & 63)]);
            }
        }
#pragma unroll
        for (int kk = 0; kk < 16; kk++) {
            float a[8], bb[4];
            *(float4*)&a[0] = *(const float4*)&As[kk][ty * 8];
            *(float4*)&a[4] = *(const float4*)&As[kk][ty * 8 + 4];
            *(float4*)&bb[0] = *(const float4*)&Bs[kk][tx * 4];
#pragma unroll
            for (int i = 0; i < 8; i++)
#pragma unroll
                for (int j = 0; j < 4; j++) acc[i][j] += a[i] * bb[j];
        }
        __syncthreads();
    }
#pragma unroll
    for (int i = 0; i < 8; i++)
#pragma unroll
        for (int j = 0; j < 4; j++)
            Cz[(size_t)(m0 + ty * 8 + i) * ldc + n0 + tx * 4 + j] = acc[i][j];
}

// ---------------- init ----------------
__global__ void init_k(const float* __restrict__ goal0, const float* __restrict__ w0,
                       float* __restrict__ outGoals, float* __restrict__ outWs) {
    int idx = blockIdx.x * blockDim.x + threadIdx.x;
    bf16 z = __float2bfloat16(0.f);
    if (idx < 2 * B * HW) {
        g_wh1[idx] = 0.f;
        g_wh0h[idx] = z; g_wh0l[idx] = z;
        g_wh1h[idx] = z; g_wh1l[idx] = z;
    }
    if (idx < B * HW) { g_wc0[idx] = 0.f; g_wc1[idx] = 0.f; }
    if (idx < 2 * B * HG) {
        g_gh1[idx] = 0.f;
        g_gh0h[idx] = z; g_gh0l[idx] = z;
        g_gh1h[idx] = z; g_gh1l[idx] = z;
    }
    if (idx < B * HG) { g_gc0[idx] = 0.f; g_gc1[idx] = 0.f; }
    if (idx < B * DOF) {
        int b = idx / DOF, d = idx - b * DOF;
        float v = goal0[idx];
        g_cat[b * CATD + d] = v;
        outGoals[(size_t)b * MS * DOF + d] = v;
    }
    if (idx < B * WSZ) {
        int b = idx / WSZ, d = idx - b * WSZ;
        float v = w0[idx];
        g_cat[b * CATD + DOF + d] = v;
        outWs[(size_t)b * MS * WSZ + d] = v;
    }
}

// ---------------- bilinear: writes hi/lo bf16 directly ----------------
__global__ __launch_bounds__(256) void bilinear_k(const float* __restrict__ bw_b,
                                                  const float* __restrict__ bg_b) {
    __shared__ float sc[CATD];
    int b = blockIdx.x, part = blockIdx.y;
    int t = threadIdx.x;
    for (int k = t; k < CATD; k += 256) sc[k] = g_cat[b * CATD + k];
    __syncthreads();
    if (part < 2) {
        int o = part * 256 + t;
        const float* a = g_Aw + (size_t)b * CATD * PW + o;
        float acc0 = __ldg(&bw_b[o]), acc1 = 0.f;
#pragma unroll 6
        for (int j = 0; j < CATD; j += 2) {
            acc0 += a[(size_t)j * PW] * sc[j];
            acc1 += a[(size_t)(j + 1) * PW] * sc[j + 1];
        }
        float v = acc0 + acc1;
        bf16 hi = __float2bfloat16(v);
        g_ywh[b * PW + o] = hi;
        g_ywl[b * PW + o] = __float2bfloat16(v - __bfloat162float(hi));
    } else {
        int o = t;
        const float* a = g_Ag + (size_t)b * DOF * PG + o;
        float acc = __ldg(&bg_b[o]);
#pragma unroll
        for (int j = 0; j < DOF; j++) acc += a[j * PG] * sc[j];
        bf16 hi = __float2bfloat16(acc);
        g_xgh[b * PG + o] = hi;
        g_xgl[b * PG + o] = __float2bfloat16(acc - __bfloat162float(hi));
    }
}

// ---------------- host ----------------
extern "C" void kernel_launch(void* const* d_in, const int* in_sizes, int n_in,
                              void* d_out, int out_size) {
    const float* ctx    = (const float*)d_in[0];
    const float* goal0  = (const float*)d_in[1];
    const float* w0     = (const float*)d_in[2];
    const float* bg_W   = (const float*)d_in[3];
    const float* bg_b   = (const float*)d_in[4];
    const float* bw_W   = (const float*)d_in[5];
    const float* bw_b   = (const float*)d_in[6];
    const float* fcg_W  = (const float*)d_in[7];
    const float* fcg_b  = (const float*)d_in[8];
    const float* fcw_W  = (const float*)d_in[9];
    const float* fcw_b  = (const float*)d_in[10];
    const float* lg_Wih = (const float*)d_in[11];
    const float* lg_Whh = (const float*)d_in[12];
    const float* lg_bih = (const float*)d_in[13];
    const float* lg_bhh = (const float*)d_in[14];
    const float* lw_Wih = (const float*)d_in[15];
    const float* lw_Whh = (const float*)d_in[16];
    const float* lw_bih = (const float*)d_in[17];
    const float* lw_bhh = (const float*)d_in[18];
    const float* og_W   = (const float*)d_in[19];
    const float* og_b   = (const float*)d_in[20];
    const float* ow_W   = (const float*)d_in[21];
    const float* ow_b   = (const float*)d_in[22];

    float* out   = (float*)d_out;
    float* goals = out;
    float* ws    = out + (size_t)B * MS * DOF;

    float *Gt, *Ag, *gh1, *gc0, *gc1, *wh1, *wc0, *wc1;
    bf16 *gh0h, *gh0l, *gh1h, *gh1l, *wh0h, *wh0l, *wh1h, *wh1l;
    bf16 *WgL0h, *WgL0l, *WgL1h, *WgL1l, *WwL0h, *WwL0l, *WwL1h, *WwL1l;
    bf16 *FwH, *FwL, *FgH, *FgL, *OwH, *OwL;
    float *BgL0, *BgL1, *BwL0, *BwL1;
    bf16 *x2h, *x2l, *y2h, *y2l;
    cudaGetSymbolAddress((void**)&Gt, g_Gt);
    cudaGetSymbolAddress((void**)&Ag, g_Ag);
    cudaGetSymbolAddress((void**)&gh1, g_gh1);
    cudaGetSymbolAddress((void**)&gc0, g_gc0);
    cudaGetSymbolAddress((void**)&gc1, g_gc1);
    cudaGetSymbolAddress((void**)&wh1, g_wh1);
    cudaGetSymbolAddress((void**)&wc0, g_wc0);
    cudaGetSymbolAddress((void**)&wc1, g_wc1);
    cudaGetSymbolAddress((void**)&gh0h, g_gh0h);
    cudaGetSymbolAddress((void**)&gh0l, g_gh0l);
    cudaGetSymbolAddress((void**)&gh1h, g_gh1h);
    cudaGetSymbolAddress((void**)&gh1l, g_gh1l);
    cudaGetSymbolAddress((void**)&wh0h, g_wh0h);
    cudaGetSymbolAddress((void**)&wh0l, g_wh0l);
    cudaGetSymbolAddress((void**)&wh1h, g_wh1h);
    cudaGetSymbolAddress((void**)&wh1l, g_wh1l);
    cudaGetSymbolAddress((void**)&WgL0h, g_WgL0h);
    cudaGetSymbolAddress((void**)&WgL0l, g_WgL0l);
    cudaGetSymbolAddress((void**)&WgL1h, g_WgL1h);
    cudaGetSymbolAddress((void**)&WgL1l, g_WgL1l);
    cudaGetSymbolAddress((void**)&WwL0h, g_WwL0h);
    cudaGetSymbolAddress((void**)&WwL0l, g_WwL0l);
    cudaGetSymbolAddress((void**)&WwL1h, g_WwL1h);
    cudaGetSymbolAddress((void**)&WwL1l, g_WwL1l);
    cudaGetSymbolAddress((void**)&BgL0, g_BgL0);
    cudaGetSymbolAddress((void**)&BgL1, g_BgL1);
    cudaGetSymbolAddress((void**)&BwL0, g_BwL0);
    cudaGetSymbolAddress((void**)&BwL1, g_BwL1);
    cudaGetSymbolAddress((void**)&FwH, g_FwH);
    cudaGetSymbolAddress((void**)&FwL, g_FwL);
    cudaGetSymbolAddress((void**)&FgH, g_FgH);
    cudaGetSymbolAddress((void**)&FgL, g_FgL);
    cudaGetSymbolAddress((void**)&OwH, g_OwH);
    cudaGetSymbolAddress((void**)&OwL, g_OwL);
    cudaGetSymbolAddress((void**)&x2h, g_x2h);
    cudaGetSymbolAddress((void**)&x2l, g_x2l);
    cudaGetSymbolAddress((void**)&y2h, g_y2h);
    cudaGetSymbolAddress((void**)&y2l, g_y2l);

    static bool attr_set = false;
    if (!attr_set) {
        cudaFuncSetAttribute(aw_mma_kernel, cudaFuncAttributeMaxDynamicSharedMemorySize, AW_SMEM);
        cudaFuncSetAttribute(gates_hmma, cudaFuncAttributeMaxDynamicSharedMemorySize, GATES_SMEM);
        cudaFuncSetAttribute(fc_hmma, cudaFuncAttributeMaxDynamicSharedMemorySize, FC_SMEM);
        cudaFuncSetAttribute(heads_k, cudaFuncAttributeMaxDynamicSharedMemorySize, FC_SMEM);
        attr_set = true;
    }

    // precompute path
    split_ctx<<<(B * CTXD) / 256, 256>>>(ctx);
    transpose_bw_split<<<dim3(CTXD / 32, PW, (CATD + 31) / 32), dim3(32, 32)>>>(bw_W);
    aw_mma_kernel<<<dim3(PW / 64, B / 128, CATD), 256, AW_SMEM>>>();

    dim3 tblk(32, 32);
    transpose_oij_jio<<<dim3(CTXD, PG / 32, 1), tblk>>>(bg_W, Gt, PG, CTXD, DOF);
    gemm_nn_batched<<<dim3(PG / 64, B / 128, DOF), 256>>>(
        ctx, CTXD, Gt, (size_t)CTXD * PG, Ag, DOF * PG, PG, PG, CTXD);

    // pack weights
    pack_w<<<(4 * HG * (PG + HG)) / 256, 256>>>(lg_Wih, lg_Whh, lg_bih, lg_bhh,
                                                WgL0h, WgL0l, BgL0, HG, PG);
    pack_w<<<(4 * HG * (HG + HG)) / 256, 256>>>(lg_Wih + (size_t)4 * HG * PG,
                                                lg_Whh + (size_t)4 * HG * HG,
                                                lg_bih + 4 * HG, lg_bhh + 4 * HG,
                                                WgL1h, WgL1l, BgL1, HG, HG);
    pack_w<<<(4 * HW * (PW + HW)) / 256, 256>>>(lw_Wih, lw_Whh, lw_bih, lw_bhh,
                                                WwL0h, WwL0l, BwL0, HW, PW);
    pack_w<<<(4 * HW * (HW + HW)) / 256, 256>>>(lw_Wih + (size_t)4 * HW * PW,
                                                lw_Whh + (size_t)4 * HW * HW,
                                                lw_bih + 4 * HW, lw_bhh + 4 * HW,
                                                WwL1h, WwL1l, BwL1, HW, HW);
    pack_plain<<<(PW * PW) / 256, 256>>>(fcw_W, FwH, FwL, PW, PW);
    pack_plain<<<(PG * PG) / 256, 256>>>(fcg_W, FgH, FgL, PG, PG);
    pack_plain<<<(WSZP * HW) / 256, 256>>>(ow_W, OwH, OwL, WSZ, HW);

    init_k<<<(2 * B * HW) / 256, 256>>>(goal0, w0, goals, ws);

    const int BHG = B * HG, BHW = B * HW;
    for (int s = 0; s < NSTEPS; s++) {
        const int p = s & 1;
        const int q = p ^ 1;

        bilinear_k<<<dim3(B, 3), 256>>>(bw_b, bg_b);
        fc_hmma<<<48, 128, FC_SMEM>>>(fcw_b, fcg_b);

        // layer 0
        gates_hmma<<<384, 128, GATES_SMEM>>>(
            x2h, x2l, PG, gh0h + p * BHG, gh0l + p * BHG,
            WgL0h, WgL0l, BgL0, gc0, nullptr, gh0h + q * BHG, gh0l + q * BHG,
            y2h, y2l, PW, wh0h + p * BHW, wh0l + p * BHW,
            WwL0h, WwL0l, BwL0, wc0, nullptr, wh0h + q * BHW, wh0l + q * BHW);

        // layer 1
        gates_hmma<<<384, 128, GATES_SMEM>>>(
            gh0h + q * BHG, gh0l + q * BHG, HG, gh1h + p * BHG, gh1l + p * BHG,
            WgL1h, WgL1l, BgL1, gc1, gh1 + q * BHG, gh1h + q * BHG, gh1l + q * BHG,
            wh0h + q * BHW, wh0l + q * BHW, HW, wh1h + p * BHW, wh1l + p * BHW,
            WwL1h, WwL1l, BwL1, wc1, nullptr, wh1h + q * BHW, wh1l + q * BHW);

        heads_k<<<32, 128, FC_SMEM>>>(gh1 + q * BHG, og_W, og_b,
                                      goals + (size_t)(s + 1) * DOF,
                                      wh1h + q * BHW, wh1l + q * BHW, ow_b,
                                      ws + (size_t)(s + 1) * WSZ);
    }
    (void)in_sizes; (void)n_in; (void)out_size; (void)wh1;
}